// round 3
// baseline (speedup 1.0000x reference)
#include <cuda_runtime.h>
#include <math.h>

#define BB 8
#define HH 64
#define WW 64
#define LL 4096
#define DM 96
#define DI 192
#define DR 6
#define NE 8064
#define NS 8192

// ------------------------- device scratch (static, no mallocs) -------------
static __device__ __align__(16) float  g_z[BB*LL*DI];      // (b,l,c) silu(z)
static __device__ __align__(16) float  g_xcpre[BB*DI*LL];  // (b,c,l) pre-conv
static __device__ __align__(16) float  g_xs[BB*DI*LL];     // (b,c,l) silu(conv)
static __device__ __align__(16) double g_fn[BB*DI*LL];     // (b,c,l) normalized feats
static __device__ unsigned long long   g_keys[BB*NE];
static __device__ int    g_parent[BB*LL];
static __device__ int    g_bfs[BB*LL];
static __device__ int    g_lvl[BB*(LL+2)];
static __device__ int    g_lvlcnt[BB*(LL+2)];
static __device__ int    g_lvlmin[BB*(LL+2)];
static __device__ int    g_revert[BB*(LL+2)];
static __device__ int    g_numlev[BB];
static __device__ int    g_adjs[BB*(LL+1)];
static __device__ int    g_adjl[BB*2*LL];
static __device__ __align__(16) float  g_dtsr[BB*DR*LL];   // (b,r,l)
static __device__ float  g_Bsv[BB*LL];
static __device__ float  g_Csv[BB*LL];
static __device__ __align__(16) float  g_up[BB*LL*DI];     // (b,l,c) BX -> aggr_up
static __device__ __align__(16) float  g_ew[BB*LL*DI];     // (b,l,c) deltaA
static __device__ __align__(16) float  g_ag[BB*LL*DI];     // (b,l,c) aggr
static __device__ __align__(16) float  g_yz[BB*LL*DI];     // (b,l,c)

// ------------------------- helpers -----------------------------------------
__device__ __forceinline__ float siluf(float x){ return x / (1.f + expf(-x)); }
__device__ __forceinline__ float softplusf(float x){
    return fmaxf(x, 0.f) + log1pf(expf(-fabsf(x)));
}
__device__ __forceinline__ float warpsum(float v){
    #pragma unroll
    for (int o = 16; o > 0; o >>= 1) v += __shfl_xor_sync(0xFFFFFFFFu, v, o);
    return v;
}

// ------------------------- 1. in_proj GEMM + split/silu --------------------
// C[m][n] = sum_k x[m][k] * W[n][k], M=32768, N=384, K=96
__global__ void __launch_bounds__(256) k_gemm_in(const float* __restrict__ A,
                                                 const float* __restrict__ W)
{
    __shared__ float sA[64][33];
    __shared__ float sW[64][33];
    int bm = blockIdx.y * 64, bn = blockIdx.x * 64;
    int tid = threadIdx.x;
    int tx = tid & 15, ty = tid >> 4;
    float acc[4][4] = {};
    for (int k0 = 0; k0 < 96; k0 += 32) {
        for (int t = tid; t < 512; t += 256) {
            int r = t >> 3, kq = t & 7;
            float4 va = *(const float4*)(A + (size_t)(bm + r) * 96 + k0 + kq * 4);
            sA[r][kq*4+0] = va.x; sA[r][kq*4+1] = va.y;
            sA[r][kq*4+2] = va.z; sA[r][kq*4+3] = va.w;
            float4 vw = *(const float4*)(W + (size_t)(bn + r) * 96 + k0 + kq * 4);
            sW[r][kq*4+0] = vw.x; sW[r][kq*4+1] = vw.y;
            sW[r][kq*4+2] = vw.z; sW[r][kq*4+3] = vw.w;
        }
        __syncthreads();
        #pragma unroll
        for (int k = 0; k < 32; k++) {
            float a[4], b[4];
            #pragma unroll
            for (int i = 0; i < 4; i++) { a[i] = sA[ty*4+i][k]; b[i] = sW[tx*4+i][k]; }
            #pragma unroll
            for (int i = 0; i < 4; i++)
                #pragma unroll
                for (int j = 0; j < 4; j++)
                    acc[i][j] += a[i] * b[j];
        }
        __syncthreads();
    }
    #pragma unroll
    for (int i = 0; i < 4; i++) {
        int m = bm + ty * 4 + i;
        int b = m >> 12, l = m & 4095;
        #pragma unroll
        for (int j = 0; j < 4; j++) {
            int n = bn + tx * 4 + j;
            float v = acc[i][j];
            if (n < DI) {
                g_xcpre[((size_t)b * DI + n) * LL + l] = v;
            } else {
                g_z[(size_t)m * DI + (n - DI)] = siluf(v);
            }
        }
    }
}

// ------------------------- 2. depthwise 3x3 conv + silu --------------------
__global__ void k_conv(const float* __restrict__ cw, const float* __restrict__ cb)
{
    int gid = blockIdx.x * blockDim.x + threadIdx.x;
    if (gid >= BB * DI * LL) return;
    int l = gid & 4095;
    int c = (gid >> 12) % DI;
    int h = l >> 6, w = l & 63;
    const float* src = g_xcpre + (size_t)(gid - l);  // (b,c) plane base
    float acc = cb[c];
    #pragma unroll
    for (int ky = 0; ky < 3; ky++) {
        int hy = h + ky - 1;
        if ((unsigned)hy >= 64u) continue;
        #pragma unroll
        for (int kx = 0; kx < 3; kx++) {
            int wx = w + kx - 1;
            if ((unsigned)wx >= 64u) continue;
            acc += src[hy * 64 + wx] * cw[c * 9 + ky * 3 + kx];
        }
    }
    g_xs[gid] = siluf(acc);
}

// ------------------------- 3. normalized features (double) -----------------
__global__ void k_fn()
{
    int gid = blockIdx.x * blockDim.x + threadIdx.x;  // b*L + l
    if (gid >= BB * LL) return;
    int b = gid >> 12, l = gid & 4095;
    const float* xp = g_xs + (size_t)b * DI * LL + l;
    double s = 0.0;
    for (int c = 0; c < DI; c++) {
        double v = (double)xp[(size_t)c * LL];
        s += v * v;
    }
    double nrm = sqrt(s);
    double den = nrm > 1e-8 ? nrm : 1e-8;
    double* fp = g_fn + (size_t)b * DI * LL + l;
    for (int c = 0; c < DI; c++)
        fp[(size_t)c * LL] = (double)xp[(size_t)c * LL] / den;
}

// ------------------------- 4. edge weights (double, sortable key) ----------
__global__ void k_edge()
{
    int gid = blockIdx.x * blockDim.x + threadIdx.x;
    if (gid >= BB * NE) return;
    int b = gid / NE, e = gid % NE;
    int u, v;
    if (e < 4032) { int r = e / 63, c = e % 63; u = r * 64 + c; v = u + 1; }
    else          { int j = e - 4032; u = j; v = j + 64; }
    const double* f = g_fn + (size_t)b * DI * LL;
    double s = 0.0;
    for (int c = 0; c < DI; c++)
        s += f[(size_t)c * LL + u] * f[(size_t)c * LL + v];
    double w = exp(-s);               // w > 0 always -> bit pattern is monotone
    g_keys[gid] = (unsigned long long)__double_as_longlong(w);
}

// ------------------------- 5. sort + Kruskal + BFS (one block / batch) -----
__global__ void __launch_bounds__(1024, 1) k_tree()
{
    extern __shared__ unsigned char sm[];
    unsigned long long* skey = (unsigned long long*)sm;                 // [0,64K)
    unsigned int*       sidx = (unsigned int*)(sm + 65536);             // [64K,96K)
    unsigned int*       adjs = (unsigned int*)(sm + 98304);             // 4097
    unsigned int*       adjl = (unsigned int*)(sm + 98304 + 16388);     // 8190
    int b = blockIdx.x;
    int tid = threadIdx.x;

    for (int i = tid; i < NS; i += 1024) {
        if (i < NE) { skey[i] = g_keys[b * NE + i]; sidx[i] = (unsigned)i; }
        else        { skey[i] = 0xFFFFFFFFFFFFFFFFULL; sidx[i] = 0xFFFFFFFFu; }
    }
    __syncthreads();

    // bitonic sort ascending by (key, idx)  -> matches stable argsort of w
    for (int k = 2; k <= NS; k <<= 1) {
        for (int j = k >> 1; j > 0; j >>= 1) {
            for (int i = tid; i < NS; i += 1024) {
                int p = i ^ j;
                if (p > i) {
                    unsigned long long ka = skey[i], kb = skey[p];
                    unsigned int ia = sidx[i], ib = sidx[p];
                    bool gt = (ka > kb) || (ka == kb && ia > ib);
                    bool up = ((i & k) == 0);
                    if (gt == up) {
                        skey[i] = kb; skey[p] = ka;
                        sidx[i] = ib; sidx[p] = ia;
                    }
                }
            }
            __syncthreads();
        }
    }

    // keys region is now free: carve uf / mst / depth out of it
    unsigned int* uf   = (unsigned int*)sm;                // 4096
    unsigned int* mstu = (unsigned int*)(sm + 16384);      // 4096
    unsigned int* mstv = (unsigned int*)(sm + 32768);      // 4096
    unsigned int* dep  = (unsigned int*)(sm + 49152);      // 4096

    for (int i = tid; i < LL; i += 1024) uf[i] = (unsigned)i;
    __syncthreads();

    if (tid == 0) {
        int cnt = 0;
        for (int t = 0; t < NS && cnt < LL - 1; t++) {
            unsigned int e = sidx[t];
            if (e >= NE) break;
            int u, v;
            if (e < 4032) { int r = e / 63, c = e % 63; u = r * 64 + c; v = u + 1; }
            else          { int j = (int)e - 4032; u = j; v = j + 64; }
            int ra = u; while (uf[ra] != (unsigned)ra) { uf[ra] = uf[uf[ra]]; ra = uf[ra]; }
            int rc = v; while (uf[rc] != (unsigned)rc) { uf[rc] = uf[uf[rc]]; rc = uf[rc]; }
            if (ra != rc) {
                uf[ra] = rc;
                mstu[cnt] = (unsigned)u; mstv[cnt] = (unsigned)v;
                cnt++;
            }
        }
    }
    __syncthreads();

    // adjacency CSR
    for (int i = tid; i <= LL; i += 1024) adjs[i] = 0;
    __syncthreads();
    for (int e = tid; e < LL - 1; e += 1024) {
        atomicAdd(&adjs[mstu[e]], 1u);
        atomicAdd(&adjs[mstv[e]], 1u);
    }
    __syncthreads();
    if (tid == 0) {
        unsigned int run = 0;
        for (int i = 0; i <= LL; i++) { unsigned int c = adjs[i]; adjs[i] = run; run += c; }
        for (int i = 0; i < LL; i++) dep[i] = adjs[i];     // cursors
        for (int e = 0; e < LL - 1; e++) {
            unsigned u = mstu[e], v = mstv[e];
            adjl[dep[u]++] = v;
            adjl[dep[v]++] = u;
        }
    }
    __syncthreads();

    // BFS (parent unique in a tree -> traversal order irrelevant for parents)
    unsigned int* par  = (unsigned int*)(sm + 65536);   // reuse sidx region
    unsigned int* bfsq = (unsigned int*)(sm + 81920);
    for (int i = tid; i < LL; i += 1024) par[i] = 0xFFFFFFFFu;
    __syncthreads();
    if (tid == 0) {
        par[0] = 0; dep[0] = 0; bfsq[0] = 0;
        int head = 0, tail = 1;
        while (head < tail) {
            int a = (int)bfsq[head++];
            for (unsigned t = adjs[a]; t < adjs[a + 1]; t++) {
                unsigned nb = adjl[t];
                if (par[nb] == 0xFFFFFFFFu) {
                    par[nb] = (unsigned)a;
                    dep[nb] = dep[a] + 1;
                    bfsq[tail++] = nb;
                }
            }
        }
        int nl = (int)dep[bfsq[LL - 1]] + 1;
        g_numlev[b] = nl;
        int* lvl = g_lvl + b * (LL + 2);
        lvl[0] = 0;
        for (int i = 1; i < LL; i++)
            if (dep[bfsq[i]] != dep[bfsq[i - 1]]) lvl[dep[bfsq[i]]] = i;
        lvl[nl] = LL;
        // per-level count + min node id (for the padded-scatter revert quirk)
        for (int d = 0; d < nl; d++) {
            int ls = lvl[d], le = lvl[d + 1];
            int mn = 0x7FFFFFFF;
            for (int i = ls; i < le; i++) mn = min(mn, (int)bfsq[i]);
            g_lvlcnt[b * (LL + 2) + d] = le - ls;
            g_lvlmin[b * (LL + 2) + d] = mn;
        }
    }
    __syncthreads();

    for (int i = tid; i < LL; i += 1024) {
        g_parent[b * LL + i] = (int)par[i];
        g_bfs[b * LL + i]    = (int)bfsq[i];
    }
    for (int i = tid; i <= LL; i += 1024) g_adjs[b * (LL + 1) + i] = (int)adjs[i];
    for (int i = tid; i < 2 * (LL - 1); i += 1024) g_adjl[b * 2 * LL + i] = (int)adjl[i];
}

// ------------------------- 5b. padded-scatter revert flags -----------------
// Reference pads each level's index list to the cross-batch max with l[0]
// (masked). The down-sweep scatter-set then writes l[0] twice: once with the
// corrected value, once (later, masked slot) with the OLD value. Last write
// wins -> node l[0] reverts to aggr_up for batches whose level is padded.
__global__ void k_revert()
{
    __shared__ int nlmax;
    if (threadIdx.x == 0) {
        int m = 0;
        for (int b = 0; b < BB; b++) m = max(m, g_numlev[b]);
        nlmax = m;
    }
    __syncthreads();
    for (int d = threadIdx.x; d < nlmax; d += blockDim.x) {
        int cnt[BB];
        int md = 0;
        for (int b = 0; b < BB; b++) {
            int c = (d < g_numlev[b]) ? g_lvlcnt[b * (LL + 2) + d] : 0;
            cnt[b] = c;
            md = max(md, c);
        }
        for (int b = 0; b < BB; b++) {
            int r = (d > 0 && cnt[b] > 0 && cnt[b] < md)
                        ? g_lvlmin[b * (LL + 2) + d] : -1;
            g_revert[b * (LL + 2) + d] = r;
        }
    }
}

// ------------------------- 6. x_dbl projection ------------------------------
__global__ void k_xdbl(const float* __restrict__ XW)   // (8,192)
{
    int gid = blockIdx.x * blockDim.x + threadIdx.x;
    if (gid >= BB * LL) return;
    int b = gid >> 12, l = gid & 4095;
    const float* xp = g_xs + (size_t)b * DI * LL + l;
    float acc[8] = {0,0,0,0,0,0,0,0};
    for (int k = 0; k < DI; k++) {
        float xv = xp[(size_t)k * LL];
        #pragma unroll
        for (int c = 0; c < 8; c++) acc[c] += XW[c * DI + k] * xv;
    }
    #pragma unroll
    for (int r = 0; r < DR; r++) g_dtsr[((size_t)b * DR + r) * LL + l] = acc[r];
    g_Bsv[gid] = acc[6];
    g_Csv[gid] = acc[7];
}

// ------------------------- 7. dts / deltaA / BX -----------------------------
__global__ void k_bxew(const float* __restrict__ dtW, const float* __restrict__ dtB,
                       const float* __restrict__ Alog)
{
    int gid = blockIdx.x * blockDim.x + threadIdx.x;
    if (gid >= BB * DI * LL) return;
    int l = gid & 4095;
    int d = (gid >> 12) % DI;
    int b = gid / (DI * LL);
    const float* dr = g_dtsr + (size_t)b * DR * LL + l;
    float s = 0.f;
    #pragma unroll
    for (int r = 0; r < DR; r++) s += dr[(size_t)r * LL] * dtW[d * DR + r];
    float dt = softplusf(s + dtB[d]);
    float A  = -expf(Alog[d]);
    float ew = expf(dt * A);
    float bx = dt * g_Bsv[b * LL + l] * g_xs[gid];
    size_t o = ((size_t)(b * LL + l)) * DI + d;
    g_ew[o] = ew;
    g_up[o] = bx;
}

// ------------------------- 8. tree scan (up + down, level-synchronous) -----
__global__ void __launch_bounds__(256) k_scan()
{
    int b  = blockIdx.y;
    int c0 = blockIdx.x * 64;
    int tid = threadIdx.x;
    int nl = g_numlev[b];
    const int* lvl  = g_lvl + b * (LL + 2);
    const int* bfs  = g_bfs + b * LL;
    const int* par  = g_parent + b * LL;
    const int* adjs = g_adjs + b * (LL + 1);
    const int* adjl = g_adjl + b * 2 * LL;
    const int* revp = g_revert + b * (LL + 2);
    float* up = g_up + (size_t)b * LL * DI;
    float* ag = g_ag + (size_t)b * LL * DI;
    const float* ew = g_ew + (size_t)b * LL * DI;

    // up-sweep
    for (int lev = nl - 1; lev >= 0; --lev) {
        int ls = lvl[lev], le = lvl[lev + 1];
        int work = (le - ls) * 64;
        for (int i = tid; i < work; i += 256) {
            int node = bfs[ls + (i >> 6)];
            int c = c0 + (i & 63);
            float acc = up[(size_t)node * DI + c];
            int p = par[node];
            int a0 = adjs[node], a1 = adjs[node + 1];
            for (int t = a0; t < a1; t++) {
                int nb = adjl[t];
                if (nb == p) continue;
                acc += ew[(size_t)nb * DI + c] * up[(size_t)nb * DI + c];
            }
            up[(size_t)node * DI + c] = acc;
        }
        __syncthreads();
    }
    // down-sweep (with padded-scatter revert)
    for (int lev = 0; lev < nl; ++lev) {
        int ls = lvl[lev], le = lvl[lev + 1];
        int rev = revp[lev];
        int work = (le - ls) * 64;
        for (int i = tid; i < work; i += 256) {
            int node = bfs[ls + (i >> 6)];
            int c = c0 + (i & 63);
            float u = up[(size_t)node * DI + c];
            float val;
            if (lev == 0) {
                val = u;
            } else {
                int p = par[node];
                float w = ew[(size_t)node * DI + c];
                val = u + w * (ag[(size_t)p * DI + c] - w * u);
                if (node == rev) val = u;   // padded duplicate scatter: old wins
            }
            ag[(size_t)node * DI + c] = val;
        }
        __syncthreads();
    }
}

// ------------------------- 9. fused LN -> *Cs -> +Ds*xs -> LN -> *z --------
__global__ void __launch_bounds__(256) k_fuse(const float* __restrict__ hg,
                                              const float* __restrict__ hb,
                                              const float* __restrict__ og,
                                              const float* __restrict__ ob,
                                              const float* __restrict__ Ds)
{
    int warp = (blockIdx.x * 256 + threadIdx.x) >> 5;
    int lane = threadIdx.x & 31;
    if (warp >= BB * LL) return;
    int b = warp >> 12, l = warp & 4095;
    const float* hrow = g_ag + (size_t)warp * DI;

    float v[6];
    #pragma unroll
    for (int j = 0; j < 6; j++) v[j] = hrow[lane + 32 * j];

    float s = 0.f;
    #pragma unroll
    for (int j = 0; j < 6; j++) s += v[j];
    float mu = warpsum(s) * (1.f / 192.f);
    float q = 0.f;
    #pragma unroll
    for (int j = 0; j < 6; j++) { float d = v[j] - mu; q += d * d; }
    float inv = rsqrtf(warpsum(q) * (1.f / 192.f) + 1e-5f);

    float Cv = g_Csv[warp];
    float y[6];
    #pragma unroll
    for (int j = 0; j < 6; j++) {
        int c = lane + 32 * j;
        float hn = (v[j] - mu) * inv * hg[c] + hb[c];
        y[j] = hn * Cv + Ds[c] * g_xs[((size_t)b * DI + c) * LL + l];
    }

    s = 0.f;
    #pragma unroll
    for (int j = 0; j < 6; j++) s += y[j];
    float mu2 = warpsum(s) * (1.f / 192.f);
    q = 0.f;
    #pragma unroll
    for (int j = 0; j < 6; j++) { float d = y[j] - mu2; q += d * d; }
    float inv2 = rsqrtf(warpsum(q) * (1.f / 192.f) + 1e-5f);

    #pragma unroll
    for (int j = 0; j < 6; j++) {
        int c = lane + 32 * j;
        float y2 = (y[j] - mu2) * inv2 * og[c] + ob[c];
        g_yz[(size_t)warp * DI + c] = y2 * g_z[(size_t)warp * DI + c];
    }
}

// ------------------------- 10. out_proj GEMM -------------------------------
__global__ void __launch_bounds__(256) k_gemm_out(const float* __restrict__ W,
                                                  float* __restrict__ out)
{
    __shared__ float sA[64][33];
    __shared__ float sW[64][33];
    int bm = blockIdx.y * 64, bn = blockIdx.x * 64;
    int tid = threadIdx.x;
    int tx = tid & 15, ty = tid >> 4;
    float acc[4][4] = {};
    for (int k0 = 0; k0 < 192; k0 += 32) {
        for (int t = tid; t < 512; t += 256) {
            int r = t >> 3, kq = t & 7;
            float4 va = *(const float4*)(g_yz + (size_t)(bm + r) * 192 + k0 + kq * 4);
            sA[r][kq*4+0] = va.x; sA[r][kq*4+1] = va.y;
            sA[r][kq*4+2] = va.z; sA[r][kq*4+3] = va.w;
            float4 vw;
            if (bn + r < 96)
                vw = *(const float4*)(W + (size_t)(bn + r) * 192 + k0 + kq * 4);
            else
                vw = make_float4(0.f, 0.f, 0.f, 0.f);
            sW[r][kq*4+0] = vw.x; sW[r][kq*4+1] = vw.y;
            sW[r][kq*4+2] = vw.z; sW[r][kq*4+3] = vw.w;
        }
        __syncthreads();
        #pragma unroll
        for (int k = 0; k < 32; k++) {
            float a[4], bv[4];
            #pragma unroll
            for (int i = 0; i < 4; i++) { a[i] = sA[ty*4+i][k]; bv[i] = sW[tx*4+i][k]; }
            #pragma unroll
            for (int i = 0; i < 4; i++)
                #pragma unroll
                for (int j = 0; j < 4; j++)
                    acc[i][j] += a[i] * bv[j];
        }
        __syncthreads();
    }
    #pragma unroll
    for (int i = 0; i < 4; i++) {
        int m = bm + ty * 4 + i;
        #pragma unroll
        for (int j = 0; j < 4; j++) {
            int n = bn + tx * 4 + j;
            if (n < 96) out[(size_t)m * 96 + n] = acc[i][j];
        }
    }
}

// ------------------------- launch ------------------------------------------
extern "C" void kernel_launch(void* const* d_in, const int* in_sizes, int n_in,
                              void* d_out, int out_size)
{
    const float* x    = (const float*)d_in[0];
    const float* inw  = (const float*)d_in[1];
    const float* cw   = (const float*)d_in[2];
    const float* cb   = (const float*)d_in[3];
    const float* xpw  = (const float*)d_in[4];
    const float* dtw  = (const float*)d_in[5];
    const float* dtb  = (const float*)d_in[6];
    const float* alog = (const float*)d_in[7];
    const float* Dsp  = (const float*)d_in[8];
    const float* hg   = (const float*)d_in[9];
    const float* hbp  = (const float*)d_in[10];
    const float* og   = (const float*)d_in[11];
    const float* obp  = (const float*)d_in[12];
    const float* opw  = (const float*)d_in[13];
    float* out = (float*)d_out;

    k_gemm_in<<<dim3(6, 512), 256>>>(x, inw);
    k_conv<<<(BB * DI * LL + 255) / 256, 256>>>(cw, cb);
    k_fn<<<(BB * LL + 255) / 256, 256>>>();
    k_edge<<<(BB * NE + 255) / 256, 256>>>();

    const int TREESMEM = 98304 + 16388 + 8190 * 4 + 4;   // ~147.5 KB
    cudaFuncSetAttribute(k_tree, cudaFuncAttributeMaxDynamicSharedMemorySize, TREESMEM);
    k_tree<<<BB, 1024, TREESMEM>>>();
    k_revert<<<1, 256>>>();

    k_xdbl<<<(BB * LL + 255) / 256, 256>>>(xpw);
    k_bxew<<<(BB * DI * LL + 255) / 256, 256>>>(dtw, dtb, alog);
    k_scan<<<dim3(3, BB), 256>>>();
    k_fuse<<<(BB * LL * 32 + 255) / 256, 256>>>(hg, hbp, og, obp, Dsp);
    k_gemm_out<<<dim3(2, 512), 256>>>(opw, out);
}

// round 4
// speedup vs baseline: 1.7228x; 1.7228x over previous
#include <cuda_runtime.h>
#include <math.h>

#define BB 8
#define HH 64
#define WW 64
#define LL 4096
#define DM 96
#define DI 192
#define DR 6
#define NE 8064

// ------------------------- device scratch (static, no mallocs) -------------
static __device__ __align__(16) float  g_z[BB*LL*DI];      // (b,l,c) silu(z)
static __device__ __align__(16) float  g_xcpre[BB*DI*LL];  // (b,c,l) pre-conv
static __device__ __align__(16) float  g_xs[BB*DI*LL];     // (b,c,l) silu(conv)
static __device__ __align__(16) double g_fn[BB*DI*LL];     // (b,c,l) normalized feats
static __device__ unsigned long long   g_keys[BB*NE];
static __device__ int    g_parent[BB*LL];
static __device__ int    g_bfs[BB*LL];
static __device__ int    g_lvl[BB*(LL+2)];
static __device__ int    g_lvlcnt[BB*(LL+2)];
static __device__ int    g_lvlmin[BB*(LL+2)];
static __device__ int    g_revert[BB*(LL+2)];
static __device__ int    g_numlev[BB];
static __device__ __align__(16) float  g_dtsr[BB*DR*LL];   // (b,r,l)
static __device__ float  g_Bsv[BB*LL];
static __device__ float  g_Csv[BB*LL];
static __device__ __align__(16) float  g_up[BB*LL*DI];     // (b,l,c) BX -> aggr_up
static __device__ __align__(16) float  g_ew[BB*LL*DI];     // (b,l,c) deltaA
static __device__ __align__(16) float  g_ag[BB*LL*DI];     // (b,l,c) aggr
static __device__ __align__(16) float  g_yz[BB*LL*DI];     // (b,l,c)

// ------------------------- helpers -----------------------------------------
__device__ __forceinline__ float siluf(float x){ return x / (1.f + expf(-x)); }
__device__ __forceinline__ float softplusf(float x){
    return fmaxf(x, 0.f) + log1pf(expf(-fabsf(x)));
}
__device__ __forceinline__ float warpsum(float v){
    #pragma unroll
    for (int o = 16; o > 0; o >>= 1) v += __shfl_xor_sync(0xFFFFFFFFu, v, o);
    return v;
}
__device__ __forceinline__ void edge_uv(int e, int& u, int& v){
    if (e < 4032) { int r = e / 63, c = e % 63; u = r * 64 + c; v = u + 1; }
    else          { int j = e - 4032; u = j; v = j + 64; }
}

// ------------------------- 1. in_proj GEMM + split/silu --------------------
__global__ void __launch_bounds__(256) k_gemm_in(const float* __restrict__ A,
                                                 const float* __restrict__ W)
{
    __shared__ float sA[64][33];
    __shared__ float sW[64][33];
    int bm = blockIdx.y * 64, bn = blockIdx.x * 64;
    int tid = threadIdx.x;
    int tx = tid & 15, ty = tid >> 4;
    float acc[4][4] = {};
    for (int k0 = 0; k0 < 96; k0 += 32) {
        for (int t = tid; t < 512; t += 256) {
            int r = t >> 3, kq = t & 7;
            float4 va = *(const float4*)(A + (size_t)(bm + r) * 96 + k0 + kq * 4);
            sA[r][kq*4+0] = va.x; sA[r][kq*4+1] = va.y;
            sA[r][kq*4+2] = va.z; sA[r][kq*4+3] = va.w;
            float4 vw = *(const float4*)(W + (size_t)(bn + r) * 96 + k0 + kq * 4);
            sW[r][kq*4+0] = vw.x; sW[r][kq*4+1] = vw.y;
            sW[r][kq*4+2] = vw.z; sW[r][kq*4+3] = vw.w;
        }
        __syncthreads();
        #pragma unroll
        for (int k = 0; k < 32; k++) {
            float a[4], b[4];
            #pragma unroll
            for (int i = 0; i < 4; i++) { a[i] = sA[ty*4+i][k]; b[i] = sW[tx*4+i][k]; }
            #pragma unroll
            for (int i = 0; i < 4; i++)
                #pragma unroll
                for (int j = 0; j < 4; j++)
                    acc[i][j] += a[i] * b[j];
        }
        __syncthreads();
    }
    #pragma unroll
    for (int i = 0; i < 4; i++) {
        int m = bm + ty * 4 + i;
        int b = m >> 12, l = m & 4095;
        #pragma unroll
        for (int j = 0; j < 4; j++) {
            int n = bn + tx * 4 + j;
            float v = acc[i][j];
            if (n < DI) {
                g_xcpre[((size_t)b * DI + n) * LL + l] = v;
            } else {
                g_z[(size_t)m * DI + (n - DI)] = siluf(v);
            }
        }
    }
}

// ------------------------- 2. depthwise 3x3 conv + silu --------------------
__global__ void k_conv(const float* __restrict__ cw, const float* __restrict__ cb)
{
    int gid = blockIdx.x * blockDim.x + threadIdx.x;
    if (gid >= BB * DI * LL) return;
    int l = gid & 4095;
    int c = (gid >> 12) % DI;
    int h = l >> 6, w = l & 63;
    const float* src = g_xcpre + (size_t)(gid - l);
    float acc = cb[c];
    #pragma unroll
    for (int ky = 0; ky < 3; ky++) {
        int hy = h + ky - 1;
        if ((unsigned)hy >= 64u) continue;
        #pragma unroll
        for (int kx = 0; kx < 3; kx++) {
            int wx = w + kx - 1;
            if ((unsigned)wx >= 64u) continue;
            acc += src[hy * 64 + wx] * cw[c * 9 + ky * 3 + kx];
        }
    }
    g_xs[gid] = siluf(acc);
}

// ------------------------- 3. normalized features (double) -----------------
__global__ void k_fn()
{
    int gid = blockIdx.x * blockDim.x + threadIdx.x;  // b*L + l
    if (gid >= BB * LL) return;
    int b = gid >> 12, l = gid & 4095;
    const float* xp = g_xs + (size_t)b * DI * LL + l;
    double s = 0.0;
    for (int c = 0; c < DI; c++) {
        double v = (double)xp[(size_t)c * LL];
        s += v * v;
    }
    double nrm = sqrt(s);
    double den = nrm > 1e-8 ? nrm : 1e-8;
    double* fp = g_fn + (size_t)b * DI * LL + l;
    for (int c = 0; c < DI; c++)
        fp[(size_t)c * LL] = (double)xp[(size_t)c * LL] / den;
}

// ------------------------- 4. edge weights (double, sortable key) ----------
__global__ void k_edge()
{
    int gid = blockIdx.x * blockDim.x + threadIdx.x;
    if (gid >= BB * NE) return;
    int b = gid / NE, e = gid % NE;
    int u, v;
    edge_uv(e, u, v);
    const double* f = g_fn + (size_t)b * DI * LL;
    double s = 0.0;
    for (int c = 0; c < DI; c++)
        s += f[(size_t)c * LL + u] * f[(size_t)c * LL + v];
    double w = exp(-s);               // w > 0 -> bit pattern monotone in value
    g_keys[gid] = (unsigned long long)__double_as_longlong(w);
}

// ------------------------- 5. Boruvka MST + levels (one block / batch) -----
// (weight,key-idx) is a strict total order -> MST unique -> identical tree to
// reference's stable-sorted Kruskal. Parents/depths/levels are tree-only
// properties, so no sort and no serial union-find needed.
__global__ void __launch_bounds__(1024, 1) k_boruvka()
{
    extern __shared__ unsigned char sm[];
    unsigned int*       comp = (unsigned int*)sm;                    // 16K
    unsigned int*       ptrA = (unsigned int*)(sm + 16384);          // 16K
    unsigned long long* best = (unsigned long long*)(sm + 32768);    // 32K
    unsigned int*       bidx = (unsigned int*)(sm + 65536);          // 16K
    unsigned int*       flag = (unsigned int*)(sm + 81920);          // 32K (NE)
    __shared__ int s_done, s_chg, s_nl;

    int b = blockIdx.x;
    int tid = threadIdx.x;
    const unsigned long long* keys = g_keys + (size_t)b * NE;

    for (int i = tid; i < LL; i += 1024) comp[i] = (unsigned)i;
    for (int e = tid; e < NE; e += 1024) flag[e] = 0;
    __syncthreads();

    // ---- Boruvka rounds ----
    for (int round = 0; round < 14; round++) {
        for (int i = tid; i < LL; i += 1024) { best[i] = ~0ULL; bidx[i] = 0xFFFFFFFFu; }
        if (tid == 0) s_done = 1;
        __syncthreads();

        // pass 1: min key per component
        for (int e = tid; e < NE; e += 1024) {
            int u, v; edge_uv(e, u, v);
            unsigned cu = comp[u], cv = comp[v];
            if (cu != cv) {
                unsigned long long k = keys[e];
                atomicMin(&best[cu], k);
                atomicMin(&best[cv], k);
            }
        }
        __syncthreads();
        // pass 2: min edge index among key==best (exact stable tie-break)
        for (int e = tid; e < NE; e += 1024) {
            int u, v; edge_uv(e, u, v);
            unsigned cu = comp[u], cv = comp[v];
            if (cu != cv) {
                unsigned long long k = keys[e];
                if (k == best[cu]) atomicMin(&bidx[cu], (unsigned)e);
                if (k == best[cv]) atomicMin(&bidx[cv], (unsigned)e);
            }
        }
        __syncthreads();
        // hook
        for (int c = tid; c < LL; c += 1024) {
            unsigned e = bidx[c];
            if (e != 0xFFFFFFFFu) {
                flag[e] = 1u;
                int u, v; edge_uv((int)e, u, v);
                unsigned cu = comp[u], cv = comp[v];
                ptrA[c] = (cu == (unsigned)c) ? cv : cu;
                s_done = 0;
            } else {
                ptrA[c] = (unsigned)c;
            }
        }
        __syncthreads();
        if (s_done) break;
        // 2-cycle removal (mutual hooks -> smaller label becomes root)
        for (int c = tid; c < LL; c += 1024) {
            unsigned p = ptrA[c];
            if (p != (unsigned)c && ptrA[p] == (unsigned)c && (unsigned)c < p)
                ptrA[c] = (unsigned)c;
        }
        __syncthreads();
        // pointer jumping
        for (int it = 0; it < 13; it++) {
            if (tid == 0) s_chg = 0;
            __syncthreads();
            for (int c = tid; c < LL; c += 1024) {
                unsigned p = ptrA[c];
                unsigned g = ptrA[p];
                if (p != g) { ptrA[c] = g; s_chg = 1; }
            }
            __syncthreads();
            if (!s_chg) break;
        }
        // relabel
        for (int i = tid; i < LL; i += 1024) comp[i] = ptrA[comp[i]];
        __syncthreads();
    }

    // ---- parallel level propagation: par/dep from root 0 ----
    unsigned int* dep = (unsigned int*)(sm + 32768);   // reuse best
    unsigned int* par = (unsigned int*)(sm + 49152);
    for (int i = tid; i < LL; i += 1024) dep[i] = 0xFFFFFFFFu;
    __syncthreads();
    if (tid == 0) { dep[0] = 0; par[0] = 0; }
    __syncthreads();

    for (unsigned r = 0;; r++) {
        if (tid == 0) s_chg = 0;
        __syncthreads();
        for (int i = tid; i < LL; i += 1024) {
            if (dep[i] != 0xFFFFFFFFu) continue;
            int h = i >> 6, w = i & 63;
            int pfound = -1;
            if (w < 63 && flag[h * 63 + w]        && dep[i + 1]  == r) pfound = i + 1;
            else if (w > 0  && flag[h * 63 + w - 1] && dep[i - 1]  == r) pfound = i - 1;
            else if (h < 63 && flag[4032 + i]       && dep[i + 64] == r) pfound = i + 64;
            else if (h > 0  && flag[4032 + i - 64]  && dep[i - 64] == r) pfound = i - 64;
            if (pfound >= 0) {
                par[i] = (unsigned)pfound;
                dep[i] = r + 1;
                s_chg = 1;
            }
        }
        __syncthreads();
        if (!s_chg) break;
    }

    // ---- counting sort by depth -> bfs order, level starts, cnt/min ----
    unsigned int* lvlcnt = (unsigned int*)(sm + 65536);     // reuse bidx
    unsigned int* lvlmin = (unsigned int*)(sm + 114176);    // fresh 16K
    unsigned int* cur    = (unsigned int*)(sm + 16384);     // reuse ptrA
    for (int i = tid; i < LL; i += 1024) { lvlcnt[i] = 0; lvlmin[i] = 0x7FFFFFFFu; }
    if (tid == 0) s_nl = 0;
    __syncthreads();
    for (int i = tid; i < LL; i += 1024) {
        unsigned d = dep[i];
        atomicAdd(&lvlcnt[d], 1u);
        atomicMin(&lvlmin[d], (unsigned)i);
        atomicMax(&s_nl, (int)d);
    }
    __syncthreads();
    if (tid == 0) {
        int nl = s_nl + 1;
        g_numlev[b] = nl;
        int run = 0;
        for (int d = 0; d < nl; d++) {
            g_lvl[b * (LL + 2) + d] = run;
            g_lvlcnt[b * (LL + 2) + d] = (int)lvlcnt[d];
            g_lvlmin[b * (LL + 2) + d] = (int)lvlmin[d];
            cur[d] = (unsigned)run;
            run += (int)lvlcnt[d];
        }
        g_lvl[b * (LL + 2) + nl] = LL;
    }
    __syncthreads();
    for (int i = tid; i < LL; i += 1024) {
        unsigned pos = atomicAdd(&cur[dep[i]], 1u);
        g_bfs[b * LL + pos] = i;
        g_parent[b * LL + i] = (int)par[i];
    }
}

// ------------------------- 5b. padded-scatter revert flags -----------------
__global__ void k_revert()
{
    __shared__ int nlmax;
    if (threadIdx.x == 0) {
        int m = 0;
        for (int b = 0; b < BB; b++) m = max(m, g_numlev[b]);
        nlmax = m;
    }
    __syncthreads();
    for (int d = threadIdx.x; d < nlmax; d += blockDim.x) {
        int cnt[BB];
        int md = 0;
        for (int b = 0; b < BB; b++) {
            int c = (d < g_numlev[b]) ? g_lvlcnt[b * (LL + 2) + d] : 0;
            cnt[b] = c;
            md = max(md, c);
        }
        for (int b = 0; b < BB; b++) {
            int r = (d > 0 && cnt[b] > 0 && cnt[b] < md)
                        ? g_lvlmin[b * (LL + 2) + d] : -1;
            g_revert[b * (LL + 2) + d] = r;
        }
    }
}

// ------------------------- 6. x_dbl projection ------------------------------
__global__ void k_xdbl(const float* __restrict__ XW)   // (8,192)
{
    int gid = blockIdx.x * blockDim.x + threadIdx.x;
    if (gid >= BB * LL) return;
    int b = gid >> 12, l = gid & 4095;
    const float* xp = g_xs + (size_t)b * DI * LL + l;
    float acc[8] = {0,0,0,0,0,0,0,0};
    for (int k = 0; k < DI; k++) {
        float xv = xp[(size_t)k * LL];
        #pragma unroll
        for (int c = 0; c < 8; c++) acc[c] += XW[c * DI + k] * xv;
    }
    #pragma unroll
    for (int r = 0; r < DR; r++) g_dtsr[((size_t)b * DR + r) * LL + l] = acc[r];
    g_Bsv[gid] = acc[6];
    g_Csv[gid] = acc[7];
}

// ------------------------- 7. dts / deltaA / BX -----------------------------
__global__ void k_bxew(const float* __restrict__ dtW, const float* __restrict__ dtB,
                       const float* __restrict__ Alog)
{
    int gid = blockIdx.x * blockDim.x + threadIdx.x;
    if (gid >= BB * DI * LL) return;
    int l = gid & 4095;
    int d = (gid >> 12) % DI;
    int b = gid / (DI * LL);
    const float* dr = g_dtsr + (size_t)b * DR * LL + l;
    float s = 0.f;
    #pragma unroll
    for (int r = 0; r < DR; r++) s += dr[(size_t)r * LL] * dtW[d * DR + r];
    float dt = softplusf(s + dtB[d]);
    float A  = -expf(Alog[d]);
    float ew = expf(dt * A);
    float bx = dt * g_Bsv[b * LL + l] * g_xs[gid];
    size_t o = ((size_t)(b * LL + l)) * DI + d;
    g_ew[o] = ew;
    g_up[o] = bx;
}

// ------------------------- 8. tree scan (up + down, level-synchronous) -----
// children of node = grid neighbors nb with par[nb]==node (MST edges are grid
// edges) -> no CSR needed.
__global__ void __launch_bounds__(256) k_scan()
{
    int b  = blockIdx.y;
    int c0 = blockIdx.x * 32;
    int tid = threadIdx.x;
    int nl = g_numlev[b];
    const int* lvl  = g_lvl + b * (LL + 2);
    const int* bfs  = g_bfs + b * LL;
    const int* par  = g_parent + b * LL;
    const int* revp = g_revert + b * (LL + 2);
    float* up = g_up + (size_t)b * LL * DI;
    float* ag = g_ag + (size_t)b * LL * DI;
    const float* ew = g_ew + (size_t)b * LL * DI;

    // up-sweep
    for (int lev = nl - 1; lev >= 0; --lev) {
        int ls = lvl[lev], le = lvl[lev + 1];
        int work = (le - ls) * 32;
        for (int i = tid; i < work; i += 256) {
            int node = bfs[ls + (i >> 5)];
            int c = c0 + (i & 31);
            int h = node >> 6, w = node & 63;
            float acc = up[(size_t)node * DI + c];
            if (w < 63) { int nb = node + 1;  if (par[nb] == node) acc += ew[(size_t)nb * DI + c] * up[(size_t)nb * DI + c]; }
            if (w > 0)  { int nb = node - 1;  if (par[nb] == node) acc += ew[(size_t)nb * DI + c] * up[(size_t)nb * DI + c]; }
            if (h < 63) { int nb = node + 64; if (par[nb] == node) acc += ew[(size_t)nb * DI + c] * up[(size_t)nb * DI + c]; }
            if (h > 0)  { int nb = node - 64; if (par[nb] == node) acc += ew[(size_t)nb * DI + c] * up[(size_t)nb * DI + c]; }
            up[(size_t)node * DI + c] = acc;
        }
        __syncthreads();
    }
    // down-sweep (with padded-scatter revert)
    for (int lev = 0; lev < nl; ++lev) {
        int ls = lvl[lev], le = lvl[lev + 1];
        int rev = revp[lev];
        int work = (le - ls) * 32;
        for (int i = tid; i < work; i += 256) {
            int node = bfs[ls + (i >> 5)];
            int c = c0 + (i & 31);
            float u = up[(size_t)node * DI + c];
            float val;
            if (lev == 0) {
                val = u;
            } else {
                int p = par[node];
                float w = ew[(size_t)node * DI + c];
                val = u + w * (ag[(size_t)p * DI + c] - w * u);
                if (node == rev) val = u;
            }
            ag[(size_t)node * DI + c] = val;
        }
        __syncthreads();
    }
}

// ------------------------- 9. fused LN -> *Cs -> +Ds*xs -> LN -> *z --------
__global__ void __launch_bounds__(256) k_fuse(const float* __restrict__ hg,
                                              const float* __restrict__ hb,
                                              const float* __restrict__ og,
                                              const float* __restrict__ ob,
                                              const float* __restrict__ Ds)
{
    int warp = (blockIdx.x * 256 + threadIdx.x) >> 5;
    int lane = threadIdx.x & 31;
    if (warp >= BB * LL) return;
    int b = warp >> 12, l = warp & 4095;
    const float* hrow = g_ag + (size_t)warp * DI;

    float v[6];
    #pragma unroll
    for (int j = 0; j < 6; j++) v[j] = hrow[lane + 32 * j];

    float s = 0.f;
    #pragma unroll
    for (int j = 0; j < 6; j++) s += v[j];
    float mu = warpsum(s) * (1.f / 192.f);
    float q = 0.f;
    #pragma unroll
    for (int j = 0; j < 6; j++) { float d = v[j] - mu; q += d * d; }
    float inv = rsqrtf(warpsum(q) * (1.f / 192.f) + 1e-5f);

    float Cv = g_Csv[warp];
    float y[6];
    #pragma unroll
    for (int j = 0; j < 6; j++) {
        int c = lane + 32 * j;
        float hn = (v[j] - mu) * inv * hg[c] + hb[c];
        y[j] = hn * Cv + Ds[c] * g_xs[((size_t)b * DI + c) * LL + l];
    }

    s = 0.f;
    #pragma unroll
    for (int j = 0; j < 6; j++) s += y[j];
    float mu2 = warpsum(s) * (1.f / 192.f);
    q = 0.f;
    #pragma unroll
    for (int j = 0; j < 6; j++) { float d = y[j] - mu2; q += d * d; }
    float inv2 = rsqrtf(warpsum(q) * (1.f / 192.f) + 1e-5f);

    #pragma unroll
    for (int j = 0; j < 6; j++) {
        int c = lane + 32 * j;
        float y2 = (y[j] - mu2) * inv2 * og[c] + ob[c];
        g_yz[(size_t)warp * DI + c] = y2 * g_z[(size_t)warp * DI + c];
    }
}

// ------------------------- 10. out_proj GEMM -------------------------------
__global__ void __launch_bounds__(256) k_gemm_out(const float* __restrict__ W,
                                                  float* __restrict__ out)
{
    __shared__ float sA[64][33];
    __shared__ float sW[64][33];
    int bm = blockIdx.y * 64, bn = blockIdx.x * 64;
    int tid = threadIdx.x;
    int tx = tid & 15, ty = tid >> 4;
    float acc[4][4] = {};
    for (int k0 = 0; k0 < 192; k0 += 32) {
        for (int t = tid; t < 512; t += 256) {
            int r = t >> 3, kq = t & 7;
            float4 va = *(const float4*)(g_yz + (size_t)(bm + r) * 192 + k0 + kq * 4);
            sA[r][kq*4+0] = va.x; sA[r][kq*4+1] = va.y;
            sA[r][kq*4+2] = va.z; sA[r][kq*4+3] = va.w;
            float4 vw;
            if (bn + r < 96)
                vw = *(const float4*)(W + (size_t)(bn + r) * 192 + k0 + kq * 4);
            else
                vw = make_float4(0.f, 0.f, 0.f, 0.f);
            sW[r][kq*4+0] = vw.x; sW[r][kq*4+1] = vw.y;
            sW[r][kq*4+2] = vw.z; sW[r][kq*4+3] = vw.w;
        }
        __syncthreads();
        #pragma unroll
        for (int k = 0; k < 32; k++) {
            float a[4], bv[4];
            #pragma unroll
            for (int i = 0; i < 4; i++) { a[i] = sA[ty*4+i][k]; bv[i] = sW[tx*4+i][k]; }
            #pragma unroll
            for (int i = 0; i < 4; i++)
                #pragma unroll
                for (int j = 0; j < 4; j++)
                    acc[i][j] += a[i] * bv[j];
        }
        __syncthreads();
    }
    #pragma unroll
    for (int i = 0; i < 4; i++) {
        int m = bm + ty * 4 + i;
        #pragma unroll
        for (int j = 0; j < 4; j++) {
            int n = bn + tx * 4 + j;
            if (n < 96) out[(size_t)m * 96 + n] = acc[i][j];
        }
    }
}

// ------------------------- launch ------------------------------------------
extern "C" void kernel_launch(void* const* d_in, const int* in_sizes, int n_in,
                              void* d_out, int out_size)
{
    const float* x    = (const float*)d_in[0];
    const float* inw  = (const float*)d_in[1];
    const float* cw   = (const float*)d_in[2];
    const float* cb   = (const float*)d_in[3];
    const float* xpw  = (const float*)d_in[4];
    const float* dtw  = (const float*)d_in[5];
    const float* dtb  = (const float*)d_in[6];
    const float* alog = (const float*)d_in[7];
    const float* Dsp  = (const float*)d_in[8];
    const float* hg   = (const float*)d_in[9];
    const float* hbp  = (const float*)d_in[10];
    const float* og   = (const float*)d_in[11];
    const float* obp  = (const float*)d_in[12];
    const float* opw  = (const float*)d_in[13];
    float* out = (float*)d_out;

    k_gemm_in<<<dim3(6, 512), 256>>>(x, inw);
    k_conv<<<(BB * DI * LL + 255) / 256, 256>>>(cw, cb);
    k_fn<<<(BB * LL + 255) / 256, 256>>>();
    k_edge<<<(BB * NE + 255) / 256, 256>>>();

    const int BORSMEM = 131072;   // comp/ptr/best/bidx/flag + lvl arrays (aliased)
    cudaFuncSetAttribute(k_boruvka, cudaFuncAttributeMaxDynamicSharedMemorySize, BORSMEM);
    k_boruvka<<<BB, 1024, BORSMEM>>>();
    k_revert<<<1, 256>>>();

    k_xdbl<<<(BB * LL + 255) / 256, 256>>>(xpw);
    k_bxew<<<(BB * DI * LL + 255) / 256, 256>>>(dtw, dtb, alog);
    k_scan<<<dim3(6, BB), 256>>>();
    k_fuse<<<(BB * LL * 32 + 255) / 256, 256>>>(hg, hbp, og, obp, Dsp);
    k_gemm_out<<<dim3(2, 512), 256>>>(opw, out);
}

// round 5
// speedup vs baseline: 1.9211x; 1.1151x over previous
#include <cuda_runtime.h>
#include <math.h>

#define BB 8
#define HH 64
#define WW 64
#define LL 4096
#define DM 96
#define DI 192
#define DR 6
#define NE 8064

// ------------------------- device scratch (static, no mallocs) -------------
static __device__ __align__(16) float  g_z[BB*LL*DI];      // (b,l,c) silu(z)
static __device__ __align__(16) float  g_xcpre[BB*DI*LL];  // (b,c,l) pre-conv
static __device__ __align__(16) float  g_xs[BB*DI*LL];     // (b,c,l) silu(conv)
static __device__ __align__(16) float  g_xst[BB*LL*DI];    // (b,l,c) transposed
static __device__ __align__(16) double g_fn[BB*DI*LL];     // (b,c,l) normalized feats
static __device__ unsigned long long   g_keys[BB*NE];
static __device__ int    g_pos[BB*LL];                     // node -> bfs position
static __device__ int    g_parp[BB*LL];                    // pos -> parent pos
static __device__ __align__(16) int4 g_childp[BB*LL];      // pos -> child positions
static __device__ int    g_lvl[BB*(LL+2)];
static __device__ int    g_lvlcnt[BB*(LL+2)];
static __device__ int    g_lvlmin[BB*(LL+2)];
static __device__ int    g_revert[BB*(LL+2)];              // pos (or -1) per level
static __device__ int    g_numlev[BB];
static __device__ float  g_Csv[BB*LL];
static __device__ __align__(16) float2 g_eu[BB*LL*DI];     // pos-ordered (ew, up)
static __device__ __align__(16) float  g_ag[BB*LL*DI];     // pos-ordered aggr
static __device__ __align__(16) float  g_yz[BB*LL*DI];     // (b,l,c)

// ------------------------- helpers -----------------------------------------
__device__ __forceinline__ float siluf(float x){ return x / (1.f + expf(-x)); }
__device__ __forceinline__ float softplusf(float x){
    return fmaxf(x, 0.f) + log1pf(expf(-fabsf(x)));
}
__device__ __forceinline__ float warpsum(float v){
    #pragma unroll
    for (int o = 16; o > 0; o >>= 1) v += __shfl_xor_sync(0xFFFFFFFFu, v, o);
    return v;
}
__device__ __forceinline__ void edge_uv(int e, int& u, int& v){
    if (e < 4032) { int r = e / 63, c = e % 63; u = r * 64 + c; v = u + 1; }
    else          { int j = e - 4032; u = j; v = j + 64; }
}

// ------------------------- 1. in_proj GEMM + split/silu (coalesced out) ----
__global__ void __launch_bounds__(256) k_gemm_in(const float* __restrict__ A,
                                                 const float* __restrict__ W)
{
    __shared__ float sA[64][33];
    __shared__ float sW[64][33];
    __shared__ float st[64][68];
    int bm = blockIdx.y * 64, bn = blockIdx.x * 64;
    int tid = threadIdx.x;
    int tx = tid & 15, ty = tid >> 4;
    float acc[4][4] = {};
    for (int k0 = 0; k0 < 96; k0 += 32) {
        for (int t = tid; t < 512; t += 256) {
            int r = t >> 3, kq = t & 7;
            float4 va = *(const float4*)(A + (size_t)(bm + r) * 96 + k0 + kq * 4);
            sA[r][kq*4+0] = va.x; sA[r][kq*4+1] = va.y;
            sA[r][kq*4+2] = va.z; sA[r][kq*4+3] = va.w;
            float4 vw = *(const float4*)(W + (size_t)(bn + r) * 96 + k0 + kq * 4);
            sW[r][kq*4+0] = vw.x; sW[r][kq*4+1] = vw.y;
            sW[r][kq*4+2] = vw.z; sW[r][kq*4+3] = vw.w;
        }
        __syncthreads();
        #pragma unroll
        for (int k = 0; k < 32; k++) {
            float a[4], b[4];
            #pragma unroll
            for (int i = 0; i < 4; i++) { a[i] = sA[ty*4+i][k]; b[i] = sW[tx*4+i][k]; }
            #pragma unroll
            for (int i = 0; i < 4; i++)
                #pragma unroll
                for (int j = 0; j < 4; j++)
                    acc[i][j] += a[i] * b[j];
        }
        __syncthreads();
    }
    int b = bm >> 12, l0 = bm & 4095;
    if (bn < DI) {
        // stage transposed: st[n_local][m_local]
        #pragma unroll
        for (int i = 0; i < 4; i++)
            #pragma unroll
            for (int j = 0; j < 4; j++)
                st[tx*4+j][ty*4+i] = acc[i][j];
        __syncthreads();
        #pragma unroll
        for (int pass = 0; pass < 4; pass++) {
            int nn = pass * 16 + (tid >> 4);
            int mm = (tid & 15) * 4;
            float4 v = *(float4*)&st[nn][mm];
            *(float4*)&g_xcpre[((size_t)(b * DI + bn + nn)) * LL + l0 + mm] = v;
        }
    } else {
        int cb = bn - DI;
        #pragma unroll
        for (int i = 0; i < 4; i++)
            #pragma unroll
            for (int j = 0; j < 4; j++)
                st[ty*4+i][tx*4+j] = acc[i][j];
        __syncthreads();
        #pragma unroll
        for (int pass = 0; pass < 4; pass++) {
            int mm = pass * 16 + (tid >> 4);
            int nn = (tid & 15) * 4;
            float4 v = *(float4*)&st[mm][nn];
            v.x = siluf(v.x); v.y = siluf(v.y); v.z = siluf(v.z); v.w = siluf(v.w);
            *(float4*)&g_z[((size_t)(bm + mm)) * DI + cb + nn] = v;
        }
    }
}

// ------------------------- 2. depthwise 3x3 conv + silu --------------------
__global__ void k_conv(const float* __restrict__ cw, const float* __restrict__ cb)
{
    int gid = blockIdx.x * blockDim.x + threadIdx.x;
    if (gid >= BB * DI * LL) return;
    int l = gid & 4095;
    int c = (gid >> 12) % DI;
    int h = l >> 6, w = l & 63;
    const float* src = g_xcpre + (size_t)(gid - l);
    float acc = cb[c];
    #pragma unroll
    for (int ky = 0; ky < 3; ky++) {
        int hy = h + ky - 1;
        if ((unsigned)hy >= 64u) continue;
        #pragma unroll
        for (int kx = 0; kx < 3; kx++) {
            int wx = w + kx - 1;
            if ((unsigned)wx >= 64u) continue;
            acc += src[hy * 64 + wx] * cw[c * 9 + ky * 3 + kx];
        }
    }
    g_xs[gid] = siluf(acc);
}

// ------------------------- 2b. transpose xs (c,l) -> (l,c) -----------------
__global__ void __launch_bounds__(256) k_xt()
{
    __shared__ float t[32][33];
    int b  = blockIdx.z;
    int c0 = blockIdx.y * 32;
    int l0 = blockIdx.x * 32;
    int tx = threadIdx.x, ty = threadIdx.y;   // 32 x 8
    #pragma unroll
    for (int k = 0; k < 4; k++)
        t[ty + 8 * k][tx] = g_xs[((size_t)(b * DI + c0 + ty + 8 * k)) * LL + l0 + tx];
    __syncthreads();
    #pragma unroll
    for (int k = 0; k < 4; k++)
        g_xst[((size_t)(b * LL + l0 + ty + 8 * k)) * DI + c0 + tx] = t[tx][ty + 8 * k];
}

// ------------------------- 3. normalized features (double) -----------------
__global__ void k_fn()
{
    int gid = blockIdx.x * blockDim.x + threadIdx.x;  // b*L + l
    if (gid >= BB * LL) return;
    int b = gid >> 12, l = gid & 4095;
    const float* xp = g_xs + (size_t)b * DI * LL + l;
    double s = 0.0;
    for (int c = 0; c < DI; c++) {
        double v = (double)xp[(size_t)c * LL];
        s += v * v;
    }
    double nrm = sqrt(s);
    double den = nrm > 1e-8 ? nrm : 1e-8;
    double* fp = g_fn + (size_t)b * DI * LL + l;
    for (int c = 0; c < DI; c++)
        fp[(size_t)c * LL] = (double)xp[(size_t)c * LL] / den;
}

// ------------------------- 4. edge weights (double, sortable key) ----------
__global__ void k_edge()
{
    int gid = blockIdx.x * blockDim.x + threadIdx.x;
    if (gid >= BB * NE) return;
    int b = gid / NE, e = gid % NE;
    int u, v;
    edge_uv(e, u, v);
    const double* f = g_fn + (size_t)b * DI * LL;
    double s = 0.0;
    for (int c = 0; c < DI; c++)
        s += f[(size_t)c * LL + u] * f[(size_t)c * LL + v];
    double w = exp(-s);
    g_keys[gid] = (unsigned long long)__double_as_longlong(w);
}

// ------------------------- 5. Boruvka MST + levels (one block / batch) -----
__global__ void __launch_bounds__(1024, 1) k_boruvka()
{
    extern __shared__ unsigned char sm[];
    unsigned int*       comp = (unsigned int*)sm;                    // 16K
    unsigned int*       ptrA = (unsigned int*)(sm + 16384);          // 16K
    unsigned long long* best = (unsigned long long*)(sm + 32768);    // 32K
    unsigned int*       bidx = (unsigned int*)(sm + 65536);          // 16K
    unsigned int*       flag = (unsigned int*)(sm + 81920);          // 32K (NE)
    __shared__ int s_done, s_chg, s_nl;

    int b = blockIdx.x;
    int tid = threadIdx.x;
    const unsigned long long* keys = g_keys + (size_t)b * NE;

    for (int i = tid; i < LL; i += 1024) comp[i] = (unsigned)i;
    for (int e = tid; e < NE; e += 1024) flag[e] = 0;
    __syncthreads();

    for (int round = 0; round < 14; round++) {
        for (int i = tid; i < LL; i += 1024) { best[i] = ~0ULL; bidx[i] = 0xFFFFFFFFu; }
        if (tid == 0) s_done = 1;
        __syncthreads();

        for (int e = tid; e < NE; e += 1024) {
            int u, v; edge_uv(e, u, v);
            unsigned cu = comp[u], cv = comp[v];
            if (cu != cv) {
                unsigned long long k = keys[e];
                atomicMin(&best[cu], k);
                atomicMin(&best[cv], k);
            }
        }
        __syncthreads();
        for (int e = tid; e < NE; e += 1024) {
            int u, v; edge_uv(e, u, v);
            unsigned cu = comp[u], cv = comp[v];
            if (cu != cv) {
                unsigned long long k = keys[e];
                if (k == best[cu]) atomicMin(&bidx[cu], (unsigned)e);
                if (k == best[cv]) atomicMin(&bidx[cv], (unsigned)e);
            }
        }
        __syncthreads();
        for (int c = tid; c < LL; c += 1024) {
            unsigned e = bidx[c];
            if (e != 0xFFFFFFFFu) {
                flag[e] = 1u;
                int u, v; edge_uv((int)e, u, v);
                unsigned cu = comp[u], cv = comp[v];
                ptrA[c] = (cu == (unsigned)c) ? cv : cu;
                s_done = 0;
            } else {
                ptrA[c] = (unsigned)c;
            }
        }
        __syncthreads();
        if (s_done) break;
        for (int c = tid; c < LL; c += 1024) {
            unsigned p = ptrA[c];
            if (p != (unsigned)c && ptrA[p] == (unsigned)c && (unsigned)c < p)
                ptrA[c] = (unsigned)c;
        }
        __syncthreads();
        for (int it = 0; it < 13; it++) {
            if (tid == 0) s_chg = 0;
            __syncthreads();
            for (int c = tid; c < LL; c += 1024) {
                unsigned p = ptrA[c];
                unsigned g = ptrA[p];
                if (p != g) { ptrA[c] = g; s_chg = 1; }
            }
            __syncthreads();
            if (!s_chg) break;
        }
        for (int i = tid; i < LL; i += 1024) comp[i] = ptrA[comp[i]];
        __syncthreads();
    }

    // ---- parallel level propagation: par/dep from root 0 ----
    unsigned int* dep = (unsigned int*)(sm + 32768);   // reuse best
    unsigned int* par = (unsigned int*)(sm + 49152);
    for (int i = tid; i < LL; i += 1024) dep[i] = 0xFFFFFFFFu;
    __syncthreads();
    if (tid == 0) { dep[0] = 0; par[0] = 0; }
    __syncthreads();

    for (unsigned r = 0;; r++) {
        if (tid == 0) s_chg = 0;
        __syncthreads();
        for (int i = tid; i < LL; i += 1024) {
            if (dep[i] != 0xFFFFFFFFu) continue;
            int h = i >> 6, w = i & 63;
            int pfound = -1;
            if (w < 63 && flag[h * 63 + w]          && dep[i + 1]  == r) pfound = i + 1;
            else if (w > 0  && flag[h * 63 + w - 1] && dep[i - 1]  == r) pfound = i - 1;
            else if (h < 63 && flag[4032 + i]       && dep[i + 64] == r) pfound = i + 64;
            else if (h > 0  && flag[4032 + i - 64]  && dep[i - 64] == r) pfound = i - 64;
            if (pfound >= 0) {
                par[i] = (unsigned)pfound;
                dep[i] = r + 1;
                s_chg = 1;
            }
        }
        __syncthreads();
        if (!s_chg) break;
    }

    // ---- counting sort by depth -> positions, level starts, cnt/min -------
    unsigned int* lvlcnt = (unsigned int*)(sm + 65536);     // reuse bidx
    unsigned int* lvlmin = (unsigned int*)(sm + 114176);    // fresh 16K
    unsigned int* cur    = (unsigned int*)(sm + 16384);     // reuse ptrA
    unsigned int* posA   = (unsigned int*)sm;               // reuse comp
    for (int i = tid; i < LL; i += 1024) { lvlcnt[i] = 0; lvlmin[i] = 0x7FFFFFFFu; }
    if (tid == 0) s_nl = 0;
    __syncthreads();
    for (int i = tid; i < LL; i += 1024) {
        unsigned d = dep[i];
        atomicAdd(&lvlcnt[d], 1u);
        atomicMin(&lvlmin[d], (unsigned)i);
        atomicMax(&s_nl, (int)d);
    }
    __syncthreads();
    if (tid == 0) {
        int nl = s_nl + 1;
        g_numlev[b] = nl;
        int run = 0;
        for (int d = 0; d < nl; d++) {
            g_lvl[b * (LL + 2) + d] = run;
            g_lvlcnt[b * (LL + 2) + d] = (int)lvlcnt[d];
            g_lvlmin[b * (LL + 2) + d] = (int)lvlmin[d];
            cur[d] = (unsigned)run;
            run += (int)lvlcnt[d];
        }
        g_lvl[b * (LL + 2) + nl] = LL;
    }
    __syncthreads();
    for (int i = tid; i < LL; i += 1024)
        posA[i] = atomicAdd(&cur[dep[i]], 1u);
    __syncthreads();
    // emit pos-ordered tree structure
    for (int i = tid; i < LL; i += 1024) {
        unsigned p = posA[i];
        g_pos[b * LL + i] = (int)p;
        g_parp[b * LL + p] = (int)posA[par[i]];
        int h = i >> 6, w = i & 63;
        int a[4]; int k = 0;
        if (w < 63 && par[i + 1]  == (unsigned)i) a[k++] = (int)posA[i + 1];
        if (w > 0  && par[i - 1]  == (unsigned)i) a[k++] = (int)posA[i - 1];
        if (h < 63 && par[i + 64] == (unsigned)i) a[k++] = (int)posA[i + 64];
        if (h > 0  && par[i - 64] == (unsigned)i) a[k++] = (int)posA[i - 64];
        int4 cp;
        cp.x = k > 0 ? a[0] : -1;
        cp.y = k > 1 ? a[1] : -1;
        cp.z = k > 2 ? a[2] : -1;
        cp.w = k > 3 ? a[3] : -1;
        g_childp[b * LL + p] = cp;
    }
}

// ------------------------- 5b. padded-scatter revert flags (as pos) --------
__global__ void k_revert()
{
    __shared__ int nlmax;
    if (threadIdx.x == 0) {
        int m = 0;
        for (int b = 0; b < BB; b++) m = max(m, g_numlev[b]);
        nlmax = m;
    }
    __syncthreads();
    for (int d = threadIdx.x; d < nlmax; d += blockDim.x) {
        int cnt[BB];
        int md = 0;
        for (int b = 0; b < BB; b++) {
            int c = (d < g_numlev[b]) ? g_lvlcnt[b * (LL + 2) + d] : 0;
            cnt[b] = c;
            md = max(md, c);
        }
        for (int b = 0; b < BB; b++) {
            int r = -1;
            if (d > 0 && cnt[b] > 0 && cnt[b] < md)
                r = g_pos[b * LL + g_lvlmin[b * (LL + 2) + d]];
            g_revert[b * (LL + 2) + d] = r;
        }
    }
}

// ------------------------- 6. fused x_dbl + dts/deltaA/BX (warp per node) --
__global__ void __launch_bounds__(256) k_ssm(const float* __restrict__ XW,
                                             const float* __restrict__ dtW,
                                             const float* __restrict__ dtB,
                                             const float* __restrict__ Alog)
{
    int gw = (blockIdx.x * 256 + threadIdx.x) >> 5;   // b*LL + l
    int lane = threadIdx.x & 31;
    if (gw >= BB * LL) return;
    int b = gw >> 12;
    const float* xrow = g_xst + (size_t)gw * DI;

    float xv[6];
    #pragma unroll
    for (int j = 0; j < 6; j++) xv[j] = xrow[lane + 32 * j];

    float acc[8];
    #pragma unroll
    for (int c8 = 0; c8 < 8; c8++) {
        float s = 0.f;
        #pragma unroll
        for (int j = 0; j < 6; j++) s += xv[j] * XW[c8 * DI + lane + 32 * j];
        acc[c8] = warpsum(s);
    }
    float Bsv = acc[6];
    if (lane == 0) g_Csv[gw] = acc[7];

    int pos = g_pos[gw];
    float2* eurow = g_eu + ((size_t)(b * LL) + pos) * DI;
    #pragma unroll
    for (int j = 0; j < 6; j++) {
        int d = lane + 32 * j;
        float s = dtB[d];
        #pragma unroll
        for (int r = 0; r < DR; r++) s += acc[r] * dtW[d * DR + r];
        float dt = softplusf(s);
        float ew = expf(-expf(Alog[d]) * dt);
        float bx = dt * Bsv * xv[j];
        eurow[d] = make_float2(ew, bx);
    }
}

// ------------------------- 7. tree scan (pos-ordered, level-synchronous) ---
__global__ void __launch_bounds__(256) k_scan()
{
    int b  = blockIdx.y;
    int c0 = blockIdx.x * 32;
    int tid = threadIdx.x;
    int nl = g_numlev[b];
    const int*  lvl   = g_lvl + b * (LL + 2);
    const int*  revp  = g_revert + b * (LL + 2);
    const int*  parp  = g_parp + b * LL;
    const int4* chp   = g_childp + b * LL;
    float2* eu = g_eu + (size_t)(b * LL) * DI;
    float*  ag = g_ag + (size_t)(b * LL) * DI;

    // up-sweep
    for (int lev = nl - 1; lev >= 0; --lev) {
        int ls = lvl[lev], le = lvl[lev + 1];
        int work = (le - ls) * 32;
        for (int i = tid; i < work; i += 256) {
            int pos = ls + (i >> 5);
            int c = c0 + (i & 31);
            int4 ch = chp[pos];
            float acc = eu[(size_t)pos * DI + c].y;
            if (ch.x >= 0) { float2 t = eu[(size_t)ch.x * DI + c]; acc += t.x * t.y; }
            if (ch.y >= 0) { float2 t = eu[(size_t)ch.y * DI + c]; acc += t.x * t.y; }
            if (ch.z >= 0) { float2 t = eu[(size_t)ch.z * DI + c]; acc += t.x * t.y; }
            if (ch.w >= 0) { float2 t = eu[(size_t)ch.w * DI + c]; acc += t.x * t.y; }
            eu[(size_t)pos * DI + c].y = acc;
        }
        __syncthreads();
    }
    // down-sweep (with padded-scatter revert)
    for (int lev = 0; lev < nl; ++lev) {
        int ls = lvl[lev], le = lvl[lev + 1];
        int rev = revp[lev];
        int work = (le - ls) * 32;
        for (int i = tid; i < work; i += 256) {
            int pos = ls + (i >> 5);
            int c = c0 + (i & 31);
            float2 e = eu[(size_t)pos * DI + c];
            float u = e.y;
            float val;
            if (lev == 0) {
                val = u;
            } else {
                int pp = parp[pos];
                float w = e.x;
                val = u + w * (ag[(size_t)pp * DI + c] - w * u);
                if (pos == rev) val = u;
            }
            ag[(size_t)pos * DI + c] = val;
        }
        __syncthreads();
    }
}

// ------------------------- 8. fused LN -> *Cs -> +Ds*xs -> LN -> *z --------
__global__ void __launch_bounds__(256) k_fuse(const float* __restrict__ hg,
                                              const float* __restrict__ hb,
                                              const float* __restrict__ og,
                                              const float* __restrict__ ob,
                                              const float* __restrict__ Ds)
{
    int warp = (blockIdx.x * 256 + threadIdx.x) >> 5;
    int lane = threadIdx.x & 31;
    if (warp >= BB * LL) return;
    int b = warp >> 12;
    int pos = g_pos[warp];
    const float* hrow = g_ag + ((size_t)(b * LL) + pos) * DI;
    const float* xrow = g_xst + (size_t)warp * DI;

    float v[6];
    #pragma unroll
    for (int j = 0; j < 6; j++) v[j] = hrow[lane + 32 * j];

    float s = 0.f;
    #pragma unroll
    for (int j = 0; j < 6; j++) s += v[j];
    float mu = warpsum(s) * (1.f / 192.f);
    float q = 0.f;
    #pragma unroll
    for (int j = 0; j < 6; j++) { float d = v[j] - mu; q += d * d; }
    float inv = rsqrtf(warpsum(q) * (1.f / 192.f) + 1e-5f);

    float Cv = g_Csv[warp];
    float y[6];
    #pragma unroll
    for (int j = 0; j < 6; j++) {
        int c = lane + 32 * j;
        float hn = (v[j] - mu) * inv * hg[c] + hb[c];
        y[j] = hn * Cv + Ds[c] * xrow[c];
    }

    s = 0.f;
    #pragma unroll
    for (int j = 0; j < 6; j++) s += y[j];
    float mu2 = warpsum(s) * (1.f / 192.f);
    q = 0.f;
    #pragma unroll
    for (int j = 0; j < 6; j++) { float d = y[j] - mu2; q += d * d; }
    float inv2 = rsqrtf(warpsum(q) * (1.f / 192.f) + 1e-5f);

    #pragma unroll
    for (int j = 0; j < 6; j++) {
        int c = lane + 32 * j;
        float y2 = (y[j] - mu2) * inv2 * og[c] + ob[c];
        g_yz[(size_t)warp * DI + c] = y2 * g_z[(size_t)warp * DI + c];
    }
}

// ------------------------- 9. out_proj GEMM --------------------------------
__global__ void __launch_bounds__(256) k_gemm_out(const float* __restrict__ W,
                                                  float* __restrict__ out)
{
    __shared__ float sA[64][33];
    __shared__ float sW[64][33];
    int bm = blockIdx.y * 64, bn = blockIdx.x * 64;
    int tid = threadIdx.x;
    int tx = tid & 15, ty = tid >> 4;
    float acc[4][4] = {};
    for (int k0 = 0; k0 < 192; k0 += 32) {
        for (int t = tid; t < 512; t += 256) {
            int r = t >> 3, kq = t & 7;
            float4 va = *(const float4*)(g_yz + (size_t)(bm + r) * 192 + k0 + kq * 4);
            sA[r][kq*4+0] = va.x; sA[r][kq*4+1] = va.y;
            sA[r][kq*4+2] = va.z; sA[r][kq*4+3] = va.w;
            float4 vw;
            if (bn + r < 96)
                vw = *(const float4*)(W + (size_t)(bn + r) * 192 + k0 + kq * 4);
            else
                vw = make_float4(0.f, 0.f, 0.f, 0.f);
            sW[r][kq*4+0] = vw.x; sW[r][kq*4+1] = vw.y;
            sW[r][kq*4+2] = vw.z; sW[r][kq*4+3] = vw.w;
        }
        __syncthreads();
        #pragma unroll
        for (int k = 0; k < 32; k++) {
            float a[4], bv[4];
            #pragma unroll
            for (int i = 0; i < 4; i++) { a[i] = sA[ty*4+i][k]; bv[i] = sW[tx*4+i][k]; }
            #pragma unroll
            for (int i = 0; i < 4; i++)
                #pragma unroll
                for (int j = 0; j < 4; j++)
                    acc[i][j] += a[i] * bv[j];
        }
        __syncthreads();
    }
    #pragma unroll
    for (int i = 0; i < 4; i++) {
        int m = bm + ty * 4 + i;
        #pragma unroll
        for (int j = 0; j < 4; j++) {
            int n = bn + tx * 4 + j;
            if (n < 96) out[(size_t)m * 96 + n] = acc[i][j];
        }
    }
}

// ------------------------- launch ------------------------------------------
extern "C" void kernel_launch(void* const* d_in, const int* in_sizes, int n_in,
                              void* d_out, int out_size)
{
    const float* x    = (const float*)d_in[0];
    const float* inw  = (const float*)d_in[1];
    const float* cw   = (const float*)d_in[2];
    const float* cb   = (const float*)d_in[3];
    const float* xpw  = (const float*)d_in[4];
    const float* dtw  = (const float*)d_in[5];
    const float* dtb  = (const float*)d_in[6];
    const float* alog = (const float*)d_in[7];
    const float* Dsp  = (const float*)d_in[8];
    const float* hg   = (const float*)d_in[9];
    const float* hbp  = (const float*)d_in[10];
    const float* og   = (const float*)d_in[11];
    const float* obp  = (const float*)d_in[12];
    const float* opw  = (const float*)d_in[13];
    float* out = (float*)d_out;

    k_gemm_in<<<dim3(6, 512), 256>>>(x, inw);
    k_conv<<<(BB * DI * LL + 255) / 256, 256>>>(cw, cb);
    k_xt<<<dim3(128, 6, 8), dim3(32, 8)>>>();
    k_fn<<<(BB * LL + 255) / 256, 256>>>();
    k_edge<<<(BB * NE + 255) / 256, 256>>>();

    const int BORSMEM = 131072;
    cudaFuncSetAttribute(k_boruvka, cudaFuncAttributeMaxDynamicSharedMemorySize, BORSMEM);
    k_boruvka<<<BB, 1024, BORSMEM>>>();
    k_revert<<<1, 256>>>();

    k_ssm<<<(BB * LL * 32 + 255) / 256, 256>>>(xpw, dtw, dtb, alog);
    k_scan<<<dim3(6, BB), 256>>>();
    k_fuse<<<(BB * LL * 32 + 255) / 256, 256>>>(hg, hbp, og, obp, Dsp);
    k_gemm_out<<<dim3(2, 512), 256>>>(opw, out);
}

// round 6
// speedup vs baseline: 3.7833x; 1.9693x over previous
#include <cuda_runtime.h>
#include <math.h>

#define BB 8
#define HH 64
#define WW 64
#define LL 4096
#define DM 96
#define DI 192
#define DR 6
#define NE 8064

// ------------------------- device scratch (static, no mallocs) -------------
static __device__ __align__(16) float  g_z[BB*LL*DI];      // (b,l,c) silu(z)
static __device__ __align__(16) float  g_xcpre[BB*DI*LL];  // (b,c,l) pre-conv
static __device__ __align__(16) float  g_xs[BB*DI*LL];     // (b,c,l) silu(conv)
static __device__ __align__(16) float  g_xst[BB*LL*DI];    // (b,l,c) transposed
static __device__ double g_rinv[BB*LL];                    // 1/max(norm,1e-8)
static __device__ unsigned long long   g_keys[BB*NE];      // packed (key|idx)
static __device__ int    g_pos[BB*LL];                     // node -> bfs position
static __device__ int    g_parp[BB*LL];                    // pos -> parent pos
static __device__ __align__(16) int4 g_childp[BB*LL];      // pos -> child positions
static __device__ int    g_lvl[BB*(LL+2)];
static __device__ int    g_lvlcnt[BB*(LL+2)];
static __device__ int    g_lvlmin[BB*(LL+2)];
static __device__ int    g_revert[BB*(LL+2)];              // pos (or -1) per level
static __device__ int    g_numlev[BB];
static __device__ float  g_Csv[BB*LL];
static __device__ __align__(16) float2 g_eu[BB*LL*DI];     // pos-ordered (ew, up)
static __device__ __align__(16) float  g_ag[BB*LL*DI];     // pos-ordered aggr
static __device__ __align__(16) float  g_yz[BB*LL*DI];     // (b,l,c)

// ------------------------- helpers -----------------------------------------
__device__ __forceinline__ float siluf(float x){ return x / (1.f + expf(-x)); }
__device__ __forceinline__ float softplusf(float x){
    return fmaxf(x, 0.f) + log1pf(expf(-fabsf(x)));
}
__device__ __forceinline__ float warpsum(float v){
    #pragma unroll
    for (int o = 16; o > 0; o >>= 1) v += __shfl_xor_sync(0xFFFFFFFFu, v, o);
    return v;
}
__device__ __forceinline__ void edge_uv(int e, int& u, int& v){
    if (e < 4032) { int r = e / 63, c = e % 63; u = r * 64 + c; v = u + 1; }
    else          { int j = e - 4032; u = j; v = j + 64; }
}

// ------------------------- 1. in_proj GEMM + split/silu (coalesced out) ----
__global__ void __launch_bounds__(256) k_gemm_in(const float* __restrict__ A,
                                                 const float* __restrict__ W)
{
    __shared__ float sA[64][33];
    __shared__ float sW[64][33];
    __shared__ float st[64][68];
    int bm = blockIdx.y * 64, bn = blockIdx.x * 64;
    int tid = threadIdx.x;
    int tx = tid & 15, ty = tid >> 4;
    float acc[4][4] = {};
    for (int k0 = 0; k0 < 96; k0 += 32) {
        for (int t = tid; t < 512; t += 256) {
            int r = t >> 3, kq = t & 7;
            float4 va = *(const float4*)(A + (size_t)(bm + r) * 96 + k0 + kq * 4);
            sA[r][kq*4+0] = va.x; sA[r][kq*4+1] = va.y;
            sA[r][kq*4+2] = va.z; sA[r][kq*4+3] = va.w;
            float4 vw = *(const float4*)(W + (size_t)(bn + r) * 96 + k0 + kq * 4);
            sW[r][kq*4+0] = vw.x; sW[r][kq*4+1] = vw.y;
            sW[r][kq*4+2] = vw.z; sW[r][kq*4+3] = vw.w;
        }
        __syncthreads();
        #pragma unroll
        for (int k = 0; k < 32; k++) {
            float a[4], b[4];
            #pragma unroll
            for (int i = 0; i < 4; i++) { a[i] = sA[ty*4+i][k]; b[i] = sW[tx*4+i][k]; }
            #pragma unroll
            for (int i = 0; i < 4; i++)
                #pragma unroll
                for (int j = 0; j < 4; j++)
                    acc[i][j] += a[i] * b[j];
        }
        __syncthreads();
    }
    int b = bm >> 12, l0 = bm & 4095;
    if (bn < DI) {
        #pragma unroll
        for (int i = 0; i < 4; i++)
            #pragma unroll
            for (int j = 0; j < 4; j++)
                st[tx*4+j][ty*4+i] = acc[i][j];
        __syncthreads();
        #pragma unroll
        for (int pass = 0; pass < 4; pass++) {
            int nn = pass * 16 + (tid >> 4);
            int mm = (tid & 15) * 4;
            float4 v = *(float4*)&st[nn][mm];
            *(float4*)&g_xcpre[((size_t)(b * DI + bn + nn)) * LL + l0 + mm] = v;
        }
    } else {
        int cb = bn - DI;
        #pragma unroll
        for (int i = 0; i < 4; i++)
            #pragma unroll
            for (int j = 0; j < 4; j++)
                st[ty*4+i][tx*4+j] = acc[i][j];
        __syncthreads();
        #pragma unroll
        for (int pass = 0; pass < 4; pass++) {
            int mm = pass * 16 + (tid >> 4);
            int nn = (tid & 15) * 4;
            float4 v = *(float4*)&st[mm][nn];
            v.x = siluf(v.x); v.y = siluf(v.y); v.z = siluf(v.z); v.w = siluf(v.w);
            *(float4*)&g_z[((size_t)(bm + mm)) * DI + cb + nn] = v;
        }
    }
}

// ------------------------- 2. depthwise 3x3 conv + silu --------------------
__global__ void k_conv(const float* __restrict__ cw, const float* __restrict__ cb)
{
    int gid = blockIdx.x * blockDim.x + threadIdx.x;
    if (gid >= BB * DI * LL) return;
    int l = gid & 4095;
    int c = (gid >> 12) % DI;
    int h = l >> 6, w = l & 63;
    const float* src = g_xcpre + (size_t)(gid - l);
    float acc = cb[c];
    #pragma unroll
    for (int ky = 0; ky < 3; ky++) {
        int hy = h + ky - 1;
        if ((unsigned)hy >= 64u) continue;
        #pragma unroll
        for (int kx = 0; kx < 3; kx++) {
            int wx = w + kx - 1;
            if ((unsigned)wx >= 64u) continue;
            acc += src[hy * 64 + wx] * cw[c * 9 + ky * 3 + kx];
        }
    }
    g_xs[gid] = siluf(acc);
}

// ------------------------- 2b. transpose xs (c,l) -> (l,c) -----------------
__global__ void __launch_bounds__(256) k_xt()
{
    __shared__ float t[32][33];
    int b  = blockIdx.z;
    int c0 = blockIdx.y * 32;
    int l0 = blockIdx.x * 32;
    int tx = threadIdx.x, ty = threadIdx.y;   // 32 x 8
    #pragma unroll
    for (int k = 0; k < 4; k++)
        t[ty + 8 * k][tx] = g_xs[((size_t)(b * DI + c0 + ty + 8 * k)) * LL + l0 + tx];
    __syncthreads();
    #pragma unroll
    for (int k = 0; k < 4; k++)
        g_xst[((size_t)(b * LL + l0 + ty + 8 * k)) * DI + c0 + tx] = t[tx][ty + 8 * k];
}

// ------------------------- 3. per-node reciprocal norms (double) -----------
__global__ void k_norm()
{
    int gid = blockIdx.x * blockDim.x + threadIdx.x;  // b*L + l
    if (gid >= BB * LL) return;
    int b = gid >> 12, l = gid & 4095;
    const float* xp = g_xs + (size_t)b * DI * LL + l;
    double s = 0.0;
    #pragma unroll 4
    for (int c = 0; c < DI; c++) {
        double v = (double)xp[(size_t)c * LL];
        s += v * v;
    }
    double nrm = sqrt(s);
    double den = nrm > 1e-8 ? nrm : 1e-8;
    g_rinv[gid] = 1.0 / den;
}

// ------------------------- 4. edge weights -> packed sortable keys ---------
// w = exp(-(f_u . f_v) * rinv_u * rinv_v) in (0.36, 2.72): positive double,
// bit pattern monotone. Pack top-51 key bits with 13-bit edge index so a
// single u64 atomicMin does min-key with stable min-index tie-break.
__global__ void k_edge()
{
    int gid = blockIdx.x * blockDim.x + threadIdx.x;
    if (gid >= BB * NE) return;
    int b = gid / NE, e = gid % NE;
    int u, v;
    edge_uv(e, u, v);
    const float* f = g_xs + (size_t)b * DI * LL;
    double s = 0.0;
    #pragma unroll 4
    for (int c = 0; c < DI; c++)
        s += (double)f[(size_t)c * LL + u] * (double)f[(size_t)c * LL + v];
    double w = exp(-s * g_rinv[b * LL + u] * g_rinv[b * LL + v]);
    unsigned long long bits = (unsigned long long)__double_as_longlong(w);
    g_keys[gid] = (bits & ~0x1FFFULL) | (unsigned long long)e;
}

// ------------------------- 5. Boruvka MST + frontier BFS (block/batch) -----
#define O_KEY  0
#define O_COMP 64512
#define O_PTR  80896
#define O_BEST 97280
#define O_FLAG 130048
#define BORSMEM 131072

__global__ void __launch_bounds__(1024, 1) k_boruvka()
{
    extern __shared__ unsigned char sm[];
    unsigned long long* skey = (unsigned long long*)(sm + O_KEY);
    unsigned int*       comp = (unsigned int*)(sm + O_COMP);
    unsigned int*       ptrA = (unsigned int*)(sm + O_PTR);
    unsigned long long* best = (unsigned long long*)(sm + O_BEST);
    unsigned int*       flag = (unsigned int*)(sm + O_FLAG);   // 252 words used
    __shared__ int s_done, s_chg, s_nl, s_qt;

    int b = blockIdx.x;
    int tid = threadIdx.x;

    for (int e = tid; e < NE; e += 1024) skey[e] = g_keys[b * NE + e];
    for (int i = tid; i < LL; i += 1024) comp[i] = (unsigned)i;
    if (tid < 256) flag[tid] = 0;
    __syncthreads();

    // ---- Boruvka rounds (single fused edge pass per round) ----
    for (int round = 0; round < 13; round++) {
        for (int i = tid; i < LL; i += 1024) best[i] = ~0ULL;
        if (tid == 0) s_done = 1;
        __syncthreads();

        for (int e = tid; e < NE; e += 1024) {
            int u, v; edge_uv(e, u, v);
            unsigned cu = comp[u], cv = comp[v];
            if (cu != cv) {
                unsigned long long k = skey[e];
                atomicMin(&best[cu], k);
                atomicMin(&best[cv], k);
            }
        }
        __syncthreads();
        // hook via chosen edge (idx in low 13 bits)
        for (int c = tid; c < LL; c += 1024) {
            unsigned long long bk = best[c];
            if (bk != ~0ULL) {
                int e = (int)(bk & 8191ULL);
                atomicOr(&flag[e >> 5], 1u << (e & 31));
                int u, v; edge_uv(e, u, v);
                unsigned cu = comp[u], cv = comp[v];
                ptrA[c] = (cu == (unsigned)c) ? cv : cu;
                s_done = 0;
            } else {
                ptrA[c] = (unsigned)c;
            }
        }
        __syncthreads();
        if (s_done) break;
        // 2-cycle removal (mutual hooks; unique weights -> only 2-cycles)
        for (int c = tid; c < LL; c += 1024) {
            unsigned p = ptrA[c];
            if (p != (unsigned)c && ptrA[p] == (unsigned)c && (unsigned)c < p)
                ptrA[c] = (unsigned)c;
        }
        __syncthreads();
        // pointer jumping
        for (int it = 0; it < 13; it++) {
            if (tid == 0) s_chg = 0;
            __syncthreads();
            for (int c = tid; c < LL; c += 1024) {
                unsigned p = ptrA[c];
                unsigned g = ptrA[p];
                if (p != g) { ptrA[c] = g; s_chg = 1; }
            }
            __syncthreads();
            if (!s_chg) break;
        }
        for (int i = tid; i < LL; i += 1024) comp[i] = ptrA[comp[i]];
        __syncthreads();
    }

    // ---- frontier BFS from node 0 (keys region is dead -> reuse) ----
    unsigned int* dep = (unsigned int*)(sm + O_KEY);
    unsigned int* par = (unsigned int*)(sm + O_KEY + 16384);
    unsigned int* q   = (unsigned int*)(sm + O_KEY + 32768);
    for (int i = tid; i < LL; i += 1024) dep[i] = 0xFFFFFFFFu;
    __syncthreads();
    if (tid == 0) { dep[0] = 0; par[0] = 0; q[0] = 0; s_qt = 1; }
    __syncthreads();

    int qh = 0, qt = 1;
    while (qh < qt) {
        for (int i = qh + tid; i < qt; i += 1024) {
            int n = (int)q[i];
            int h = n >> 6, w = n & 63;
            unsigned d = dep[n] + 1;
            if (w < 63) { int e = h * 63 + w; int m = n + 1;
                if ((flag[e >> 5] >> (e & 31) & 1u) && dep[m] == 0xFFFFFFFFu) {
                    dep[m] = d; par[m] = (unsigned)n; q[atomicAdd(&s_qt, 1)] = (unsigned)m; } }
            if (w > 0)  { int e = h * 63 + w - 1; int m = n - 1;
                if ((flag[e >> 5] >> (e & 31) & 1u) && dep[m] == 0xFFFFFFFFu) {
                    dep[m] = d; par[m] = (unsigned)n; q[atomicAdd(&s_qt, 1)] = (unsigned)m; } }
            if (h < 63) { int e = 4032 + n; int m = n + 64;
                if ((flag[e >> 5] >> (e & 31) & 1u) && dep[m] == 0xFFFFFFFFu) {
                    dep[m] = d; par[m] = (unsigned)n; q[atomicAdd(&s_qt, 1)] = (unsigned)m; } }
            if (h > 0)  { int e = 4032 + n - 64; int m = n - 64;
                if ((flag[e >> 5] >> (e & 31) & 1u) && dep[m] == 0xFFFFFFFFu) {
                    dep[m] = d; par[m] = (unsigned)n; q[atomicAdd(&s_qt, 1)] = (unsigned)m; } }
        }
        __syncthreads();
        qh = qt;
        qt = s_qt;
        __syncthreads();
    }

    // ---- levels: counts, min node, positions ----
    unsigned int* lvlcnt = (unsigned int*)(sm + O_COMP);
    unsigned int* lvlmin = (unsigned int*)(sm + O_PTR);
    unsigned int* cur    = (unsigned int*)(sm + O_BEST);
    unsigned int* posA   = (unsigned int*)(sm + O_BEST + 16384);
    for (int i = tid; i < LL; i += 1024) { lvlcnt[i] = 0; lvlmin[i] = 0x7FFFFFFFu; }
    if (tid == 0) s_nl = 0;
    __syncthreads();
    for (int i = tid; i < LL; i += 1024) {
        unsigned d = dep[i];
        atomicAdd(&lvlcnt[d], 1u);
        atomicMin(&lvlmin[d], (unsigned)i);
        atomicMax(&s_nl, (int)d);
    }
    __syncthreads();
    if (tid == 0) {
        int nl = s_nl + 1;
        g_numlev[b] = nl;
        int run = 0;
        for (int d = 0; d < nl; d++) {
            g_lvl[b * (LL + 2) + d] = run;
            g_lvlcnt[b * (LL + 2) + d] = (int)lvlcnt[d];
            g_lvlmin[b * (LL + 2) + d] = (int)lvlmin[d];
            cur[d] = (unsigned)run;
            run += (int)lvlcnt[d];
        }
        g_lvl[b * (LL + 2) + nl] = LL;
    }
    __syncthreads();
    for (int i = tid; i < LL; i += 1024)
        posA[i] = atomicAdd(&cur[dep[i]], 1u);
    __syncthreads();
    // emit pos-ordered tree structure (fixed child order: +1,-1,+64,-64)
    for (int i = tid; i < LL; i += 1024) {
        unsigned p = posA[i];
        g_pos[b * LL + i] = (int)p;
        g_parp[b * LL + p] = (int)posA[par[i]];
        int h = i >> 6, w = i & 63;
        int a[4]; int k = 0;
        if (w < 63 && par[i + 1]  == (unsigned)i) a[k++] = (int)posA[i + 1];
        if (w > 0  && par[i - 1]  == (unsigned)i) a[k++] = (int)posA[i - 1];
        if (h < 63 && par[i + 64] == (unsigned)i) a[k++] = (int)posA[i + 64];
        if (h > 0  && par[i - 64] == (unsigned)i) a[k++] = (int)posA[i - 64];
        int4 cp;
        cp.x = k > 0 ? a[0] : -1;
        cp.y = k > 1 ? a[1] : -1;
        cp.z = k > 2 ? a[2] : -1;
        cp.w = k > 3 ? a[3] : -1;
        g_childp[b * LL + p] = cp;
    }
}

// ------------------------- 5b. padded-scatter revert flags (as pos) --------
__global__ void k_revert()
{
    __shared__ int nlmax;
    if (threadIdx.x == 0) {
        int m = 0;
        for (int b = 0; b < BB; b++) m = max(m, g_numlev[b]);
        nlmax = m;
    }
    __syncthreads();
    for (int d = threadIdx.x; d < nlmax; d += blockDim.x) {
        int cnt[BB];
        int md = 0;
        for (int b = 0; b < BB; b++) {
            int c = (d < g_numlev[b]) ? g_lvlcnt[b * (LL + 2) + d] : 0;
            cnt[b] = c;
            md = max(md, c);
        }
        for (int b = 0; b < BB; b++) {
            int r = -1;
            if (d > 0 && cnt[b] > 0 && cnt[b] < md)
                r = g_pos[b * LL + g_lvlmin[b * (LL + 2) + d]];
            g_revert[b * (LL + 2) + d] = r;
        }
    }
}

// ------------------------- 6. fused x_dbl + dts/deltaA/BX (warp per node) --
__global__ void __launch_bounds__(256) k_ssm(const float* __restrict__ XW,
                                             const float* __restrict__ dtW,
                                             const float* __restrict__ dtB,
                                             const float* __restrict__ Alog)
{
    int gw = (blockIdx.x * 256 + threadIdx.x) >> 5;   // b*LL + l
    int lane = threadIdx.x & 31;
    if (gw >= BB * LL) return;
    int b = gw >> 12;
    const float* xrow = g_xst + (size_t)gw * DI;

    float xv[6];
    #pragma unroll
    for (int j = 0; j < 6; j++) xv[j] = xrow[lane + 32 * j];

    float acc[8];
    #pragma unroll
    for (int c8 = 0; c8 < 8; c8++) {
        float s = 0.f;
        #pragma unroll
        for (int j = 0; j < 6; j++) s += xv[j] * XW[c8 * DI + lane + 32 * j];
        acc[c8] = warpsum(s);
    }
    float Bsv = acc[6];
    if (lane == 0) g_Csv[gw] = acc[7];

    int pos = g_pos[gw];
    float2* eurow = g_eu + ((size_t)(b * LL) + pos) * DI;
    #pragma unroll
    for (int j = 0; j < 6; j++) {
        int d = lane + 32 * j;
        float s = dtB[d];
        #pragma unroll
        for (int r = 0; r < DR; r++) s += acc[r] * dtW[d * DR + r];
        float dt = softplusf(s);
        float ew = expf(-expf(Alog[d]) * dt);
        float bx = dt * Bsv * xv[j];
        eurow[d] = make_float2(ew, bx);
    }
}

// ------------------------- 7. tree scan (pos-ordered, level-synchronous) ---
__global__ void __launch_bounds__(256) k_scan()
{
    int b  = blockIdx.y;
    int c0 = blockIdx.x * 32;
    int tid = threadIdx.x;
    int nl = g_numlev[b];
    const int*  lvl   = g_lvl + b * (LL + 2);
    const int*  revp  = g_revert + b * (LL + 2);
    const int*  parp  = g_parp + b * LL;
    const int4* chp   = g_childp + b * LL;
    float2* eu = g_eu + (size_t)(b * LL) * DI;
    float*  ag = g_ag + (size_t)(b * LL) * DI;

    // up-sweep
    for (int lev = nl - 1; lev >= 0; --lev) {
        int ls = lvl[lev], le = lvl[lev + 1];
        int work = (le - ls) * 32;
        for (int i = tid; i < work; i += 256) {
            int pos = ls + (i >> 5);
            int c = c0 + (i & 31);
            int4 ch = chp[pos];
            float acc = eu[(size_t)pos * DI + c].y;
            if (ch.x >= 0) { float2 t = eu[(size_t)ch.x * DI + c]; acc += t.x * t.y; }
            if (ch.y >= 0) { float2 t = eu[(size_t)ch.y * DI + c]; acc += t.x * t.y; }
            if (ch.z >= 0) { float2 t = eu[(size_t)ch.z * DI + c]; acc += t.x * t.y; }
            if (ch.w >= 0) { float2 t = eu[(size_t)ch.w * DI + c]; acc += t.x * t.y; }
            eu[(size_t)pos * DI + c].y = acc;
        }
        __syncthreads();
    }
    // down-sweep (with padded-scatter revert)
    for (int lev = 0; lev < nl; ++lev) {
        int ls = lvl[lev], le = lvl[lev + 1];
        int rev = revp[lev];
        int work = (le - ls) * 32;
        for (int i = tid; i < work; i += 256) {
            int pos = ls + (i >> 5);
            int c = c0 + (i & 31);
            float2 e = eu[(size_t)pos * DI + c];
            float u = e.y;
            float val;
            if (lev == 0) {
                val = u;
            } else {
                int pp = parp[pos];
                float w = e.x;
                val = u + w * (ag[(size_t)pp * DI + c] - w * u);
                if (pos == rev) val = u;
            }
            ag[(size_t)pos * DI + c] = val;
        }
        __syncthreads();
    }
}

// ------------------------- 8. fused LN -> *Cs -> +Ds*xs -> LN -> *z --------
__global__ void __launch_bounds__(256) k_fuse(const float* __restrict__ hg,
                                              const float* __restrict__ hb,
                                              const float* __restrict__ og,
                                              const float* __restrict__ ob,
                                              const float* __restrict__ Ds)
{
    int warp = (blockIdx.x * 256 + threadIdx.x) >> 5;
    int lane = threadIdx.x & 31;
    if (warp >= BB * LL) return;
    int b = warp >> 12;
    int pos = g_pos[warp];
    const float* hrow = g_ag + ((size_t)(b * LL) + pos) * DI;
    const float* xrow = g_xst + (size_t)warp * DI;

    float v[6];
    #pragma unroll
    for (int j = 0; j < 6; j++) v[j] = hrow[lane + 32 * j];

    float s = 0.f;
    #pragma unroll
    for (int j = 0; j < 6; j++) s += v[j];
    float mu = warpsum(s) * (1.f / 192.f);
    float q = 0.f;
    #pragma unroll
    for (int j = 0; j < 6; j++) { float d = v[j] - mu; q += d * d; }
    float inv = rsqrtf(warpsum(q) * (1.f / 192.f) + 1e-5f);

    float Cv = g_Csv[warp];
    float y[6];
    #pragma unroll
    for (int j = 0; j < 6; j++) {
        int c = lane + 32 * j;
        float hn = (v[j] - mu) * inv * hg[c] + hb[c];
        y[j] = hn * Cv + Ds[c] * xrow[c];
    }

    s = 0.f;
    #pragma unroll
    for (int j = 0; j < 6; j++) s += y[j];
    float mu2 = warpsum(s) * (1.f / 192.f);
    q = 0.f;
    #pragma unroll
    for (int j = 0; j < 6; j++) { float d = y[j] - mu2; q += d * d; }
    float inv2 = rsqrtf(warpsum(q) * (1.f / 192.f) + 1e-5f);

    #pragma unroll
    for (int j = 0; j < 6; j++) {
        int c = lane + 32 * j;
        float y2 = (y[j] - mu2) * inv2 * og[c] + ob[c];
        g_yz[(size_t)warp * DI + c] = y2 * g_z[(size_t)warp * DI + c];
    }
}

// ------------------------- 9. out_proj GEMM --------------------------------
__global__ void __launch_bounds__(256) k_gemm_out(const float* __restrict__ W,
                                                  float* __restrict__ out)
{
    __shared__ float sA[64][33];
    __shared__ float sW[64][33];
    int bm = blockIdx.y * 64, bn = blockIdx.x * 64;
    int tid = threadIdx.x;
    int tx = tid & 15, ty = tid >> 4;
    float acc[4][4] = {};
    for (int k0 = 0; k0 < 192; k0 += 32) {
        for (int t = tid; t < 512; t += 256) {
            int r = t >> 3, kq = t & 7;
            float4 va = *(const float4*)(g_yz + (size_t)(bm + r) * 192 + k0 + kq * 4);
            sA[r][kq*4+0] = va.x; sA[r][kq*4+1] = va.y;
            sA[r][kq*4+2] = va.z; sA[r][kq*4+3] = va.w;
            float4 vw;
            if (bn + r < 96)
                vw = *(const float4*)(W + (size_t)(bn + r) * 192 + k0 + kq * 4);
            else
                vw = make_float4(0.f, 0.f, 0.f, 0.f);
            sW[r][kq*4+0] = vw.x; sW[r][kq*4+1] = vw.y;
            sW[r][kq*4+2] = vw.z; sW[r][kq*4+3] = vw.w;
        }
        __syncthreads();
        #pragma unroll
        for (int k = 0; k < 32; k++) {
            float a[4], bv[4];
            #pragma unroll
            for (int i = 0; i < 4; i++) { a[i] = sA[ty*4+i][k]; bv[i] = sW[tx*4+i][k]; }
            #pragma unroll
            for (int i = 0; i < 4; i++)
                #pragma unroll
                for (int j = 0; j < 4; j++)
                    acc[i][j] += a[i] * bv[j];
        }
        __syncthreads();
    }
    #pragma unroll
    for (int i = 0; i < 4; i++) {
        int m = bm + ty * 4 + i;
        #pragma unroll
        for (int j = 0; j < 4; j++) {
            int n = bn + tx * 4 + j;
            if (n < 96) out[(size_t)m * 96 + n] = acc[i][j];
        }
    }
}

// ------------------------- launch ------------------------------------------
extern "C" void kernel_launch(void* const* d_in, const int* in_sizes, int n_in,
                              void* d_out, int out_size)
{
    const float* x    = (const float*)d_in[0];
    const float* inw  = (const float*)d_in[1];
    const float* cw   = (const float*)d_in[2];
    const float* cb   = (const float*)d_in[3];
    const float* xpw  = (const float*)d_in[4];
    const float* dtw  = (const float*)d_in[5];
    const float* dtb  = (const float*)d_in[6];
    const float* alog = (const float*)d_in[7];
    const float* Dsp  = (const float*)d_in[8];
    const float* hg   = (const float*)d_in[9];
    const float* hbp  = (const float*)d_in[10];
    const float* og   = (const float*)d_in[11];
    const float* obp  = (const float*)d_in[12];
    const float* opw  = (const float*)d_in[13];
    float* out = (float*)d_out;

    k_gemm_in<<<dim3(6, 512), 256>>>(x, inw);
    k_conv<<<(BB * DI * LL + 255) / 256, 256>>>(cw, cb);
    k_xt<<<dim3(128, 6, 8), dim3(32, 8)>>>();
    k_norm<<<(BB * LL + 255) / 256, 256>>>();
    k_edge<<<(BB * NE + 255) / 256, 256>>>();

    cudaFuncSetAttribute(k_boruvka, cudaFuncAttributeMaxDynamicSharedMemorySize, BORSMEM);
    k_boruvka<<<BB, 1024, BORSMEM>>>();
    k_revert<<<1, 256>>>();

    k_ssm<<<(BB * LL * 32 + 255) / 256, 256>>>(xpw, dtw, dtb, alog);
    k_scan<<<dim3(6, BB), 256>>>();
    k_fuse<<<(BB * LL * 32 + 255) / 256, 256>>>(hg, hbp, og, obp, Dsp);
    k_gemm_out<<<dim3(2, 512), 256>>>(opw, out);
}

// round 7
// speedup vs baseline: 4.3127x; 1.1399x over previous
#include <cuda_runtime.h>
#include <math.h>

#define BB 8
#define HH 64
#define WW 64
#define LL 4096
#define DM 96
#define DI 192
#define DR 6
#define NE 8064
#define CPB 6   // channels per scan block

// ------------------------- device scratch (static, no mallocs) -------------
static __device__ __align__(16) float  g_z[BB*LL*DI];      // (b,l,c) silu(z)
static __device__ __align__(16) float  g_xcpre[BB*DI*LL];  // (b,c,l) pre-conv
static __device__ __align__(16) float  g_xs[BB*DI*LL];     // (b,c,l) silu(conv)
static __device__ __align__(16) float  g_xst[BB*LL*DI];    // (b,l,c) transposed
static __device__ double g_rinv[BB*LL];                    // 1/max(norm,1e-8)
static __device__ unsigned long long   g_keys[BB*NE];      // packed (key|idx)
static __device__ int    g_pos[BB*LL];                     // node -> bfs position
static __device__ int    g_bfs[BB*LL];                     // pos  -> node
static __device__ int    g_parp[BB*LL];                    // pos  -> parent pos
static __device__ int    g_lvl[BB*(LL+2)];
static __device__ int    g_lvlcnt[BB*(LL+2)];
static __device__ int    g_lvlmin[BB*(LL+2)];
static __device__ int    g_revert[BB*(LL+2)];              // pos (or -1) per level
static __device__ int    g_numlev[BB];
static __device__ float  g_Csv[BB*LL];
static __device__ __align__(16) float2 g_eu[BB*LL*DI];     // node-ordered (ew, up)
static __device__ __align__(16) float  g_ag[BB*LL*DI];     // pos-ordered aggr
static __device__ __align__(16) float  g_yz[BB*LL*DI];     // (b,l,c)

// ------------------------- helpers -----------------------------------------
__device__ __forceinline__ float siluf(float x){ return x / (1.f + expf(-x)); }
__device__ __forceinline__ float softplusf(float x){
    return fmaxf(x, 0.f) + log1pf(expf(-fabsf(x)));
}
__device__ __forceinline__ float warpsum(float v){
    #pragma unroll
    for (int o = 16; o > 0; o >>= 1) v += __shfl_xor_sync(0xFFFFFFFFu, v, o);
    return v;
}
__device__ __forceinline__ double warpsumd(double v){
    #pragma unroll
    for (int o = 16; o > 0; o >>= 1) v += __shfl_xor_sync(0xFFFFFFFFu, v, o);
    return v;
}
__device__ __forceinline__ void edge_uv(int e, int& u, int& v){
    if (e < 4032) { int r = e / 63, c = e % 63; u = r * 64 + c; v = u + 1; }
    else          { int j = e - 4032; u = j; v = j + 64; }
}

// ------------------------- 1. in_proj GEMM + split/silu (coalesced out) ----
__global__ void __launch_bounds__(256) k_gemm_in(const float* __restrict__ A,
                                                 const float* __restrict__ W)
{
    __shared__ float sA[64][33];
    __shared__ float sW[64][33];
    __shared__ float st[64][68];
    int bm = blockIdx.y * 64, bn = blockIdx.x * 64;
    int tid = threadIdx.x;
    int tx = tid & 15, ty = tid >> 4;
    float acc[4][4] = {};
    for (int k0 = 0; k0 < 96; k0 += 32) {
        for (int t = tid; t < 512; t += 256) {
            int r = t >> 3, kq = t & 7;
            float4 va = *(const float4*)(A + (size_t)(bm + r) * 96 + k0 + kq * 4);
            sA[r][kq*4+0] = va.x; sA[r][kq*4+1] = va.y;
            sA[r][kq*4+2] = va.z; sA[r][kq*4+3] = va.w;
            float4 vw = *(const float4*)(W + (size_t)(bn + r) * 96 + k0 + kq * 4);
            sW[r][kq*4+0] = vw.x; sW[r][kq*4+1] = vw.y;
            sW[r][kq*4+2] = vw.z; sW[r][kq*4+3] = vw.w;
        }
        __syncthreads();
        #pragma unroll
        for (int k = 0; k < 32; k++) {
            float a[4], b[4];
            #pragma unroll
            for (int i = 0; i < 4; i++) { a[i] = sA[ty*4+i][k]; b[i] = sW[tx*4+i][k]; }
            #pragma unroll
            for (int i = 0; i < 4; i++)
                #pragma unroll
                for (int j = 0; j < 4; j++)
                    acc[i][j] += a[i] * b[j];
        }
        __syncthreads();
    }
    int b = bm >> 12, l0 = bm & 4095;
    if (bn < DI) {
        #pragma unroll
        for (int i = 0; i < 4; i++)
            #pragma unroll
            for (int j = 0; j < 4; j++)
                st[tx*4+j][ty*4+i] = acc[i][j];
        __syncthreads();
        #pragma unroll
        for (int pass = 0; pass < 4; pass++) {
            int nn = pass * 16 + (tid >> 4);
            int mm = (tid & 15) * 4;
            float4 v = *(float4*)&st[nn][mm];
            *(float4*)&g_xcpre[((size_t)(b * DI + bn + nn)) * LL + l0 + mm] = v;
        }
    } else {
        int cb = bn - DI;
        #pragma unroll
        for (int i = 0; i < 4; i++)
            #pragma unroll
            for (int j = 0; j < 4; j++)
                st[ty*4+i][tx*4+j] = acc[i][j];
        __syncthreads();
        #pragma unroll
        for (int pass = 0; pass < 4; pass++) {
            int mm = pass * 16 + (tid >> 4);
            int nn = (tid & 15) * 4;
            float4 v = *(float4*)&st[mm][nn];
            v.x = siluf(v.x); v.y = siluf(v.y); v.z = siluf(v.z); v.w = siluf(v.w);
            *(float4*)&g_z[((size_t)(bm + mm)) * DI + cb + nn] = v;
        }
    }
}

// ------------------------- 2. depthwise 3x3 conv + silu --------------------
__global__ void k_conv(const float* __restrict__ cw, const float* __restrict__ cb)
{
    int gid = blockIdx.x * blockDim.x + threadIdx.x;
    if (gid >= BB * DI * LL) return;
    int l = gid & 4095;
    int c = (gid >> 12) % DI;
    int h = l >> 6, w = l & 63;
    const float* src = g_xcpre + (size_t)(gid - l);
    float acc = cb[c];
    #pragma unroll
    for (int ky = 0; ky < 3; ky++) {
        int hy = h + ky - 1;
        if ((unsigned)hy >= 64u) continue;
        #pragma unroll
        for (int kx = 0; kx < 3; kx++) {
            int wx = w + kx - 1;
            if ((unsigned)wx >= 64u) continue;
            acc += src[hy * 64 + wx] * cw[c * 9 + ky * 3 + kx];
        }
    }
    g_xs[gid] = siluf(acc);
}

// ------------------------- 2b. transpose xs (c,l) -> (l,c) -----------------
__global__ void __launch_bounds__(256) k_xt()
{
    __shared__ float t[32][33];
    int b  = blockIdx.z;
    int c0 = blockIdx.y * 32;
    int l0 = blockIdx.x * 32;
    int tx = threadIdx.x, ty = threadIdx.y;   // 32 x 8
    #pragma unroll
    for (int k = 0; k < 4; k++)
        t[ty + 8 * k][tx] = g_xs[((size_t)(b * DI + c0 + ty + 8 * k)) * LL + l0 + tx];
    __syncthreads();
    #pragma unroll
    for (int k = 0; k < 4; k++)
        g_xst[((size_t)(b * LL + l0 + ty + 8 * k)) * DI + c0 + tx] = t[tx][ty + 8 * k];
}

// ------------------------- 3. reciprocal norms (warp per node, double) -----
__global__ void __launch_bounds__(256) k_norm()
{
    int gid = (blockIdx.x * 256 + threadIdx.x) >> 5;   // b*L + l
    int lane = threadIdx.x & 31;
    if (gid >= BB * LL) return;
    const float* xrow = g_xst + (size_t)gid * DI;
    double s = 0.0;
    #pragma unroll
    for (int j = 0; j < 6; j++) {
        double v = (double)xrow[lane + 32 * j];
        s += v * v;
    }
    s = warpsumd(s);
    if (lane == 0) {
        double nrm = sqrt(s);
        double den = nrm > 1e-8 ? nrm : 1e-8;
        g_rinv[gid] = 1.0 / den;
    }
}

// ------------------------- 4. edge weights (warp per edge) -----------------
// w = exp(-(f_u.f_v)*rinv_u*rinv_v) in (0.36,2.72): positive double, bit
// pattern monotone. Pack top-51 bits with 13-bit edge index: one u64
// atomicMin = min-key with stable min-index tie-break.
__global__ void __launch_bounds__(256) k_edge()
{
    int gid = (blockIdx.x * 256 + threadIdx.x) >> 5;
    int lane = threadIdx.x & 31;
    if (gid >= BB * NE) return;
    int b = gid / NE, e = gid % NE;
    int u, v;
    edge_uv(e, u, v);
    const float* xu = g_xst + ((size_t)(b * LL) + u) * DI;
    const float* xv = g_xst + ((size_t)(b * LL) + v) * DI;
    double s = 0.0;
    #pragma unroll
    for (int j = 0; j < 6; j++)
        s += (double)xu[lane + 32 * j] * (double)xv[lane + 32 * j];
    s = warpsumd(s);
    if (lane == 0) {
        double w = exp(-s * g_rinv[b * LL + u] * g_rinv[b * LL + v]);
        unsigned long long bits = (unsigned long long)__double_as_longlong(w);
        g_keys[gid] = (bits & ~0x1FFFULL) | (unsigned long long)e;
    }
}

// ------------------------- 5. Boruvka MST + frontier BFS (block/batch) -----
#define O_KEY  0
#define O_COMP 64512
#define O_PTR  80896
#define O_BEST 97280
#define O_FLAG 130048
#define BORSMEM 131072

__global__ void __launch_bounds__(1024, 1) k_boruvka()
{
    extern __shared__ unsigned char sm[];
    unsigned long long* skey = (unsigned long long*)(sm + O_KEY);
    unsigned int*       comp = (unsigned int*)(sm + O_COMP);
    unsigned int*       ptrA = (unsigned int*)(sm + O_PTR);
    unsigned long long* best = (unsigned long long*)(sm + O_BEST);
    unsigned int*       flag = (unsigned int*)(sm + O_FLAG);
    __shared__ int s_done, s_chg, s_nl, s_qt;

    int b = blockIdx.x;
    int tid = threadIdx.x;

    for (int e = tid; e < NE; e += 1024) skey[e] = g_keys[b * NE + e];
    for (int i = tid; i < LL; i += 1024) comp[i] = (unsigned)i;
    if (tid < 256) flag[tid] = 0;
    __syncthreads();

    for (int round = 0; round < 13; round++) {
        for (int i = tid; i < LL; i += 1024) best[i] = ~0ULL;
        if (tid == 0) s_done = 1;
        __syncthreads();

        for (int e = tid; e < NE; e += 1024) {
            int u, v; edge_uv(e, u, v);
            unsigned cu = comp[u], cv = comp[v];
            if (cu != cv) {
                unsigned long long k = skey[e];
                atomicMin(&best[cu], k);
                atomicMin(&best[cv], k);
            }
        }
        __syncthreads();
        for (int c = tid; c < LL; c += 1024) {
            unsigned long long bk = best[c];
            if (bk != ~0ULL) {
                int e = (int)(bk & 8191ULL);
                atomicOr(&flag[e >> 5], 1u << (e & 31));
                int u, v; edge_uv(e, u, v);
                unsigned cu = comp[u], cv = comp[v];
                ptrA[c] = (cu == (unsigned)c) ? cv : cu;
                s_done = 0;
            } else {
                ptrA[c] = (unsigned)c;
            }
        }
        __syncthreads();
        if (s_done) break;
        for (int c = tid; c < LL; c += 1024) {
            unsigned p = ptrA[c];
            if (p != (unsigned)c && ptrA[p] == (unsigned)c && (unsigned)c < p)
                ptrA[c] = (unsigned)c;
        }
        __syncthreads();
        for (int it = 0; it < 13; it++) {
            if (tid == 0) s_chg = 0;
            __syncthreads();
            for (int c = tid; c < LL; c += 1024) {
                unsigned p = ptrA[c];
                unsigned g = ptrA[p];
                if (p != g) { ptrA[c] = g; s_chg = 1; }
            }
            __syncthreads();
            if (!s_chg) break;
        }
        for (int i = tid; i < LL; i += 1024) comp[i] = ptrA[comp[i]];
        __syncthreads();
    }

    // ---- frontier BFS from node 0 ----
    unsigned int* dep = (unsigned int*)(sm + O_KEY);
    unsigned int* par = (unsigned int*)(sm + O_KEY + 16384);
    unsigned int* q   = (unsigned int*)(sm + O_KEY + 32768);
    for (int i = tid; i < LL; i += 1024) dep[i] = 0xFFFFFFFFu;
    __syncthreads();
    if (tid == 0) { dep[0] = 0; par[0] = 0; q[0] = 0; s_qt = 1; }
    __syncthreads();

    int qh = 0, qt = 1;
    while (qh < qt) {
        for (int i = qh + tid; i < qt; i += 1024) {
            int n = (int)q[i];
            int h = n >> 6, w = n & 63;
            unsigned d = dep[n] + 1;
            if (w < 63) { int e = h * 63 + w; int m = n + 1;
                if ((flag[e >> 5] >> (e & 31) & 1u) && dep[m] == 0xFFFFFFFFu) {
                    dep[m] = d; par[m] = (unsigned)n; q[atomicAdd(&s_qt, 1)] = (unsigned)m; } }
            if (w > 0)  { int e = h * 63 + w - 1; int m = n - 1;
                if ((flag[e >> 5] >> (e & 31) & 1u) && dep[m] == 0xFFFFFFFFu) {
                    dep[m] = d; par[m] = (unsigned)n; q[atomicAdd(&s_qt, 1)] = (unsigned)m; } }
            if (h < 63) { int e = 4032 + n; int m = n + 64;
                if ((flag[e >> 5] >> (e & 31) & 1u) && dep[m] == 0xFFFFFFFFu) {
                    dep[m] = d; par[m] = (unsigned)n; q[atomicAdd(&s_qt, 1)] = (unsigned)m; } }
            if (h > 0)  { int e = 4032 + n - 64; int m = n - 64;
                if ((flag[e >> 5] >> (e & 31) & 1u) && dep[m] == 0xFFFFFFFFu) {
                    dep[m] = d; par[m] = (unsigned)n; q[atomicAdd(&s_qt, 1)] = (unsigned)m; } }
        }
        __syncthreads();
        qh = qt;
        qt = s_qt;
        __syncthreads();
    }

    // ---- levels + positions ----
    unsigned int* lvlcnt = (unsigned int*)(sm + O_COMP);
    unsigned int* lvlmin = (unsigned int*)(sm + O_PTR);
    unsigned int* cur    = (unsigned int*)(sm + O_BEST);
    unsigned int* posA   = (unsigned int*)(sm + O_BEST + 16384);
    for (int i = tid; i < LL; i += 1024) { lvlcnt[i] = 0; lvlmin[i] = 0x7FFFFFFFu; }
    if (tid == 0) s_nl = 0;
    __syncthreads();
    for (int i = tid; i < LL; i += 1024) {
        unsigned d = dep[i];
        atomicAdd(&lvlcnt[d], 1u);
        atomicMin(&lvlmin[d], (unsigned)i);
        atomicMax(&s_nl, (int)d);
    }
    __syncthreads();
    if (tid == 0) {
        int nl = s_nl + 1;
        g_numlev[b] = nl;
        int run = 0;
        for (int d = 0; d < nl; d++) {
            g_lvl[b * (LL + 2) + d] = run;
            g_lvlcnt[b * (LL + 2) + d] = (int)lvlcnt[d];
            g_lvlmin[b * (LL + 2) + d] = (int)lvlmin[d];
            cur[d] = (unsigned)run;
            run += (int)lvlcnt[d];
        }
        g_lvl[b * (LL + 2) + nl] = LL;
    }
    __syncthreads();
    for (int i = tid; i < LL; i += 1024)
        posA[i] = atomicAdd(&cur[dep[i]], 1u);
    __syncthreads();
    for (int i = tid; i < LL; i += 1024) {
        unsigned p = posA[i];
        g_pos[b * LL + i] = (int)p;
        g_bfs[b * LL + p] = i;
        g_parp[b * LL + p] = (int)posA[par[i]];
    }
}

// ------------------------- 5b. padded-scatter revert flags (as pos) --------
__global__ void k_revert()
{
    __shared__ int nlmax;
    if (threadIdx.x == 0) {
        int m = 0;
        for (int b = 0; b < BB; b++) m = max(m, g_numlev[b]);
        nlmax = m;
    }
    __syncthreads();
    for (int d = threadIdx.x; d < nlmax; d += blockDim.x) {
        int cnt[BB];
        int md = 0;
        for (int b = 0; b < BB; b++) {
            int c = (d < g_numlev[b]) ? g_lvlcnt[b * (LL + 2) + d] : 0;
            cnt[b] = c;
            md = max(md, c);
        }
        for (int b = 0; b < BB; b++) {
            int r = -1;
            if (d > 0 && cnt[b] > 0 && cnt[b] < md)
                r = g_pos[b * LL + g_lvlmin[b * (LL + 2) + d]];
            g_revert[b * (LL + 2) + d] = r;
        }
    }
}

// ------------------------- 6. fused x_dbl + dts/deltaA/BX (node-ordered) ---
__global__ void __launch_bounds__(256) k_ssm(const float* __restrict__ XW,
                                             const float* __restrict__ dtW,
                                             const float* __restrict__ dtB,
                                             const float* __restrict__ Alog)
{
    int gw = (blockIdx.x * 256 + threadIdx.x) >> 5;   // b*LL + l
    int lane = threadIdx.x & 31;
    if (gw >= BB * LL) return;
    const float* xrow = g_xst + (size_t)gw * DI;

    float xv[6];
    #pragma unroll
    for (int j = 0; j < 6; j++) xv[j] = xrow[lane + 32 * j];

    float acc[8];
    #pragma unroll
    for (int c8 = 0; c8 < 8; c8++) {
        float s = 0.f;
        #pragma unroll
        for (int j = 0; j < 6; j++) s += xv[j] * XW[c8 * DI + lane + 32 * j];
        acc[c8] = warpsum(s);
    }
    float Bsv = acc[6];
    if (lane == 0) g_Csv[gw] = acc[7];

    float2* eurow = g_eu + (size_t)gw * DI;
    #pragma unroll
    for (int j = 0; j < 6; j++) {
        int d = lane + 32 * j;
        float s = dtB[d];
        #pragma unroll
        for (int r = 0; r < DR; r++) s += acc[r] * dtW[d * DR + r];
        float dt = softplusf(s);
        float ew = expf(-expf(Alog[d]) * dt);
        float bx = dt * Bsv * xv[j];
        eurow[d] = make_float2(ew, bx);
    }
}

// ------------------------- 7. resident-smem tree scan -----------------------
// Block = (batch, 6-channel group). acc/ew/parp live entirely in shared
// memory -> per-level dependency chain is LDS-latency, not L2-latency.
// Up-sweep: child-side atomicAdd into parent slot (no child lists needed).
// Down-sweep: in-place transform (parents finalized in earlier levels).
#define SCAN_SMEM (LL*CPB*4*2 + LL*4)
__global__ void __launch_bounds__(256) k_scan()
{
    extern __shared__ unsigned char sms[];
    float* acc_s  = (float*)sms;                        // LL*CPB
    float* ew_s   = (float*)(sms + LL*CPB*4);           // LL*CPB
    int*   parp_s = (int*)(sms + LL*CPB*8);             // LL

    int b  = blockIdx.y;
    int c0 = blockIdx.x * CPB;
    int tid = threadIdx.x;
    int nl = g_numlev[b];
    const int* lvl  = g_lvl + b * (LL + 2);
    const int* revp = g_revert + b * (LL + 2);
    const int* bfs  = g_bfs + b * LL;
    const float2* eu = g_eu + (size_t)(b * LL) * DI;
    float* agout = g_ag + (size_t)(b * LL) * DI;

    for (int i = tid; i < LL; i += 256) parp_s[i] = g_parp[b * LL + i];
    for (int idx = tid; idx < LL * CPB; idx += 256) {
        int pos = idx / CPB, cc = idx % CPB;
        float2 v = eu[(size_t)bfs[pos] * DI + c0 + cc];
        ew_s[idx]  = v.x;
        acc_s[idx] = v.y;
    }
    __syncthreads();

    // up-sweep: children (level lev) accumulate into parents (level lev-1)
    for (int lev = nl - 1; lev >= 1; --lev) {
        int ls = lvl[lev], le = lvl[lev + 1];
        int n = (le - ls) * CPB;
        for (int i = tid; i < n; i += 256) {
            int idx = ls * CPB + i;
            int pos = ls + i / CPB, cc = i % CPB;
            atomicAdd(&acc_s[parp_s[pos] * CPB + cc], ew_s[idx] * acc_s[idx]);
        }
        __syncthreads();
    }
    // down-sweep: in-place acc -> ag, stream out
    for (int lev = 0; lev < nl; ++lev) {
        int ls = lvl[lev], le = lvl[lev + 1];
        int rev = revp[lev];
        int n = (le - ls) * CPB;
        for (int i = tid; i < n; i += 256) {
            int idx = ls * CPB + i;
            int pos = ls + i / CPB, cc = i % CPB;
            float u = acc_s[idx];
            float val = u;
            if (lev > 0) {
                float w = ew_s[idx];
                val = u + w * (acc_s[parp_s[pos] * CPB + cc] - w * u);
                if (pos == rev) val = u;
            }
            acc_s[idx] = val;
            agout[(size_t)pos * DI + c0 + cc] = val;
        }
        __syncthreads();
    }
}

// ------------------------- 8. fused LN -> *Cs -> +Ds*xs -> LN -> *z --------
__global__ void __launch_bounds__(256) k_fuse(const float* __restrict__ hg,
                                              const float* __restrict__ hb,
                                              const float* __restrict__ og,
                                              const float* __restrict__ ob,
                                              const float* __restrict__ Ds)
{
    int warp = (blockIdx.x * 256 + threadIdx.x) >> 5;
    int lane = threadIdx.x & 31;
    if (warp >= BB * LL) return;
    int b = warp >> 12;
    int pos = g_pos[warp];
    const float* hrow = g_ag + ((size_t)(b * LL) + pos) * DI;
    const float* xrow = g_xst + (size_t)warp * DI;

    float v[6];
    #pragma unroll
    for (int j = 0; j < 6; j++) v[j] = hrow[lane + 32 * j];

    float s = 0.f;
    #pragma unroll
    for (int j = 0; j < 6; j++) s += v[j];
    float mu = warpsum(s) * (1.f / 192.f);
    float q = 0.f;
    #pragma unroll
    for (int j = 0; j < 6; j++) { float d = v[j] - mu; q += d * d; }
    float inv = rsqrtf(warpsum(q) * (1.f / 192.f) + 1e-5f);

    float Cv = g_Csv[warp];
    float y[6];
    #pragma unroll
    for (int j = 0; j < 6; j++) {
        int c = lane + 32 * j;
        float hn = (v[j] - mu) * inv * hg[c] + hb[c];
        y[j] = hn * Cv + Ds[c] * xrow[c];
    }

    s = 0.f;
    #pragma unroll
    for (int j = 0; j < 6; j++) s += y[j];
    float mu2 = warpsum(s) * (1.f / 192.f);
    q = 0.f;
    #pragma unroll
    for (int j = 0; j < 6; j++) { float d = y[j] - mu2; q += d * d; }
    float inv2 = rsqrtf(warpsum(q) * (1.f / 192.f) + 1e-5f);

    #pragma unroll
    for (int j = 0; j < 6; j++) {
        int c = lane + 32 * j;
        float y2 = (y[j] - mu2) * inv2 * og[c] + ob[c];
        g_yz[(size_t)warp * DI + c] = y2 * g_z[(size_t)warp * DI + c];
    }
}

// ------------------------- 9. out_proj GEMM --------------------------------
__global__ void __launch_bounds__(256) k_gemm_out(const float* __restrict__ W,
                                                  float* __restrict__ out)
{
    __shared__ float sA[64][33];
    __shared__ float sW[64][33];
    int bm = blockIdx.y * 64, bn = blockIdx.x * 64;
    int tid = threadIdx.x;
    int tx = tid & 15, ty = tid >> 4;
    float acc[4][4] = {};
    for (int k0 = 0; k0 < 192; k0 += 32) {
        for (int t = tid; t < 512; t += 256) {
            int r = t >> 3, kq = t & 7;
            float4 va = *(const float4*)(g_yz + (size_t)(bm + r) * 192 + k0 + kq * 4);
            sA[r][kq*4+0] = va.x; sA[r][kq*4+1] = va.y;
            sA[r][kq*4+2] = va.z; sA[r][kq*4+3] = va.w;
            float4 vw;
            if (bn + r < 96)
                vw = *(const float4*)(W + (size_t)(bn + r) * 192 + k0 + kq * 4);
            else
                vw = make_float4(0.f, 0.f, 0.f, 0.f);
            sW[r][kq*4+0] = vw.x; sW[r][kq*4+1] = vw.y;
            sW[r][kq*4+2] = vw.z; sW[r][kq*4+3] = vw.w;
        }
        __syncthreads();
        #pragma unroll
        for (int k = 0; k < 32; k++) {
            float a[4], bv[4];
            #pragma unroll
            for (int i = 0; i < 4; i++) { a[i] = sA[ty*4+i][k]; bv[i] = sW[tx*4+i][k]; }
            #pragma unroll
            for (int i = 0; i < 4; i++)
                #pragma unroll
                for (int j = 0; j < 4; j++)
                    acc[i][j] += a[i] * bv[j];
        }
        __syncthreads();
    }
    #pragma unroll
    for (int i = 0; i < 4; i++) {
        int m = bm + ty * 4 + i;
        #pragma unroll
        for (int j = 0; j < 4; j++) {
            int n = bn + tx * 4 + j;
            if (n < 96) out[(size_t)m * 96 + n] = acc[i][j];
        }
    }
}

// ------------------------- launch ------------------------------------------
extern "C" void kernel_launch(void* const* d_in, const int* in_sizes, int n_in,
                              void* d_out, int out_size)
{
    const float* x    = (const float*)d_in[0];
    const float* inw  = (const float*)d_in[1];
    const float* cw   = (const float*)d_in[2];
    const float* cb   = (const float*)d_in[3];
    const float* xpw  = (const float*)d_in[4];
    const float* dtw  = (const float*)d_in[5];
    const float* dtb  = (const float*)d_in[6];
    const float* alog = (const float*)d_in[7];
    const float* Dsp  = (const float*)d_in[8];
    const float* hg   = (const float*)d_in[9];
    const float* hbp  = (const float*)d_in[10];
    const float* og   = (const float*)d_in[11];
    const float* obp  = (const float*)d_in[12];
    const float* opw  = (const float*)d_in[13];
    float* out = (float*)d_out;

    k_gemm_in<<<dim3(6, 512), 256>>>(x, inw);
    k_conv<<<(BB * DI * LL + 255) / 256, 256>>>(cw, cb);
    k_xt<<<dim3(128, 6, 8), dim3(32, 8)>>>();
    k_norm<<<(BB * LL * 32 + 255) / 256, 256>>>();
    k_edge<<<(BB * NE * 32 + 255) / 256, 256>>>();

    cudaFuncSetAttribute(k_boruvka, cudaFuncAttributeMaxDynamicSharedMemorySize, BORSMEM);
    k_boruvka<<<BB, 1024, BORSMEM>>>();
    k_revert<<<1, 256>>>();

    k_ssm<<<(BB * LL * 32 + 255) / 256, 256>>>(xpw, dtw, dtb, alog);

    cudaFuncSetAttribute(k_scan, cudaFuncAttributeMaxDynamicSharedMemorySize, SCAN_SMEM);
    k_scan<<<dim3(DI / CPB, BB), 256, SCAN_SMEM>>>();

    k_fuse<<<(BB * LL * 32 + 255) / 256, 256>>>(hg, hbp, og, obp, Dsp);
    k_gemm_out<<<dim3(2, 512), 256>>>(opw, out);
}

// round 8
// speedup vs baseline: 4.6874x; 1.0869x over previous
#include <cuda_runtime.h>
#include <math.h>

#define BB 8
#define HH 64
#define WW 64
#define LL 4096
#define DM 96
#define DI 192
#define DR 6
#define NE 8064
#define CPB 6   // channels per scan block (1 per warp)

// ------------------------- device scratch (static, no mallocs) -------------
static __device__ __align__(16) float  g_z[BB*LL*DI];      // (b,l,c) silu(z)
static __device__ __align__(16) float  g_xcpre[BB*DI*LL];  // (b,c,l) pre-conv
static __device__ __align__(16) float  g_xs[BB*DI*LL];     // (b,c,l) silu(conv)
static __device__ __align__(16) float  g_xst[BB*LL*DI];    // (b,l,c) transposed
static __device__ double g_rinv[BB*LL];                    // 1/max(norm,1e-8)
static __device__ unsigned long long   g_keys[BB*NE];      // packed (key|idx)
static __device__ int    g_pos[BB*LL];                     // node -> bfs position
static __device__ int    g_bfs[BB*LL];                     // pos  -> node
static __device__ int    g_parp[BB*LL];                    // pos  -> parent pos
static __device__ int    g_lvl[BB*(LL+2)];
static __device__ int    g_lvlcnt[BB*(LL+2)];
static __device__ int    g_lvlmin[BB*(LL+2)];
static __device__ int    g_revert[BB*(LL+2)];              // pos (or -1) per level
static __device__ int    g_numlev[BB];
static __device__ float  g_Csv[BB*LL];
static __device__ __align__(16) float2 g_eu[BB*LL*DI];     // node-ordered (ew, up)
static __device__ __align__(16) float  g_ag[BB*LL*DI];     // pos-ordered aggr
static __device__ __align__(16) float  g_yz[BB*LL*DI];     // (b,l,c)

// ------------------------- helpers -----------------------------------------
__device__ __forceinline__ float siluf(float x){ return x / (1.f + expf(-x)); }
__device__ __forceinline__ float softplusf(float x){
    return fmaxf(x, 0.f) + log1pf(expf(-fabsf(x)));
}
__device__ __forceinline__ float warpsum(float v){
    #pragma unroll
    for (int o = 16; o > 0; o >>= 1) v += __shfl_xor_sync(0xFFFFFFFFu, v, o);
    return v;
}
__device__ __forceinline__ void edge_uv(int e, int& u, int& v){
    if (e < 4032) { int r = e / 63, c = e % 63; u = r * 64 + c; v = u + 1; }
    else          { int j = e - 4032; u = j; v = j + 64; }
}

// ------------------------- 1. in_proj GEMM + split/silu (coalesced out) ----
__global__ void __launch_bounds__(256) k_gemm_in(const float* __restrict__ A,
                                                 const float* __restrict__ W)
{
    __shared__ float sA[64][33];
    __shared__ float sW[64][33];
    __shared__ float st[64][68];
    int bm = blockIdx.y * 64, bn = blockIdx.x * 64;
    int tid = threadIdx.x;
    int tx = tid & 15, ty = tid >> 4;
    float acc[4][4] = {};
    for (int k0 = 0; k0 < 96; k0 += 32) {
        for (int t = tid; t < 512; t += 256) {
            int r = t >> 3, kq = t & 7;
            float4 va = *(const float4*)(A + (size_t)(bm + r) * 96 + k0 + kq * 4);
            sA[r][kq*4+0] = va.x; sA[r][kq*4+1] = va.y;
            sA[r][kq*4+2] = va.z; sA[r][kq*4+3] = va.w;
            float4 vw = *(const float4*)(W + (size_t)(bn + r) * 96 + k0 + kq * 4);
            sW[r][kq*4+0] = vw.x; sW[r][kq*4+1] = vw.y;
            sW[r][kq*4+2] = vw.z; sW[r][kq*4+3] = vw.w;
        }
        __syncthreads();
        #pragma unroll
        for (int k = 0; k < 32; k++) {
            float a[4], b[4];
            #pragma unroll
            for (int i = 0; i < 4; i++) { a[i] = sA[ty*4+i][k]; b[i] = sW[tx*4+i][k]; }
            #pragma unroll
            for (int i = 0; i < 4; i++)
                #pragma unroll
                for (int j = 0; j < 4; j++)
                    acc[i][j] += a[i] * b[j];
        }
        __syncthreads();
    }
    int b = bm >> 12, l0 = bm & 4095;
    if (bn < DI) {
        #pragma unroll
        for (int i = 0; i < 4; i++)
            #pragma unroll
            for (int j = 0; j < 4; j++)
                st[tx*4+j][ty*4+i] = acc[i][j];
        __syncthreads();
        #pragma unroll
        for (int pass = 0; pass < 4; pass++) {
            int nn = pass * 16 + (tid >> 4);
            int mm = (tid & 15) * 4;
            float4 v = *(float4*)&st[nn][mm];
            *(float4*)&g_xcpre[((size_t)(b * DI + bn + nn)) * LL + l0 + mm] = v;
        }
    } else {
        int cb = bn - DI;
        #pragma unroll
        for (int i = 0; i < 4; i++)
            #pragma unroll
            for (int j = 0; j < 4; j++)
                st[ty*4+i][tx*4+j] = acc[i][j];
        __syncthreads();
        #pragma unroll
        for (int pass = 0; pass < 4; pass++) {
            int mm = pass * 16 + (tid >> 4);
            int nn = (tid & 15) * 4;
            float4 v = *(float4*)&st[mm][nn];
            v.x = siluf(v.x); v.y = siluf(v.y); v.z = siluf(v.z); v.w = siluf(v.w);
            *(float4*)&g_z[((size_t)(bm + mm)) * DI + cb + nn] = v;
        }
    }
}

// ------------------------- 2. depthwise 3x3 conv + silu --------------------
__global__ void k_conv(const float* __restrict__ cw, const float* __restrict__ cb)
{
    int gid = blockIdx.x * blockDim.x + threadIdx.x;
    if (gid >= BB * DI * LL) return;
    int l = gid & 4095;
    int c = (gid >> 12) % DI;
    int h = l >> 6, w = l & 63;
    const float* src = g_xcpre + (size_t)(gid - l);
    float acc = cb[c];
    #pragma unroll
    for (int ky = 0; ky < 3; ky++) {
        int hy = h + ky - 1;
        if ((unsigned)hy >= 64u) continue;
        #pragma unroll
        for (int kx = 0; kx < 3; kx++) {
            int wx = w + kx - 1;
            if ((unsigned)wx >= 64u) continue;
            acc += src[hy * 64 + wx] * cw[c * 9 + ky * 3 + kx];
        }
    }
    g_xs[gid] = siluf(acc);
}

// ------------------------- 2b. transpose xs (c,l) -> (l,c) -----------------
__global__ void __launch_bounds__(256) k_xt()
{
    __shared__ float t[32][33];
    int b  = blockIdx.z;
    int c0 = blockIdx.y * 32;
    int l0 = blockIdx.x * 32;
    int tx = threadIdx.x, ty = threadIdx.y;   // 32 x 8
    #pragma unroll
    for (int k = 0; k < 4; k++)
        t[ty + 8 * k][tx] = g_xs[((size_t)(b * DI + c0 + ty + 8 * k)) * LL + l0 + tx];
    __syncthreads();
    #pragma unroll
    for (int k = 0; k < 4; k++)
        g_xst[((size_t)(b * LL + l0 + ty + 8 * k)) * DI + c0 + tx] = t[tx][ty + 8 * k];
}

// ------------------------- 3. reciprocal norms (thread/node, 4 fp64 chains)
__global__ void k_norm()
{
    int gid = blockIdx.x * blockDim.x + threadIdx.x;  // b*L + l
    if (gid >= BB * LL) return;
    int b = gid >> 12, l = gid & 4095;
    const float* xp = g_xs + (size_t)b * DI * LL + l;
    double a0 = 0.0, a1 = 0.0, a2 = 0.0, a3 = 0.0;
    for (int c = 0; c < DI; c += 4) {
        double v0 = (double)xp[(size_t)(c + 0) * LL];
        double v1 = (double)xp[(size_t)(c + 1) * LL];
        double v2 = (double)xp[(size_t)(c + 2) * LL];
        double v3 = (double)xp[(size_t)(c + 3) * LL];
        a0 += v0 * v0; a1 += v1 * v1; a2 += v2 * v2; a3 += v3 * v3;
    }
    double s = (a0 + a1) + (a2 + a3);
    double nrm = sqrt(s);
    double den = nrm > 1e-8 ? nrm : 1e-8;
    g_rinv[gid] = 1.0 / den;
}

// ------------------------- 4. edge weights (thread/edge, 4 fp64 chains) ----
// w = exp(-(f_u.f_v)*rinv_u*rinv_v) in (0.36,2.72): positive double, bit
// pattern monotone. Pack top-51 bits with 13-bit edge index: one u64
// atomicMin = min-key with stable min-index tie-break.
__global__ void k_edge()
{
    int gid = blockIdx.x * blockDim.x + threadIdx.x;
    if (gid >= BB * NE) return;
    int b = gid / NE, e = gid % NE;
    int u, v;
    edge_uv(e, u, v);
    const float* f = g_xs + (size_t)b * DI * LL;
    double a0 = 0.0, a1 = 0.0, a2 = 0.0, a3 = 0.0;
    for (int c = 0; c < DI; c += 4) {
        a0 += (double)f[(size_t)(c + 0) * LL + u] * (double)f[(size_t)(c + 0) * LL + v];
        a1 += (double)f[(size_t)(c + 1) * LL + u] * (double)f[(size_t)(c + 1) * LL + v];
        a2 += (double)f[(size_t)(c + 2) * LL + u] * (double)f[(size_t)(c + 2) * LL + v];
        a3 += (double)f[(size_t)(c + 3) * LL + u] * (double)f[(size_t)(c + 3) * LL + v];
    }
    double s = (a0 + a1) + (a2 + a3);
    double w = exp(-s * g_rinv[b * LL + u] * g_rinv[b * LL + v]);
    unsigned long long bits = (unsigned long long)__double_as_longlong(w);
    g_keys[gid] = (bits & ~0x1FFFULL) | (unsigned long long)e;
}

// ------------------------- 5. Boruvka MST + warp BFS (block/batch) ---------
#define O_KEY  0
#define O_COMP 64512
#define O_PTR  80896
#define O_BEST 97280
#define O_FLAG 130048
#define BORSMEM 131072

__global__ void __launch_bounds__(1024, 1) k_boruvka()
{
    extern __shared__ unsigned char sm[];
    unsigned long long* skey = (unsigned long long*)(sm + O_KEY);
    unsigned int*       comp = (unsigned int*)(sm + O_COMP);
    unsigned int*       ptrA = (unsigned int*)(sm + O_PTR);
    unsigned long long* best = (unsigned long long*)(sm + O_BEST);
    unsigned int*       flag = (unsigned int*)(sm + O_FLAG);
    __shared__ int s_done, s_chg, s_nl, s_qt;

    int b = blockIdx.x;
    int tid = threadIdx.x;

    for (int e = tid; e < NE; e += 1024) skey[e] = g_keys[b * NE + e];
    for (int i = tid; i < LL; i += 1024) comp[i] = (unsigned)i;
    if (tid < 256) flag[tid] = 0;
    __syncthreads();

    for (int round = 0; round < 13; round++) {
        for (int i = tid; i < LL; i += 1024) best[i] = ~0ULL;
        if (tid == 0) s_done = 1;
        __syncthreads();

        for (int e = tid; e < NE; e += 1024) {
            int u, v; edge_uv(e, u, v);
            unsigned cu = comp[u], cv = comp[v];
            if (cu != cv) {
                unsigned long long k = skey[e];
                atomicMin(&best[cu], k);
                atomicMin(&best[cv], k);
            }
        }
        __syncthreads();
        for (int c = tid; c < LL; c += 1024) {
            unsigned long long bk = best[c];
            if (bk != ~0ULL) {
                int e = (int)(bk & 8191ULL);
                atomicOr(&flag[e >> 5], 1u << (e & 31));
                int u, v; edge_uv(e, u, v);
                unsigned cu = comp[u], cv = comp[v];
                ptrA[c] = (cu == (unsigned)c) ? cv : cu;
                s_done = 0;
            } else {
                ptrA[c] = (unsigned)c;
            }
        }
        __syncthreads();
        if (s_done) break;
        for (int c = tid; c < LL; c += 1024) {
            unsigned p = ptrA[c];
            if (p != (unsigned)c && ptrA[p] == (unsigned)c && (unsigned)c < p)
                ptrA[c] = (unsigned)c;
        }
        __syncthreads();
        for (int it = 0; it < 13; it++) {
            if (tid == 0) s_chg = 0;
            __syncthreads();
            for (int c = tid; c < LL; c += 1024) {
                unsigned p = ptrA[c];
                unsigned g = ptrA[p];
                if (p != g) { ptrA[c] = g; s_chg = 1; }
            }
            __syncthreads();
            if (!s_chg) break;
        }
        for (int i = tid; i < LL; i += 1024) comp[i] = ptrA[comp[i]];
        __syncthreads();
    }

    // ---- warp-synchronous BFS from node 0 (warp 0 only) ----
    unsigned int* dep = (unsigned int*)(sm + O_KEY);
    unsigned int* par = (unsigned int*)(sm + O_KEY + 16384);
    unsigned int* q   = (unsigned int*)(sm + O_KEY + 32768);
    for (int i = tid; i < LL; i += 1024) dep[i] = 0xFFFFFFFFu;
    __syncthreads();
    if (tid == 0) { dep[0] = 0; par[0] = 0; q[0] = 0; s_qt = 1; }
    __syncthreads();

    if (tid < 32) {
        int qh = 0, qt = 1;
        while (qh < qt) {
            for (int i = qh + tid; i < qt; i += 32) {
                int n = (int)q[i];
                int h = n >> 6, w = n & 63;
                unsigned d = dep[n] + 1;
                if (w < 63) { int e = h * 63 + w; int m = n + 1;
                    if ((flag[e >> 5] >> (e & 31) & 1u) && dep[m] == 0xFFFFFFFFu) {
                        dep[m] = d; par[m] = (unsigned)n; q[atomicAdd(&s_qt, 1)] = (unsigned)m; } }
                if (w > 0)  { int e = h * 63 + w - 1; int m = n - 1;
                    if ((flag[e >> 5] >> (e & 31) & 1u) && dep[m] == 0xFFFFFFFFu) {
                        dep[m] = d; par[m] = (unsigned)n; q[atomicAdd(&s_qt, 1)] = (unsigned)m; } }
                if (h < 63) { int e = 4032 + n; int m = n + 64;
                    if ((flag[e >> 5] >> (e & 31) & 1u) && dep[m] == 0xFFFFFFFFu) {
                        dep[m] = d; par[m] = (unsigned)n; q[atomicAdd(&s_qt, 1)] = (unsigned)m; } }
                if (h > 0)  { int e = 4032 + n - 64; int m = n - 64;
                    if ((flag[e >> 5] >> (e & 31) & 1u) && dep[m] == 0xFFFFFFFFu) {
                        dep[m] = d; par[m] = (unsigned)n; q[atomicAdd(&s_qt, 1)] = (unsigned)m; } }
            }
            __syncwarp();
            qh = qt;
            qt = *(volatile int*)&s_qt;
            __syncwarp();
        }
    }
    __syncthreads();

    // ---- levels + positions ----
    unsigned int* lvlcnt = (unsigned int*)(sm + O_COMP);
    unsigned int* lvlmin = (unsigned int*)(sm + O_PTR);
    unsigned int* cur    = (unsigned int*)(sm + O_BEST);
    unsigned int* posA   = (unsigned int*)(sm + O_BEST + 16384);
    for (int i = tid; i < LL; i += 1024) { lvlcnt[i] = 0; lvlmin[i] = 0x7FFFFFFFu; }
    if (tid == 0) s_nl = 0;
    __syncthreads();
    for (int i = tid; i < LL; i += 1024) {
        unsigned d = dep[i];
        atomicAdd(&lvlcnt[d], 1u);
        atomicMin(&lvlmin[d], (unsigned)i);
        atomicMax(&s_nl, (int)d);
    }
    __syncthreads();
    if (tid == 0) {
        int nl = s_nl + 1;
        g_numlev[b] = nl;
        int run = 0;
        for (int d = 0; d < nl; d++) {
            g_lvl[b * (LL + 2) + d] = run;
            g_lvlcnt[b * (LL + 2) + d] = (int)lvlcnt[d];
            g_lvlmin[b * (LL + 2) + d] = (int)lvlmin[d];
            cur[d] = (unsigned)run;
            run += (int)lvlcnt[d];
        }
        g_lvl[b * (LL + 2) + nl] = LL;
    }
    __syncthreads();
    for (int i = tid; i < LL; i += 1024)
        posA[i] = atomicAdd(&cur[dep[i]], 1u);
    __syncthreads();
    for (int i = tid; i < LL; i += 1024) {
        unsigned p = posA[i];
        g_pos[b * LL + i] = (int)p;
        g_bfs[b * LL + p] = i;
        g_parp[b * LL + p] = (int)posA[par[i]];
    }
}

// ------------------------- 5b. padded-scatter revert flags (as pos) --------
__global__ void k_revert()
{
    __shared__ int nlmax;
    if (threadIdx.x == 0) {
        int m = 0;
        for (int b = 0; b < BB; b++) m = max(m, g_numlev[b]);
        nlmax = m;
    }
    __syncthreads();
    for (int d = threadIdx.x; d < nlmax; d += blockDim.x) {
        int cnt[BB];
        int md = 0;
        for (int b = 0; b < BB; b++) {
            int c = (d < g_numlev[b]) ? g_lvlcnt[b * (LL + 2) + d] : 0;
            cnt[b] = c;
            md = max(md, c);
        }
        for (int b = 0; b < BB; b++) {
            int r = -1;
            if (d > 0 && cnt[b] > 0 && cnt[b] < md)
                r = g_pos[b * LL + g_lvlmin[b * (LL + 2) + d]];
            g_revert[b * (LL + 2) + d] = r;
        }
    }
}

// ------------------------- 6. fused x_dbl + dts/deltaA/BX (node-ordered) ---
__global__ void __launch_bounds__(256) k_ssm(const float* __restrict__ XW,
                                             const float* __restrict__ dtW,
                                             const float* __restrict__ dtB,
                                             const float* __restrict__ Alog)
{
    int gw = (blockIdx.x * 256 + threadIdx.x) >> 5;   // b*LL + l
    int lane = threadIdx.x & 31;
    if (gw >= BB * LL) return;
    const float* xrow = g_xst + (size_t)gw * DI;

    float xv[6];
    #pragma unroll
    for (int j = 0; j < 6; j++) xv[j] = xrow[lane + 32 * j];

    float acc[8];
    #pragma unroll
    for (int c8 = 0; c8 < 8; c8++) {
        float s = 0.f;
        #pragma unroll
        for (int j = 0; j < 6; j++) s += xv[j] * XW[c8 * DI + lane + 32 * j];
        acc[c8] = warpsum(s);
    }
    float Bsv = acc[6];
    if (lane == 0) g_Csv[gw] = acc[7];

    float2* eurow = g_eu + (size_t)gw * DI;
    #pragma unroll
    for (int j = 0; j < 6; j++) {
        int d = lane + 32 * j;
        float s = dtB[d];
        #pragma unroll
        for (int r = 0; r < DR; r++) s += acc[r] * dtW[d * DR + r];
        float dt = softplusf(s);
        float ew = expf(-expf(Alog[d]) * dt);
        float bx = dt * Bsv * xv[j];
        eurow[d] = make_float2(ew, bx);
    }
}

// ------------------------- 7. warp-autonomous smem tree scan ----------------
// Block = (batch, 6 channels); each warp owns ONE channel with a private
// acc/ew slice -> level loops need only __syncwarp (no block barriers).
#define SCAN_SMEM (CPB*LL*4*2 + LL*4 + (LL+2)*4)
__global__ void __launch_bounds__(192) k_scan()
{
    extern __shared__ unsigned char sms[];
    float* acc_all = (float*)sms;                      // [CPB][LL]
    float* ew_all  = (float*)(sms + CPB*LL*4);         // [CPB][LL]
    int*   parp_s  = (int*)(sms + CPB*LL*8);           // [LL]
    int*   lvl_s   = (int*)(sms + CPB*LL*8 + LL*4);    // [nl+1]

    int b  = blockIdx.y;
    int c0 = blockIdx.x * CPB;
    int tid = threadIdx.x;
    int warp = tid >> 5, lane = tid & 31;
    int nl = g_numlev[b];
    const int* revp = g_revert + b * (LL + 2);
    const int* bfs  = g_bfs + b * LL;
    const float2* eu = g_eu + (size_t)(b * LL) * DI;
    float* agout = g_ag + (size_t)(b * LL) * DI;

    for (int i = tid; i < LL; i += 192) parp_s[i] = g_parp[b * LL + i];
    for (int i = tid; i <= nl; i += 192) lvl_s[i] = g_lvl[b * (LL + 2) + i];
    for (int idx = tid; idx < LL * CPB; idx += 192) {
        int pos = idx / CPB, cc = idx % CPB;
        float2 v = eu[(size_t)bfs[pos] * DI + c0 + cc];
        ew_all[cc * LL + pos]  = v.x;
        acc_all[cc * LL + pos] = v.y;
    }
    __syncthreads();

    // each warp: private channel slice -> warp-synchronous level loops
    float* A = acc_all + warp * LL;
    float* E = ew_all + warp * LL;

    // up-sweep: children accumulate into parents (one level up)
    for (int lev = nl - 1; lev >= 1; --lev) {
        int ls = lvl_s[lev], le = lvl_s[lev + 1];
        for (int pos = ls + lane; pos < le; pos += 32)
            atomicAdd(&A[parp_s[pos]], E[pos] * A[pos]);
        __syncwarp();
    }
    // down-sweep: in-place (parents already final)
    for (int lev = 0; lev < nl; ++lev) {
        int ls = lvl_s[lev], le = lvl_s[lev + 1];
        int rev = revp[lev];
        for (int pos = ls + lane; pos < le; pos += 32) {
            float u = A[pos];
            float val = u;
            if (lev > 0) {
                float w = E[pos];
                val = u + w * (A[parp_s[pos]] - w * u);
                if (pos == rev) val = u;
            }
            A[pos] = val;
        }
        __syncwarp();
    }
    __syncthreads();

    // stream out (pos-ordered)
    for (int idx = tid; idx < LL * CPB; idx += 192) {
        int pos = idx / CPB, cc = idx % CPB;
        agout[(size_t)pos * DI + c0 + cc] = acc_all[cc * LL + pos];
    }
}

// ------------------------- 8. fused LN -> *Cs -> +Ds*xs -> LN -> *z --------
__global__ void __launch_bounds__(256) k_fuse(const float* __restrict__ hg,
                                              const float* __restrict__ hb,
                                              const float* __restrict__ og,
                                              const float* __restrict__ ob,
                                              const float* __restrict__ Ds)
{
    int warp = (blockIdx.x * 256 + threadIdx.x) >> 5;
    int lane = threadIdx.x & 31;
    if (warp >= BB * LL) return;
    int b = warp >> 12;
    int pos = g_pos[warp];
    const float* hrow = g_ag + ((size_t)(b * LL) + pos) * DI;
    const float* xrow = g_xst + (size_t)warp * DI;

    float v[6];
    #pragma unroll
    for (int j = 0; j < 6; j++) v[j] = hrow[lane + 32 * j];

    float s = 0.f;
    #pragma unroll
    for (int j = 0; j < 6; j++) s += v[j];
    float mu = warpsum(s) * (1.f / 192.f);
    float q = 0.f;
    #pragma unroll
    for (int j = 0; j < 6; j++) { float d = v[j] - mu; q += d * d; }
    float inv = rsqrtf(warpsum(q) * (1.f / 192.f) + 1e-5f);

    float Cv = g_Csv[warp];
    float y[6];
    #pragma unroll
    for (int j = 0; j < 6; j++) {
        int c = lane + 32 * j;
        float hn = (v[j] - mu) * inv * hg[c] + hb[c];
        y[j] = hn * Cv + Ds[c] * xrow[c];
    }

    s = 0.f;
    #pragma unroll
    for (int j = 0; j < 6; j++) s += y[j];
    float mu2 = warpsum(s) * (1.f / 192.f);
    q = 0.f;
    #pragma unroll
    for (int j = 0; j < 6; j++) { float d = y[j] - mu2; q += d * d; }
    float inv2 = rsqrtf(warpsum(q) * (1.f / 192.f) + 1e-5f);

    #pragma unroll
    for (int j = 0; j < 6; j++) {
        int c = lane + 32 * j;
        float y2 = (y[j] - mu2) * inv2 * og[c] + ob[c];
        g_yz[(size_t)warp * DI + c] = y2 * g_z[(size_t)warp * DI + c];
    }
}

// ------------------------- 9. out_proj GEMM --------------------------------
__global__ void __launch_bounds__(256) k_gemm_out(const float* __restrict__ W,
                                                  float* __restrict__ out)
{
    __shared__ float sA[64][33];
    __shared__ float sW[64][33];
    int bm = blockIdx.y * 64, bn = blockIdx.x * 64;
    int tid = threadIdx.x;
    int tx = tid & 15, ty = tid >> 4;
    float acc[4][4] = {};
    for (int k0 = 0; k0 < 192; k0 += 32) {
        for (int t = tid; t < 512; t += 256) {
            int r = t >> 3, kq = t & 7;
            float4 va = *(const float4*)(g_yz + (size_t)(bm + r) * 192 + k0 + kq * 4);
            sA[r][kq*4+0] = va.x; sA[r][kq*4+1] = va.y;
            sA[r][kq*4+2] = va.z; sA[r][kq*4+3] = va.w;
            float4 vw;
            if (bn + r < 96)
                vw = *(const float4*)(W + (size_t)(bn + r) * 192 + k0 + kq * 4);
            else
                vw = make_float4(0.f, 0.f, 0.f, 0.f);
            sW[r][kq*4+0] = vw.x; sW[r][kq*4+1] = vw.y;
            sW[r][kq*4+2] = vw.z; sW[r][kq*4+3] = vw.w;
        }
        __syncthreads();
        #pragma unroll
        for (int k = 0; k < 32; k++) {
            float a[4], bv[4];
            #pragma unroll
            for (int i = 0; i < 4; i++) { a[i] = sA[ty*4+i][k]; bv[i] = sW[tx*4+i][k]; }
            #pragma unroll
            for (int i = 0; i < 4; i++)
                #pragma unroll
                for (int j = 0; j < 4; j++)
                    acc[i][j] += a[i] * bv[j];
        }
        __syncthreads();
    }
    #pragma unroll
    for (int i = 0; i < 4; i++) {
        int m = bm + ty * 4 + i;
        #pragma unroll
        for (int j = 0; j < 4; j++) {
            int n = bn + tx * 4 + j;
            if (n < 96) out[(size_t)m * 96 + n] = acc[i][j];
        }
    }
}

// ------------------------- launch ------------------------------------------
extern "C" void kernel_launch(void* const* d_in, const int* in_sizes, int n_in,
                              void* d_out, int out_size)
{
    const float* x    = (const float*)d_in[0];
    const float* inw  = (const float*)d_in[1];
    const float* cw   = (const float*)d_in[2];
    const float* cb   = (const float*)d_in[3];
    const float* xpw  = (const float*)d_in[4];
    const float* dtw  = (const float*)d_in[5];
    const float* dtb  = (const float*)d_in[6];
    const float* alog = (const float*)d_in[7];
    const float* Dsp  = (const float*)d_in[8];
    const float* hg   = (const float*)d_in[9];
    const float* hbp  = (const float*)d_in[10];
    const float* og   = (const float*)d_in[11];
    const float* obp  = (const float*)d_in[12];
    const float* opw  = (const float*)d_in[13];
    float* out = (float*)d_out;

    k_gemm_in<<<dim3(6, 512), 256>>>(x, inw);
    k_conv<<<(BB * DI * LL + 255) / 256, 256>>>(cw, cb);
    k_xt<<<dim3(128, 6, 8), dim3(32, 8)>>>();
    k_norm<<<(BB * LL + 255) / 256, 256>>>();
    k_edge<<<(BB * NE + 255) / 256, 256>>>();

    cudaFuncSetAttribute(k_boruvka, cudaFuncAttributeMaxDynamicSharedMemorySize, BORSMEM);
    k_boruvka<<<BB, 1024, BORSMEM>>>();
    k_revert<<<1, 256>>>();

    k_ssm<<<(BB * LL * 32 + 255) / 256, 256>>>(xpw, dtw, dtb, alog);

    cudaFuncSetAttribute(k_scan, cudaFuncAttributeMaxDynamicSharedMemorySize, SCAN_SMEM);
    k_scan<<<dim3(DI / CPB, BB), 192, SCAN_SMEM>>>();

    k_fuse<<<(BB * LL * 32 + 255) / 256, 256>>>(hg, hbp, og, obp, Dsp);
    k_gemm_out<<<dim3(2, 512), 256>>>(opw, out);
}

// round 9
// speedup vs baseline: 5.0142x; 1.0697x over previous
#include <cuda_runtime.h>
#include <math.h>

#define BB 8
#define HH 64
#define WW 64
#define LL 4096
#define DM 96
#define DI 192
#define DR 6
#define NE 8064
#define CPB 6   // channels per scan block (1 per warp)

// ------------------------- device scratch (static, no mallocs) -------------
static __device__ __align__(16) float  g_z[BB*LL*DI];      // (b,l,c) silu(z)
static __device__ __align__(16) float  g_xcpre[BB*DI*LL];  // (b,c,l) pre-conv
static __device__ __align__(16) float  g_xs[BB*DI*LL];     // (b,c,l) silu(conv)
static __device__ __align__(16) float  g_xst[BB*LL*DI];    // (b,l,c) transposed
static __device__ double g_rinv[BB*LL];                    // 1/max(norm,1e-8)
static __device__ unsigned long long   g_keys[BB*NE];      // packed (key|idx)
static __device__ int    g_pos[BB*LL];                     // node -> bfs position
static __device__ int    g_bfs[BB*LL];                     // pos  -> node
static __device__ int    g_parp[BB*LL];                    // pos  -> parent pos
static __device__ int    g_lvl[BB*(LL+2)];
static __device__ int    g_lvlcnt[BB*(LL+2)];
static __device__ int    g_lvlmin[BB*(LL+2)];
static __device__ int    g_revert[BB*(LL+2)];              // pos (or -1) per level
static __device__ int    g_numlev[BB];
static __device__ float  g_Csv[BB*LL];
static __device__ __align__(16) float2 g_eu[BB*LL*DI];     // node-ordered (ew, up)
static __device__ __align__(16) float  g_ag[BB*LL*DI];     // pos-ordered aggr
static __device__ __align__(16) float  g_yz[BB*LL*DI];     // (b,l,c)

// ------------------------- helpers -----------------------------------------
__device__ __forceinline__ float siluf(float x){ return x / (1.f + expf(-x)); }
__device__ __forceinline__ float softplusf(float x){
    return fmaxf(x, 0.f) + log1pf(expf(-fabsf(x)));
}
__device__ __forceinline__ float warpsum(float v){
    #pragma unroll
    for (int o = 16; o > 0; o >>= 1) v += __shfl_xor_sync(0xFFFFFFFFu, v, o);
    return v;
}
__device__ __forceinline__ void edge_uv(int e, int& u, int& v){
    if (e < 4032) { int r = e / 63, c = e % 63; u = r * 64 + c; v = u + 1; }
    else          { int j = e - 4032; u = j; v = j + 64; }
}

// ------------------------- 1. in_proj GEMM + split/silu (coalesced out) ----
__global__ void __launch_bounds__(256) k_gemm_in(const float* __restrict__ A,
                                                 const float* __restrict__ W)
{
    __shared__ float sA[64][33];
    __shared__ float sW[64][33];
    __shared__ float st[64][68];
    int bm = blockIdx.y * 64, bn = blockIdx.x * 64;
    int tid = threadIdx.x;
    int tx = tid & 15, ty = tid >> 4;
    float acc[4][4] = {};
    for (int k0 = 0; k0 < 96; k0 += 32) {
        for (int t = tid; t < 512; t += 256) {
            int r = t >> 3, kq = t & 7;
            float4 va = *(const float4*)(A + (size_t)(bm + r) * 96 + k0 + kq * 4);
            sA[r][kq*4+0] = va.x; sA[r][kq*4+1] = va.y;
            sA[r][kq*4+2] = va.z; sA[r][kq*4+3] = va.w;
            float4 vw = *(const float4*)(W + (size_t)(bn + r) * 96 + k0 + kq * 4);
            sW[r][kq*4+0] = vw.x; sW[r][kq*4+1] = vw.y;
            sW[r][kq*4+2] = vw.z; sW[r][kq*4+3] = vw.w;
        }
        __syncthreads();
        #pragma unroll
        for (int k = 0; k < 32; k++) {
            float a[4], b[4];
            #pragma unroll
            for (int i = 0; i < 4; i++) { a[i] = sA[ty*4+i][k]; b[i] = sW[tx*4+i][k]; }
            #pragma unroll
            for (int i = 0; i < 4; i++)
                #pragma unroll
                for (int j = 0; j < 4; j++)
                    acc[i][j] += a[i] * b[j];
        }
        __syncthreads();
    }
    int b = bm >> 12, l0 = bm & 4095;
    if (bn < DI) {
        #pragma unroll
        for (int i = 0; i < 4; i++)
            #pragma unroll
            for (int j = 0; j < 4; j++)
                st[tx*4+j][ty*4+i] = acc[i][j];
        __syncthreads();
        #pragma unroll
        for (int pass = 0; pass < 4; pass++) {
            int nn = pass * 16 + (tid >> 4);
            int mm = (tid & 15) * 4;
            float4 v = *(float4*)&st[nn][mm];
            *(float4*)&g_xcpre[((size_t)(b * DI + bn + nn)) * LL + l0 + mm] = v;
        }
    } else {
        int cb = bn - DI;
        #pragma unroll
        for (int i = 0; i < 4; i++)
            #pragma unroll
            for (int j = 0; j < 4; j++)
                st[ty*4+i][tx*4+j] = acc[i][j];
        __syncthreads();
        #pragma unroll
        for (int pass = 0; pass < 4; pass++) {
            int mm = pass * 16 + (tid >> 4);
            int nn = (tid & 15) * 4;
            float4 v = *(float4*)&st[mm][nn];
            v.x = siluf(v.x); v.y = siluf(v.y); v.z = siluf(v.z); v.w = siluf(v.w);
            *(float4*)&g_z[((size_t)(bm + mm)) * DI + cb + nn] = v;
        }
    }
}

// ------------------------- 2. depthwise conv + silu + transpose (fused) ----
// Block = (b, 32-c tile, 32-l tile). Emits g_xs (c,l) AND g_xst (l,c), both
// coalesced, killing the separate transpose pass.
__global__ void __launch_bounds__(256) k_conv(const float* __restrict__ cw,
                                              const float* __restrict__ cb)
{
    __shared__ float t[32][33];
    int b  = blockIdx.z;
    int c0 = blockIdx.y * 32;
    int l0 = blockIdx.x * 32;
    int tx = threadIdx.x, ty = threadIdx.y;   // 32 x 8
    int l = l0 + tx;
    int h = l >> 6, w = l & 63;
    #pragma unroll
    for (int k = 0; k < 4; k++) {
        int c = c0 + ty + 8 * k;
        const float* src = g_xcpre + (size_t)(b * DI + c) * LL;
        float acc = cb[c];
        #pragma unroll
        for (int ky = 0; ky < 3; ky++) {
            int hy = h + ky - 1;
            if ((unsigned)hy >= 64u) continue;
            #pragma unroll
            for (int kx = 0; kx < 3; kx++) {
                int wx = w + kx - 1;
                if ((unsigned)wx >= 64u) continue;
                acc += src[hy * 64 + wx] * cw[c * 9 + ky * 3 + kx];
            }
        }
        float val = siluf(acc);
        g_xs[(size_t)(b * DI + c) * LL + l] = val;
        t[ty + 8 * k][tx] = val;
    }
    __syncthreads();
    #pragma unroll
    for (int k = 0; k < 4; k++)
        g_xst[((size_t)(b * LL + l0 + ty + 8 * k)) * DI + c0 + tx] = t[tx][ty + 8 * k];
}

// ------------------------- 3. reciprocal norms (thread/node, 4 fp64 chains)
__global__ void k_norm()
{
    int gid = blockIdx.x * blockDim.x + threadIdx.x;  // b*L + l
    if (gid >= BB * LL) return;
    int b = gid >> 12, l = gid & 4095;
    const float* xp = g_xs + (size_t)b * DI * LL + l;
    double a0 = 0.0, a1 = 0.0, a2 = 0.0, a3 = 0.0;
    for (int c = 0; c < DI; c += 4) {
        double v0 = (double)xp[(size_t)(c + 0) * LL];
        double v1 = (double)xp[(size_t)(c + 1) * LL];
        double v2 = (double)xp[(size_t)(c + 2) * LL];
        double v3 = (double)xp[(size_t)(c + 3) * LL];
        a0 += v0 * v0; a1 += v1 * v1; a2 += v2 * v2; a3 += v3 * v3;
    }
    double s = (a0 + a1) + (a2 + a3);
    double nrm = sqrt(s);
    double den = nrm > 1e-8 ? nrm : 1e-8;
    g_rinv[gid] = 1.0 / den;
}

// ------------------------- 4. edge weights (thread/edge, 4 fp64 chains) ----
__global__ void k_edge()
{
    int gid = blockIdx.x * blockDim.x + threadIdx.x;
    if (gid >= BB * NE) return;
    int b = gid / NE, e = gid % NE;
    int u, v;
    edge_uv(e, u, v);
    const float* f = g_xs + (size_t)b * DI * LL;
    double a0 = 0.0, a1 = 0.0, a2 = 0.0, a3 = 0.0;
    for (int c = 0; c < DI; c += 4) {
        a0 += (double)f[(size_t)(c + 0) * LL + u] * (double)f[(size_t)(c + 0) * LL + v];
        a1 += (double)f[(size_t)(c + 1) * LL + u] * (double)f[(size_t)(c + 1) * LL + v];
        a2 += (double)f[(size_t)(c + 2) * LL + u] * (double)f[(size_t)(c + 2) * LL + v];
        a3 += (double)f[(size_t)(c + 3) * LL + u] * (double)f[(size_t)(c + 3) * LL + v];
    }
    double s = (a0 + a1) + (a2 + a3);
    double w = exp(-s * g_rinv[b * LL + u] * g_rinv[b * LL + v]);
    unsigned long long bits = (unsigned long long)__double_as_longlong(w);
    g_keys[gid] = (bits & ~0x1FFFULL) | (unsigned long long)e;
}

// ------------------------- 5. Boruvka MST + warp BFS (block/batch) ---------
#define O_KEY  0
#define O_COMP 64512
#define O_PTR  80896
#define O_BEST 97280
#define O_FLAG 130048
#define BORSMEM 131072

__global__ void __launch_bounds__(1024, 1) k_boruvka()
{
    extern __shared__ unsigned char sm[];
    unsigned long long* skey = (unsigned long long*)(sm + O_KEY);
    unsigned int*       comp = (unsigned int*)(sm + O_COMP);
    unsigned int*       ptrA = (unsigned int*)(sm + O_PTR);
    unsigned long long* best = (unsigned long long*)(sm + O_BEST);
    unsigned int*       flag = (unsigned int*)(sm + O_FLAG);
    __shared__ int s_done, s_chg, s_nl, s_qt;

    int b = blockIdx.x;
    int tid = threadIdx.x;

    for (int e = tid; e < NE; e += 1024) skey[e] = g_keys[b * NE + e];
    for (int i = tid; i < LL; i += 1024) comp[i] = (unsigned)i;
    if (tid < 256) flag[tid] = 0;
    __syncthreads();

    for (int round = 0; round < 13; round++) {
        for (int i = tid; i < LL; i += 1024) best[i] = ~0ULL;
        if (tid == 0) s_done = 1;
        __syncthreads();

        for (int e = tid; e < NE; e += 1024) {
            int u, v; edge_uv(e, u, v);
            unsigned cu = comp[u], cv = comp[v];
            if (cu != cv) {
                unsigned long long k = skey[e];
                atomicMin(&best[cu], k);
                atomicMin(&best[cv], k);
            }
        }
        __syncthreads();
        for (int c = tid; c < LL; c += 1024) {
            unsigned long long bk = best[c];
            if (bk != ~0ULL) {
                int e = (int)(bk & 8191ULL);
                atomicOr(&flag[e >> 5], 1u << (e & 31));
                int u, v; edge_uv(e, u, v);
                unsigned cu = comp[u], cv = comp[v];
                ptrA[c] = (cu == (unsigned)c) ? cv : cu;
                s_done = 0;
            } else {
                ptrA[c] = (unsigned)c;
            }
        }
        __syncthreads();
        if (s_done) break;
        for (int c = tid; c < LL; c += 1024) {
            unsigned p = ptrA[c];
            if (p != (unsigned)c && ptrA[p] == (unsigned)c && (unsigned)c < p)
                ptrA[c] = (unsigned)c;
        }
        __syncthreads();
        for (int it = 0; it < 13; it++) {
            if (tid == 0) s_chg = 0;
            __syncthreads();
            for (int c = tid; c < LL; c += 1024) {
                unsigned p = ptrA[c];
                unsigned g = ptrA[p];
                if (p != g) { ptrA[c] = g; s_chg = 1; }
            }
            __syncthreads();
            if (!s_chg) break;
        }
        for (int i = tid; i < LL; i += 1024) comp[i] = ptrA[comp[i]];
        __syncthreads();
    }

    // ---- warp-synchronous BFS from node 0 (warp 0 only) ----
    unsigned int* dep = (unsigned int*)(sm + O_KEY);
    unsigned int* par = (unsigned int*)(sm + O_KEY + 16384);
    unsigned int* q   = (unsigned int*)(sm + O_KEY + 32768);
    for (int i = tid; i < LL; i += 1024) dep[i] = 0xFFFFFFFFu;
    __syncthreads();
    if (tid == 0) { dep[0] = 0; par[0] = 0; q[0] = 0; s_qt = 1; }
    __syncthreads();

    if (tid < 32) {
        int qh = 0, qt = 1;
        while (qh < qt) {
            for (int i = qh + tid; i < qt; i += 32) {
                int n = (int)q[i];
                int h = n >> 6, w = n & 63;
                unsigned d = dep[n] + 1;
                if (w < 63) { int e = h * 63 + w; int m = n + 1;
                    if ((flag[e >> 5] >> (e & 31) & 1u) && dep[m] == 0xFFFFFFFFu) {
                        dep[m] = d; par[m] = (unsigned)n; q[atomicAdd(&s_qt, 1)] = (unsigned)m; } }
                if (w > 0)  { int e = h * 63 + w - 1; int m = n - 1;
                    if ((flag[e >> 5] >> (e & 31) & 1u) && dep[m] == 0xFFFFFFFFu) {
                        dep[m] = d; par[m] = (unsigned)n; q[atomicAdd(&s_qt, 1)] = (unsigned)m; } }
                if (h < 63) { int e = 4032 + n; int m = n + 64;
                    if ((flag[e >> 5] >> (e & 31) & 1u) && dep[m] == 0xFFFFFFFFu) {
                        dep[m] = d; par[m] = (unsigned)n; q[atomicAdd(&s_qt, 1)] = (unsigned)m; } }
                if (h > 0)  { int e = 4032 + n - 64; int m = n - 64;
                    if ((flag[e >> 5] >> (e & 31) & 1u) && dep[m] == 0xFFFFFFFFu) {
                        dep[m] = d; par[m] = (unsigned)n; q[atomicAdd(&s_qt, 1)] = (unsigned)m; } }
            }
            __syncwarp();
            qh = qt;
            qt = *(volatile int*)&s_qt;
            __syncwarp();
        }
    }
    __syncthreads();

    // ---- levels + positions ----
    unsigned int* lvlcnt = (unsigned int*)(sm + O_COMP);
    unsigned int* lvlmin = (unsigned int*)(sm + O_PTR);
    unsigned int* cur    = (unsigned int*)(sm + O_BEST);
    unsigned int* posA   = (unsigned int*)(sm + O_BEST + 16384);
    for (int i = tid; i < LL; i += 1024) { lvlcnt[i] = 0; lvlmin[i] = 0x7FFFFFFFu; }
    if (tid == 0) s_nl = 0;
    __syncthreads();
    for (int i = tid; i < LL; i += 1024) {
        unsigned d = dep[i];
        atomicAdd(&lvlcnt[d], 1u);
        atomicMin(&lvlmin[d], (unsigned)i);
        atomicMax(&s_nl, (int)d);
    }
    __syncthreads();
    if (tid == 0) {
        int nl = s_nl + 1;
        g_numlev[b] = nl;
        int run = 0;
        for (int d = 0; d < nl; d++) {
            g_lvl[b * (LL + 2) + d] = run;
            g_lvlcnt[b * (LL + 2) + d] = (int)lvlcnt[d];
            g_lvlmin[b * (LL + 2) + d] = (int)lvlmin[d];
            cur[d] = (unsigned)run;
            run += (int)lvlcnt[d];
        }
        g_lvl[b * (LL + 2) + nl] = LL;
    }
    __syncthreads();
    for (int i = tid; i < LL; i += 1024)
        posA[i] = atomicAdd(&cur[dep[i]], 1u);
    __syncthreads();
    for (int i = tid; i < LL; i += 1024) {
        unsigned p = posA[i];
        g_pos[b * LL + i] = (int)p;
        g_bfs[b * LL + p] = i;
        g_parp[b * LL + p] = (int)posA[par[i]];
    }
}

// ------------------------- 5b. padded-scatter revert flags (as pos) --------
__global__ void k_revert()
{
    __shared__ int nlmax;
    if (threadIdx.x == 0) {
        int m = 0;
        for (int b = 0; b < BB; b++) m = max(m, g_numlev[b]);
        nlmax = m;
    }
    __syncthreads();
    for (int d = threadIdx.x; d < nlmax; d += blockDim.x) {
        int cnt[BB];
        int md = 0;
        for (int b = 0; b < BB; b++) {
            int c = (d < g_numlev[b]) ? g_lvlcnt[b * (LL + 2) + d] : 0;
            cnt[b] = c;
            md = max(md, c);
        }
        for (int b = 0; b < BB; b++) {
            int r = -1;
            if (d > 0 && cnt[b] > 0 && cnt[b] < md)
                r = g_pos[b * LL + g_lvlmin[b * (LL + 2) + d]];
            g_revert[b * (LL + 2) + d] = r;
        }
    }
}

// ------------------------- 6. fused x_dbl + dts/deltaA/BX (node-ordered) ---
__global__ void __launch_bounds__(256) k_ssm(const float* __restrict__ XW,
                                             const float* __restrict__ dtW,
                                             const float* __restrict__ dtB,
                                             const float* __restrict__ Alog)
{
    int gw = (blockIdx.x * 256 + threadIdx.x) >> 5;   // b*LL + l
    int lane = threadIdx.x & 31;
    if (gw >= BB * LL) return;
    const float* xrow = g_xst + (size_t)gw * DI;

    float xv[6];
    #pragma unroll
    for (int j = 0; j < 6; j++) xv[j] = xrow[lane + 32 * j];

    float acc[8];
    #pragma unroll
    for (int c8 = 0; c8 < 8; c8++) {
        float s = 0.f;
        #pragma unroll
        for (int j = 0; j < 6; j++) s += xv[j] * XW[c8 * DI + lane + 32 * j];
        acc[c8] = warpsum(s);
    }
    float Bsv = acc[6];
    if (lane == 0) g_Csv[gw] = acc[7];

    float2* eurow = g_eu + (size_t)gw * DI;
    #pragma unroll
    for (int j = 0; j < 6; j++) {
        int d = lane + 32 * j;
        float s = dtB[d];
        #pragma unroll
        for (int r = 0; r < DR; r++) s += acc[r] * dtW[d * DR + r];
        float dt = softplusf(s);
        float ew = expf(-expf(Alog[d]) * dt);
        float bx = dt * Bsv * xv[j];
        eurow[d] = make_float2(ew, bx);
    }
}

// ------------------------- 7. warp-autonomous smem tree scan ----------------
// 512 threads: all 16 warps stream bulk in/out; warps 0-5 own one channel
// each for the warp-synchronous level loops.
#define SCAN_SMEM (CPB*LL*4*2 + LL*4 + (LL+2)*4)
__global__ void __launch_bounds__(512) k_scan()
{
    extern __shared__ unsigned char sms[];
    float* acc_all = (float*)sms;                      // [CPB][LL]
    float* ew_all  = (float*)(sms + CPB*LL*4);         // [CPB][LL]
    int*   parp_s  = (int*)(sms + CPB*LL*8);           // [LL]
    int*   lvl_s   = (int*)(sms + CPB*LL*8 + LL*4);    // [nl+1]

    int b  = blockIdx.y;
    int c0 = blockIdx.x * CPB;
    int tid = threadIdx.x;
    int warp = tid >> 5, lane = tid & 31;
    int nl = g_numlev[b];
    const int* revp = g_revert + b * (LL + 2);
    const int* bfs  = g_bfs + b * LL;
    const float2* eu = g_eu + (size_t)(b * LL) * DI;
    float* agout = g_ag + (size_t)(b * LL) * DI;

    for (int i = tid; i < LL; i += 512) parp_s[i] = g_parp[b * LL + i];
    for (int i = tid; i <= nl; i += 512) lvl_s[i] = g_lvl[b * (LL + 2) + i];
    for (int idx = tid; idx < LL * CPB; idx += 512) {
        int pos = idx / CPB, cc = idx % CPB;
        float2 v = eu[(size_t)bfs[pos] * DI + c0 + cc];
        ew_all[cc * LL + pos]  = v.x;
        acc_all[cc * LL + pos] = v.y;
    }
    __syncthreads();

    if (warp < CPB) {
        float* A = acc_all + warp * LL;
        float* E = ew_all + warp * LL;
        // up-sweep: children accumulate into parents
        for (int lev = nl - 1; lev >= 1; --lev) {
            int ls = lvl_s[lev], le = lvl_s[lev + 1];
            for (int pos = ls + lane; pos < le; pos += 32)
                atomicAdd(&A[parp_s[pos]], E[pos] * A[pos]);
            __syncwarp();
        }
        // down-sweep: in-place (parents already final)
        for (int lev = 0; lev < nl; ++lev) {
            int ls = lvl_s[lev], le = lvl_s[lev + 1];
            int rev = revp[lev];
            for (int pos = ls + lane; pos < le; pos += 32) {
                float u = A[pos];
                float val = u;
                if (lev > 0) {
                    float w = E[pos];
                    val = u + w * (A[parp_s[pos]] - w * u);
                    if (pos == rev) val = u;
                }
                A[pos] = val;
            }
            __syncwarp();
        }
    }
    __syncthreads();

    for (int idx = tid; idx < LL * CPB; idx += 512) {
        int pos = idx / CPB, cc = idx % CPB;
        agout[(size_t)pos * DI + c0 + cc] = acc_all[cc * LL + pos];
    }
}

// ------------------------- 8. fused LN -> *Cs -> +Ds*xs -> LN -> *z --------
__global__ void __launch_bounds__(256) k_fuse(const float* __restrict__ hg,
                                              const float* __restrict__ hb,
                                              const float* __restrict__ og,
                                              const float* __restrict__ ob,
                                              const float* __restrict__ Ds)
{
    int warp = (blockIdx.x * 256 + threadIdx.x) >> 5;
    int lane = threadIdx.x & 31;
    if (warp >= BB * LL) return;
    int b = warp >> 12;
    int pos = g_pos[warp];
    const float* hrow = g_ag + ((size_t)(b * LL) + pos) * DI;
    const float* xrow = g_xst + (size_t)warp * DI;

    float v[6];
    #pragma unroll
    for (int j = 0; j < 6; j++) v[j] = hrow[lane + 32 * j];

    float s = 0.f;
    #pragma unroll
    for (int j = 0; j < 6; j++) s += v[j];
    float mu = warpsum(s) * (1.f / 192.f);
    float q = 0.f;
    #pragma unroll
    for (int j = 0; j < 6; j++) { float d = v[j] - mu; q += d * d; }
    float inv = rsqrtf(warpsum(q) * (1.f / 192.f) + 1e-5f);

    float Cv = g_Csv[warp];
    float y[6];
    #pragma unroll
    for (int j = 0; j < 6; j++) {
        int c = lane + 32 * j;
        float hn = (v[j] - mu) * inv * hg[c] + hb[c];
        y[j] = hn * Cv + Ds[c] * xrow[c];
    }

    s = 0.f;
    #pragma unroll
    for (int j = 0; j < 6; j++) s += y[j];
    float mu2 = warpsum(s) * (1.f / 192.f);
    q = 0.f;
    #pragma unroll
    for (int j = 0; j < 6; j++) { float d = y[j] - mu2; q += d * d; }
    float inv2 = rsqrtf(warpsum(q) * (1.f / 192.f) + 1e-5f);

    #pragma unroll
    for (int j = 0; j < 6; j++) {
        int c = lane + 32 * j;
        float y2 = (y[j] - mu2) * inv2 * og[c] + ob[c];
        g_yz[(size_t)warp * DI + c] = y2 * g_z[(size_t)warp * DI + c];
    }
}

// ------------------------- 9. out_proj GEMM --------------------------------
__global__ void __launch_bounds__(256) k_gemm_out(const float* __restrict__ W,
                                                  float* __restrict__ out)
{
    __shared__ float sA[64][33];
    __shared__ float sW[64][33];
    int bm = blockIdx.y * 64, bn = blockIdx.x * 64;
    int tid = threadIdx.x;
    int tx = tid & 15, ty = tid >> 4;
    float acc[4][4] = {};
    for (int k0 = 0; k0 < 192; k0 += 32) {
        for (int t = tid; t < 512; t += 256) {
            int r = t >> 3, kq = t & 7;
            float4 va = *(const float4*)(g_yz + (size_t)(bm + r) * 192 + k0 + kq * 4);
            sA[r][kq*4+0] = va.x; sA[r][kq*4+1] = va.y;
            sA[r][kq*4+2] = va.z; sA[r][kq*4+3] = va.w;
            float4 vw;
            if (bn + r < 96)
                vw = *(const float4*)(W + (size_t)(bn + r) * 192 + k0 + kq * 4);
            else
                vw = make_float4(0.f, 0.f, 0.f, 0.f);
            sW[r][kq*4+0] = vw.x; sW[r][kq*4+1] = vw.y;
            sW[r][kq*4+2] = vw.z; sW[r][kq*4+3] = vw.w;
        }
        __syncthreads();
        #pragma unroll
        for (int k = 0; k < 32; k++) {
            float a[4], bv[4];
            #pragma unroll
            for (int i = 0; i < 4; i++) { a[i] = sA[ty*4+i][k]; bv[i] = sW[tx*4+i][k]; }
            #pragma unroll
            for (int i = 0; i < 4; i++)
                #pragma unroll
                for (int j = 0; j < 4; j++)
                    acc[i][j] += a[i] * bv[j];
        }
        __syncthreads();
    }
    #pragma unroll
    for (int i = 0; i < 4; i++) {
        int m = bm + ty * 4 + i;
        #pragma unroll
        for (int j = 0; j < 4; j++) {
            int n = bn + tx * 4 + j;
            if (n < 96) out[(size_t)m * 96 + n] = acc[i][j];
        }
    }
}

// ------------------------- launch ------------------------------------------
extern "C" void kernel_launch(void* const* d_in, const int* in_sizes, int n_in,
                              void* d_out, int out_size)
{
    const float* x    = (const float*)d_in[0];
    const float* inw  = (const float*)d_in[1];
    const float* cw   = (const float*)d_in[2];
    const float* cb   = (const float*)d_in[3];
    const float* xpw  = (const float*)d_in[4];
    const float* dtw  = (const float*)d_in[5];
    const float* dtb  = (const float*)d_in[6];
    const float* alog = (const float*)d_in[7];
    const float* Dsp  = (const float*)d_in[8];
    const float* hg   = (const float*)d_in[9];
    const float* hbp  = (const float*)d_in[10];
    const float* og   = (const float*)d_in[11];
    const float* obp  = (const float*)d_in[12];
    const float* opw  = (const float*)d_in[13];
    float* out = (float*)d_out;

    // one-time stream/event setup (runs on the uncaptured correctness call;
    // the capture call replays identical launches/events every time)
    static cudaStream_t sTree = nullptr;
    static cudaEvent_t evFork = nullptr, evTree = nullptr;
    if (sTree == nullptr) {
        cudaStreamCreateWithFlags(&sTree, cudaStreamNonBlocking);
        cudaEventCreateWithFlags(&evFork, cudaEventDisableTiming);
        cudaEventCreateWithFlags(&evTree, cudaEventDisableTiming);
    }

    k_gemm_in<<<dim3(6, 512), 256>>>(x, inw);
    k_conv<<<dim3(128, 6, 8), dim3(32, 8)>>>(cw, cb);

    // fork: tree chain (8-SM kernels) overlaps the dense ssm pass
    cudaEventRecord(evFork, 0);
    cudaStreamWaitEvent(sTree, evFork, 0);
    k_norm<<<(BB * LL + 255) / 256, 256, 0, sTree>>>();
    k_edge<<<(BB * NE + 255) / 256, 256, 0, sTree>>>();
    cudaFuncSetAttribute(k_boruvka, cudaFuncAttributeMaxDynamicSharedMemorySize, BORSMEM);
    k_boruvka<<<BB, 1024, BORSMEM, sTree>>>();
    k_revert<<<1, 256, 0, sTree>>>();
    cudaEventRecord(evTree, sTree);

    k_ssm<<<(BB * LL * 32 + 255) / 256, 256>>>(xpw, dtw, dtb, alog);

    cudaStreamWaitEvent(0, evTree, 0);
    cudaFuncSetAttribute(k_scan, cudaFuncAttributeMaxDynamicSharedMemorySize, SCAN_SMEM);
    k_scan<<<dim3(DI / CPB, BB), 512, SCAN_SMEM>>>();

    k_fuse<<<(BB * LL * 32 + 255) / 256, 256>>>(hg, hbp, og, obp, Dsp);
    k_gemm_out<<<dim3(2, 512), 256>>>(opw, out);
}

// round 10
// speedup vs baseline: 5.2813x; 1.0533x over previous
#include <cuda_runtime.h>
#include <math.h>

#define BB 8
#define HH 64
#define WW 64
#define LL 4096
#define DM 96
#define DI 192
#define DR 6
#define NE 8064
#define CPB 6   // channels per scan block (1 per warp)

// ------------------------- device scratch (static, no mallocs) -------------
static __device__ __align__(16) float  g_z[BB*LL*DI];      // (b,l,c) silu(z)
static __device__ __align__(16) float  g_xcpre[BB*DI*LL];  // (b,c,l) pre-conv
static __device__ __align__(16) float  g_xst[BB*LL*DI];    // (b,l,c)
static __device__ double g_rinv[BB*LL];                    // 1/max(norm,1e-8)
static __device__ unsigned long long   g_keys[BB*NE];      // packed (key|idx)
static __device__ int    g_pos[BB*LL];                     // node -> bfs position
static __device__ int    g_bfs[BB*LL];                     // pos  -> node
static __device__ int    g_parp[BB*LL];                    // pos  -> parent pos
static __device__ int    g_lvl[BB*(LL+2)];
static __device__ int    g_lvlcnt[BB*(LL+2)];
static __device__ int    g_lvlmin[BB*(LL+2)];
static __device__ int    g_revert[BB*(LL+2)];              // pos (or -1) per level
static __device__ int    g_numlev[BB];
static __device__ float  g_Csv[BB*LL];
static __device__ __align__(16) float2 g_eu[BB*LL*DI];     // node-ordered (ew, up)
static __device__ __align__(16) float  g_ag[BB*LL*DI];     // pos-ordered aggr
static __device__ __align__(16) float  g_yz[BB*LL*DI];     // (b,l,c)

// ------------------------- helpers -----------------------------------------
__device__ __forceinline__ float siluf(float x){ return x / (1.f + expf(-x)); }
__device__ __forceinline__ float softplusf(float x){
    return fmaxf(x, 0.f) + log1pf(expf(-fabsf(x)));
}
__device__ __forceinline__ float warpsum(float v){
    #pragma unroll
    for (int o = 16; o > 0; o >>= 1) v += __shfl_xor_sync(0xFFFFFFFFu, v, o);
    return v;
}
__device__ __forceinline__ void edge_uv(int e, int& u, int& v){
    if (e < 4032) { int r = e / 63, c = e % 63; u = r * 64 + c; v = u + 1; }
    else          { int j = e - 4032; u = j; v = j + 64; }
}
// Knuth TwoSum (no ordering assumption)
__device__ __forceinline__ void two_sum(float a, float b, float& s, float& e){
    s = a + b;
    float bv = s - a;
    e = (a - (s - bv)) + (b - bv);
}
// float-float dot: lane accumulates 6 terms with TwoProd+TwoSum, then
// warp-reduces the (hi,lo) pair. Error ~2^-45 relative — far below the
// 2^-39 key truncation.
__device__ __forceinline__ double ff_dot_reduce(const float* __restrict__ a,
                                                const float* __restrict__ b,
                                                int lane){
    float hi = 0.f, lo = 0.f;
    #pragma unroll
    for (int j = 0; j < 6; j++) {
        float x = a[lane + 32 * j], y = b[lane + 32 * j];
        float p = x * y;
        float pe = fmaf(x, y, -p);
        float s, e;
        two_sum(hi, p, s, e);
        hi = s;
        lo += e + pe;
    }
    #pragma unroll
    for (int o = 16; o > 0; o >>= 1) {
        float oh = __shfl_xor_sync(0xFFFFFFFFu, hi, o);
        float ol = __shfl_xor_sync(0xFFFFFFFFu, lo, o);
        float s, e;
        two_sum(hi, oh, s, e);
        hi = s;
        lo += e + ol;
    }
    return (double)hi + (double)lo;
}
// order-preserving double -> u64 map (handles sign)
__device__ __forceinline__ unsigned long long key_map(double t){
    unsigned long long x = (unsigned long long)__double_as_longlong(t);
    return (x >> 63) ? ~x : (x | 0x8000000000000000ULL);
}

// ------------------------- 1. in_proj GEMM + split/silu (coalesced out) ----
__global__ void __launch_bounds__(256) k_gemm_in(const float* __restrict__ A,
                                                 const float* __restrict__ W)
{
    __shared__ float sA[64][33];
    __shared__ float sW[64][33];
    __shared__ float st[64][68];
    int bm = blockIdx.y * 64, bn = blockIdx.x * 64;
    int tid = threadIdx.x;
    int tx = tid & 15, ty = tid >> 4;
    float acc[4][4] = {};
    for (int k0 = 0; k0 < 96; k0 += 32) {
        for (int t = tid; t < 512; t += 256) {
            int r = t >> 3, kq = t & 7;
            float4 va = *(const float4*)(A + (size_t)(bm + r) * 96 + k0 + kq * 4);
            sA[r][kq*4+0] = va.x; sA[r][kq*4+1] = va.y;
            sA[r][kq*4+2] = va.z; sA[r][kq*4+3] = va.w;
            float4 vw = *(const float4*)(W + (size_t)(bn + r) * 96 + k0 + kq * 4);
            sW[r][kq*4+0] = vw.x; sW[r][kq*4+1] = vw.y;
            sW[r][kq*4+2] = vw.z; sW[r][kq*4+3] = vw.w;
        }
        __syncthreads();
        #pragma unroll
        for (int k = 0; k < 32; k++) {
            float a[4], b[4];
            #pragma unroll
            for (int i = 0; i < 4; i++) { a[i] = sA[ty*4+i][k]; b[i] = sW[tx*4+i][k]; }
            #pragma unroll
            for (int i = 0; i < 4; i++)
                #pragma unroll
                for (int j = 0; j < 4; j++)
                    acc[i][j] += a[i] * b[j];
        }
        __syncthreads();
    }
    int b = bm >> 12, l0 = bm & 4095;
    if (bn < DI) {
        #pragma unroll
        for (int i = 0; i < 4; i++)
            #pragma unroll
            for (int j = 0; j < 4; j++)
                st[tx*4+j][ty*4+i] = acc[i][j];
        __syncthreads();
        #pragma unroll
        for (int pass = 0; pass < 4; pass++) {
            int nn = pass * 16 + (tid >> 4);
            int mm = (tid & 15) * 4;
            float4 v = *(float4*)&st[nn][mm];
            *(float4*)&g_xcpre[((size_t)(b * DI + bn + nn)) * LL + l0 + mm] = v;
        }
    } else {
        int cb = bn - DI;
        #pragma unroll
        for (int i = 0; i < 4; i++)
            #pragma unroll
            for (int j = 0; j < 4; j++)
                st[ty*4+i][tx*4+j] = acc[i][j];
        __syncthreads();
        #pragma unroll
        for (int pass = 0; pass < 4; pass++) {
            int mm = pass * 16 + (tid >> 4);
            int nn = (tid & 15) * 4;
            float4 v = *(float4*)&st[mm][nn];
            v.x = siluf(v.x); v.y = siluf(v.y); v.z = siluf(v.z); v.w = siluf(v.w);
            *(float4*)&g_z[((size_t)(bm + mm)) * DI + cb + nn] = v;
        }
    }
}

// ------------------------- 2. depthwise conv + silu -> xst only ------------
__global__ void __launch_bounds__(256) k_conv(const float* __restrict__ cw,
                                              const float* __restrict__ cb)
{
    __shared__ float t[32][33];
    int b  = blockIdx.z;
    int c0 = blockIdx.y * 32;
    int l0 = blockIdx.x * 32;
    int tx = threadIdx.x, ty = threadIdx.y;   // 32 x 8
    int l = l0 + tx;
    int h = l >> 6, w = l & 63;
    #pragma unroll
    for (int k = 0; k < 4; k++) {
        int c = c0 + ty + 8 * k;
        const float* src = g_xcpre + (size_t)(b * DI + c) * LL;
        float acc = cb[c];
        #pragma unroll
        for (int ky = 0; ky < 3; ky++) {
            int hy = h + ky - 1;
            if ((unsigned)hy >= 64u) continue;
            #pragma unroll
            for (int kx = 0; kx < 3; kx++) {
                int wx = w + kx - 1;
                if ((unsigned)wx >= 64u) continue;
                acc += src[hy * 64 + wx] * cw[c * 9 + ky * 3 + kx];
            }
        }
        t[ty + 8 * k][tx] = siluf(acc);
    }
    __syncthreads();
    #pragma unroll
    for (int k = 0; k < 4; k++)
        g_xst[((size_t)(b * LL + l0 + ty + 8 * k)) * DI + c0 + tx] = t[tx][ty + 8 * k];
}

// ------------------------- 3. reciprocal norms (warp/node, float-float) ----
__global__ void __launch_bounds__(256) k_norm()
{
    int gid = (blockIdx.x * 256 + threadIdx.x) >> 5;   // b*L + l
    int lane = threadIdx.x & 31;
    if (gid >= BB * LL) return;
    const float* xrow = g_xst + (size_t)gid * DI;
    double s = ff_dot_reduce(xrow, xrow, lane);
    if (lane == 0) {
        double nrm = sqrt(s);
        double den = nrm > 1e-8 ? nrm : 1e-8;
        g_rinv[gid] = 1.0 / den;
    }
}

// ------------------------- 4. edge keys (warp/edge, float-float, NO exp) ---
// Order of w = exp(-dot) equals order of -dot: skip exp, map the (possibly
// negative) double through the monotone double->u64 map, truncate 13 bits,
// pack the edge index for the stable tie-break.
__global__ void __launch_bounds__(256) k_edge()
{
    int gid = (blockIdx.x * 256 + threadIdx.x) >> 5;
    int lane = threadIdx.x & 31;
    if (gid >= BB * NE) return;
    int b = gid / NE, e = gid % NE;
    int u, v;
    edge_uv(e, u, v);
    const float* xu = g_xst + ((size_t)(b * LL) + u) * DI;
    const float* xv = g_xst + ((size_t)(b * LL) + v) * DI;
    double s = ff_dot_reduce(xu, xv, lane);
    if (lane == 0) {
        double t = -(s * g_rinv[b * LL + u] * g_rinv[b * LL + v]);
        g_keys[gid] = (key_map(t) & ~0x1FFFULL) | (unsigned long long)e;
    }
}

// ------------------------- 5. Boruvka MST + warp BFS (block/batch) ---------
#define O_KEY  0
#define O_COMP 64512
#define O_PTR  80896
#define O_BEST 97280
#define O_FLAG 130048
#define BORSMEM 131072

__global__ void __launch_bounds__(1024, 1) k_boruvka()
{
    extern __shared__ unsigned char sm[];
    unsigned long long* skey = (unsigned long long*)(sm + O_KEY);
    unsigned int*       comp = (unsigned int*)(sm + O_COMP);
    unsigned int*       ptrA = (unsigned int*)(sm + O_PTR);
    unsigned long long* best = (unsigned long long*)(sm + O_BEST);
    unsigned int*       flag = (unsigned int*)(sm + O_FLAG);
    __shared__ int s_done, s_chg, s_nl, s_qt;

    int b = blockIdx.x;
    int tid = threadIdx.x;

    for (int e = tid; e < NE; e += 1024) skey[e] = g_keys[b * NE + e];
    for (int i = tid; i < LL; i += 1024) comp[i] = (unsigned)i;
    if (tid < 256) flag[tid] = 0;
    __syncthreads();

    for (int round = 0; round < 13; round++) {
        for (int i = tid; i < LL; i += 1024) best[i] = ~0ULL;
        if (tid == 0) s_done = 1;
        __syncthreads();

        for (int e = tid; e < NE; e += 1024) {
            int u, v; edge_uv(e, u, v);
            unsigned cu = comp[u], cv = comp[v];
            if (cu != cv) {
                unsigned long long k = skey[e];
                atomicMin(&best[cu], k);
                atomicMin(&best[cv], k);
            }
        }
        __syncthreads();
        for (int c = tid; c < LL; c += 1024) {
            unsigned long long bk = best[c];
            if (bk != ~0ULL) {
                int e = (int)(bk & 8191ULL);
                atomicOr(&flag[e >> 5], 1u << (e & 31));
                int u, v; edge_uv(e, u, v);
                unsigned cu = comp[u], cv = comp[v];
                ptrA[c] = (cu == (unsigned)c) ? cv : cu;
                s_done = 0;
            } else {
                ptrA[c] = (unsigned)c;
            }
        }
        __syncthreads();
        if (s_done) break;
        for (int c = tid; c < LL; c += 1024) {
            unsigned p = ptrA[c];
            if (p != (unsigned)c && ptrA[p] == (unsigned)c && (unsigned)c < p)
                ptrA[c] = (unsigned)c;
        }
        __syncthreads();
        for (int it = 0; it < 13; it++) {
            if (tid == 0) s_chg = 0;
            __syncthreads();
            for (int c = tid; c < LL; c += 1024) {
                unsigned p = ptrA[c];
                unsigned g = ptrA[p];
                if (p != g) { ptrA[c] = g; s_chg = 1; }
            }
            __syncthreads();
            if (!s_chg) break;
        }
        for (int i = tid; i < LL; i += 1024) comp[i] = ptrA[comp[i]];
        __syncthreads();
    }

    // ---- warp-synchronous BFS from node 0 (warp 0 only) ----
    unsigned int* dep = (unsigned int*)(sm + O_KEY);
    unsigned int* par = (unsigned int*)(sm + O_KEY + 16384);
    unsigned int* q   = (unsigned int*)(sm + O_KEY + 32768);
    for (int i = tid; i < LL; i += 1024) dep[i] = 0xFFFFFFFFu;
    __syncthreads();
    if (tid == 0) { dep[0] = 0; par[0] = 0; q[0] = 0; s_qt = 1; }
    __syncthreads();

    if (tid < 32) {
        int qh = 0, qt = 1;
        while (qh < qt) {
            for (int i = qh + tid; i < qt; i += 32) {
                int n = (int)q[i];
                int h = n >> 6, w = n & 63;
                unsigned d = dep[n] + 1;
                if (w < 63) { int e = h * 63 + w; int m = n + 1;
                    if ((flag[e >> 5] >> (e & 31) & 1u) && dep[m] == 0xFFFFFFFFu) {
                        dep[m] = d; par[m] = (unsigned)n; q[atomicAdd(&s_qt, 1)] = (unsigned)m; } }
                if (w > 0)  { int e = h * 63 + w - 1; int m = n - 1;
                    if ((flag[e >> 5] >> (e & 31) & 1u) && dep[m] == 0xFFFFFFFFu) {
                        dep[m] = d; par[m] = (unsigned)n; q[atomicAdd(&s_qt, 1)] = (unsigned)m; } }
                if (h < 63) { int e = 4032 + n; int m = n + 64;
                    if ((flag[e >> 5] >> (e & 31) & 1u) && dep[m] == 0xFFFFFFFFu) {
                        dep[m] = d; par[m] = (unsigned)n; q[atomicAdd(&s_qt, 1)] = (unsigned)m; } }
                if (h > 0)  { int e = 4032 + n - 64; int m = n - 64;
                    if ((flag[e >> 5] >> (e & 31) & 1u) && dep[m] == 0xFFFFFFFFu) {
                        dep[m] = d; par[m] = (unsigned)n; q[atomicAdd(&s_qt, 1)] = (unsigned)m; } }
            }
            __syncwarp();
            qh = qt;
            qt = *(volatile int*)&s_qt;
            __syncwarp();
        }
    }
    __syncthreads();

    // ---- levels + positions ----
    unsigned int* lvlcnt = (unsigned int*)(sm + O_COMP);
    unsigned int* lvlmin = (unsigned int*)(sm + O_PTR);
    unsigned int* cur    = (unsigned int*)(sm + O_BEST);
    unsigned int* posA   = (unsigned int*)(sm + O_BEST + 16384);
    for (int i = tid; i < LL; i += 1024) { lvlcnt[i] = 0; lvlmin[i] = 0x7FFFFFFFu; }
    if (tid == 0) s_nl = 0;
    __syncthreads();
    for (int i = tid; i < LL; i += 1024) {
        unsigned d = dep[i];
        atomicAdd(&lvlcnt[d], 1u);
        atomicMin(&lvlmin[d], (unsigned)i);
        atomicMax(&s_nl, (int)d);
    }
    __syncthreads();
    if (tid == 0) {
        int nl = s_nl + 1;
        g_numlev[b] = nl;
        int run = 0;
        for (int d = 0; d < nl; d++) {
            g_lvl[b * (LL + 2) + d] = run;
            g_lvlcnt[b * (LL + 2) + d] = (int)lvlcnt[d];
            g_lvlmin[b * (LL + 2) + d] = (int)lvlmin[d];
            cur[d] = (unsigned)run;
            run += (int)lvlcnt[d];
        }
        g_lvl[b * (LL + 2) + nl] = LL;
    }
    __syncthreads();
    for (int i = tid; i < LL; i += 1024)
        posA[i] = atomicAdd(&cur[dep[i]], 1u);
    __syncthreads();
    for (int i = tid; i < LL; i += 1024) {
        unsigned p = posA[i];
        g_pos[b * LL + i] = (int)p;
        g_bfs[b * LL + p] = i;
        g_parp[b * LL + p] = (int)posA[par[i]];
    }
}

// ------------------------- 5b. padded-scatter revert flags (as pos) --------
__global__ void k_revert()
{
    __shared__ int nlmax;
    if (threadIdx.x == 0) {
        int m = 0;
        for (int b = 0; b < BB; b++) m = max(m, g_numlev[b]);
        nlmax = m;
    }
    __syncthreads();
    for (int d = threadIdx.x; d < nlmax; d += blockDim.x) {
        int cnt[BB];
        int md = 0;
        for (int b = 0; b < BB; b++) {
            int c = (d < g_numlev[b]) ? g_lvlcnt[b * (LL + 2) + d] : 0;
            cnt[b] = c;
            md = max(md, c);
        }
        for (int b = 0; b < BB; b++) {
            int r = -1;
            if (d > 0 && cnt[b] > 0 && cnt[b] < md)
                r = g_pos[b * LL + g_lvlmin[b * (LL + 2) + d]];
            g_revert[b * (LL + 2) + d] = r;
        }
    }
}

// ------------------------- 6. fused x_dbl + dts/deltaA/BX (node-ordered) ---
__global__ void __launch_bounds__(256) k_ssm(const float* __restrict__ XW,
                                             const float* __restrict__ dtW,
                                             const float* __restrict__ dtB,
                                             const float* __restrict__ Alog)
{
    int gw = (blockIdx.x * 256 + threadIdx.x) >> 5;   // b*LL + l
    int lane = threadIdx.x & 31;
    if (gw >= BB * LL) return;
    const float* xrow = g_xst + (size_t)gw * DI;

    float xv[6];
    #pragma unroll
    for (int j = 0; j < 6; j++) xv[j] = xrow[lane + 32 * j];

    float acc[8];
    #pragma unroll
    for (int c8 = 0; c8 < 8; c8++) {
        float s = 0.f;
        #pragma unroll
        for (int j = 0; j < 6; j++) s += xv[j] * XW[c8 * DI + lane + 32 * j];
        acc[c8] = warpsum(s);
    }
    float Bsv = acc[6];
    if (lane == 0) g_Csv[gw] = acc[7];

    float2* eurow = g_eu + (size_t)gw * DI;
    #pragma unroll
    for (int j = 0; j < 6; j++) {
        int d = lane + 32 * j;
        float s = dtB[d];
        #pragma unroll
        for (int r = 0; r < DR; r++) s += acc[r] * dtW[d * DR + r];
        float dt = softplusf(s);
        float ew = expf(-expf(Alog[d]) * dt);
        float bx = dt * Bsv * xv[j];
        eurow[d] = make_float2(ew, bx);
    }
}

// ------------------------- 7. warp-autonomous smem tree scan ----------------
#define SCAN_SMEM (CPB*LL*4*2 + LL*4 + (LL+2)*4)
__global__ void __launch_bounds__(512) k_scan()
{
    extern __shared__ unsigned char sms[];
    float* acc_all = (float*)sms;                      // [CPB][LL]
    float* ew_all  = (float*)(sms + CPB*LL*4);         // [CPB][LL]
    int*   parp_s  = (int*)(sms + CPB*LL*8);           // [LL]
    int*   lvl_s   = (int*)(sms + CPB*LL*8 + LL*4);    // [nl+1]

    int b  = blockIdx.y;
    int c0 = blockIdx.x * CPB;
    int tid = threadIdx.x;
    int warp = tid >> 5, lane = tid & 31;
    int nl = g_numlev[b];
    const int* revp = g_revert + b * (LL + 2);
    const int* bfs  = g_bfs + b * LL;
    const float2* eu = g_eu + (size_t)(b * LL) * DI;
    float* agout = g_ag + (size_t)(b * LL) * DI;

    for (int i = tid; i < LL; i += 512) parp_s[i] = g_parp[b * LL + i];
    for (int i = tid; i <= nl; i += 512) lvl_s[i] = g_lvl[b * (LL + 2) + i];
    for (int idx = tid; idx < LL * CPB; idx += 512) {
        int pos = idx / CPB, cc = idx % CPB;
        float2 v = eu[(size_t)bfs[pos] * DI + c0 + cc];
        ew_all[cc * LL + pos]  = v.x;
        acc_all[cc * LL + pos] = v.y;
    }
    __syncthreads();

    if (warp < CPB) {
        float* A = acc_all + warp * LL;
        float* E = ew_all + warp * LL;
        for (int lev = nl - 1; lev >= 1; --lev) {
            int ls = lvl_s[lev], le = lvl_s[lev + 1];
            for (int pos = ls + lane; pos < le; pos += 32)
                atomicAdd(&A[parp_s[pos]], E[pos] * A[pos]);
            __syncwarp();
        }
        for (int lev = 0; lev < nl; ++lev) {
            int ls = lvl_s[lev], le = lvl_s[lev + 1];
            int rev = revp[lev];
            for (int pos = ls + lane; pos < le; pos += 32) {
                float u = A[pos];
                float val = u;
                if (lev > 0) {
                    float w = E[pos];
                    val = u + w * (A[parp_s[pos]] - w * u);
                    if (pos == rev) val = u;
                }
                A[pos] = val;
            }
            __syncwarp();
        }
    }
    __syncthreads();

    for (int idx = tid; idx < LL * CPB; idx += 512) {
        int pos = idx / CPB, cc = idx % CPB;
        agout[(size_t)pos * DI + c0 + cc] = acc_all[cc * LL + pos];
    }
}

// ------------------------- 8. fused LN -> *Cs -> +Ds*xs -> LN -> *z --------
__global__ void __launch_bounds__(256) k_fuse(const float* __restrict__ hg,
                                              const float* __restrict__ hb,
                                              const float* __restrict__ og,
                                              const float* __restrict__ ob,
                                              const float* __restrict__ Ds)
{
    int warp = (blockIdx.x * 256 + threadIdx.x) >> 5;
    int lane = threadIdx.x & 31;
    if (warp >= BB * LL) return;
    int b = warp >> 12;
    int pos = g_pos[warp];
    const float* hrow = g_ag + ((size_t)(b * LL) + pos) * DI;
    const float* xrow = g_xst + (size_t)warp * DI;

    float v[6];
    #pragma unroll
    for (int j = 0; j < 6; j++) v[j] = hrow[lane + 32 * j];

    float s = 0.f;
    #pragma unroll
    for (int j = 0; j < 6; j++) s += v[j];
    float mu = warpsum(s) * (1.f / 192.f);
    float q = 0.f;
    #pragma unroll
    for (int j = 0; j < 6; j++) { float d = v[j] - mu; q += d * d; }
    float inv = rsqrtf(warpsum(q) * (1.f / 192.f) + 1e-5f);

    float Cv = g_Csv[warp];
    float y[6];
    #pragma unroll
    for (int j = 0; j < 6; j++) {
        int c = lane + 32 * j;
        float hn = (v[j] - mu) * inv * hg[c] + hb[c];
        y[j] = hn * Cv + Ds[c] * xrow[c];
    }

    s = 0.f;
    #pragma unroll
    for (int j = 0; j < 6; j++) s += y[j];
    float mu2 = warpsum(s) * (1.f / 192.f);
    q = 0.f;
    #pragma unroll
    for (int j = 0; j < 6; j++) { float d = y[j] - mu2; q += d * d; }
    float inv2 = rsqrtf(warpsum(q) * (1.f / 192.f) + 1e-5f);

    #pragma unroll
    for (int j = 0; j < 6; j++) {
        int c = lane + 32 * j;
        float y2 = (y[j] - mu2) * inv2 * og[c] + ob[c];
        g_yz[(size_t)warp * DI + c] = y2 * g_z[(size_t)warp * DI + c];
    }
}

// ------------------------- 9. out_proj GEMM --------------------------------
__global__ void __launch_bounds__(256) k_gemm_out(const float* __restrict__ W,
                                                  float* __restrict__ out)
{
    __shared__ float sA[64][33];
    __shared__ float sW[64][33];
    int bm = blockIdx.y * 64, bn = blockIdx.x * 64;
    int tid = threadIdx.x;
    int tx = tid & 15, ty = tid >> 4;
    float acc[4][4] = {};
    for (int k0 = 0; k0 < 192; k0 += 32) {
        for (int t = tid; t < 512; t += 256) {
            int r = t >> 3, kq = t & 7;
            float4 va = *(const float4*)(g_yz + (size_t)(bm + r) * 192 + k0 + kq * 4);
            sA[r][kq*4+0] = va.x; sA[r][kq*4+1] = va.y;
            sA[r][kq*4+2] = va.z; sA[r][kq*4+3] = va.w;
            float4 vw;
            if (bn + r < 96)
                vw = *(const float4*)(W + (size_t)(bn + r) * 192 + k0 + kq * 4);
            else
                vw = make_float4(0.f, 0.f, 0.f, 0.f);
            sW[r][kq*4+0] = vw.x; sW[r][kq*4+1] = vw.y;
            sW[r][kq*4+2] = vw.z; sW[r][kq*4+3] = vw.w;
        }
        __syncthreads();
        #pragma unroll
        for (int k = 0; k < 32; k++) {
            float a[4], bv[4];
            #pragma unroll
            for (int i = 0; i < 4; i++) { a[i] = sA[ty*4+i][k]; bv[i] = sW[tx*4+i][k]; }
            #pragma unroll
            for (int i = 0; i < 4; i++)
                #pragma unroll
                for (int j = 0; j < 4; j++)
                    acc[i][j] += a[i] * bv[j];
        }
        __syncthreads();
    }
    #pragma unroll
    for (int i = 0; i < 4; i++) {
        int m = bm + ty * 4 + i;
        #pragma unroll
        for (int j = 0; j < 4; j++) {
            int n = bn + tx * 4 + j;
            if (n < 96) out[(size_t)m * 96 + n] = acc[i][j];
        }
    }
}

// ------------------------- launch ------------------------------------------
extern "C" void kernel_launch(void* const* d_in, const int* in_sizes, int n_in,
                              void* d_out, int out_size)
{
    const float* x    = (const float*)d_in[0];
    const float* inw  = (const float*)d_in[1];
    const float* cw   = (const float*)d_in[2];
    const float* cb   = (const float*)d_in[3];
    const float* xpw  = (const float*)d_in[4];
    const float* dtw  = (const float*)d_in[5];
    const float* dtb  = (const float*)d_in[6];
    const float* alog = (const float*)d_in[7];
    const float* Dsp  = (const float*)d_in[8];
    const float* hg   = (const float*)d_in[9];
    const float* hbp  = (const float*)d_in[10];
    const float* og   = (const float*)d_in[11];
    const float* obp  = (const float*)d_in[12];
    const float* opw  = (const float*)d_in[13];
    float* out = (float*)d_out;

    static cudaStream_t sTree = nullptr;
    static cudaEvent_t evFork = nullptr, evTree = nullptr;
    if (sTree == nullptr) {
        cudaStreamCreateWithFlags(&sTree, cudaStreamNonBlocking);
        cudaEventCreateWithFlags(&evFork, cudaEventDisableTiming);
        cudaEventCreateWithFlags(&evTree, cudaEventDisableTiming);
    }

    k_gemm_in<<<dim3(6, 512), 256>>>(x, inw);
    k_conv<<<dim3(128, 6, 8), dim3(32, 8)>>>(cw, cb);

    // fork: tree chain overlaps the dense ssm pass
    cudaEventRecord(evFork, 0);
    cudaStreamWaitEvent(sTree, evFork, 0);
    k_norm<<<(BB * LL * 32 + 255) / 256, 256, 0, sTree>>>();
    k_edge<<<(BB * NE * 32 + 255) / 256, 256, 0, sTree>>>();
    cudaFuncSetAttribute(k_boruvka, cudaFuncAttributeMaxDynamicSharedMemorySize, BORSMEM);
    k_boruvka<<<BB, 1024, BORSMEM, sTree>>>();
    k_revert<<<1, 256, 0, sTree>>>();
    cudaEventRecord(evTree, sTree);

    k_ssm<<<(BB * LL * 32 + 255) / 256, 256>>>(xpw, dtw, dtb, alog);

    cudaStreamWaitEvent(0, evTree, 0);
    cudaFuncSetAttribute(k_scan, cudaFuncAttributeMaxDynamicSharedMemorySize, SCAN_SMEM);
    k_scan<<<dim3(DI / CPB, BB), 512, SCAN_SMEM>>>();

    k_fuse<<<(BB * LL * 32 + 255) / 256, 256>>>(hg, hbp, og, obp, Dsp);
    k_gemm_out<<<dim3(2, 512), 256>>>(opw, out);
}

// round 11
// speedup vs baseline: 5.3694x; 1.0167x over previous
#include <cuda_runtime.h>
#include <math.h>

#define BB 8
#define HH 64
#define WW 64
#define LL 4096
#define DM 96
#define DI 192
#define DR 6
#define NE 8064
#define CPB 6   // channels per scan block (1 per warp)

// ------------------------- device scratch (static, no mallocs) -------------
static __device__ __align__(16) float  g_z[BB*LL*DI];      // (b,l,c) silu(z)
static __device__ __align__(16) float  g_xcpre[BB*DI*LL];  // (b,c,l) pre-conv
static __device__ __align__(16) float  g_xst[BB*LL*DI];    // (b,l,c)
static __device__ double g_rinv[BB*LL];                    // 1/max(norm,1e-8)
static __device__ unsigned long long   g_keys[BB*NE];      // packed (key|idx)
static __device__ int    g_pos[BB*LL];                     // node -> bfs position
static __device__ int    g_bfs[BB*LL];                     // pos  -> node
static __device__ int    g_parp[BB*LL];                    // pos  -> parent pos
static __device__ int    g_lvl[BB*(LL+2)];
static __device__ int    g_lvlcnt[BB*(LL+2)];
static __device__ int    g_lvlmin[BB*(LL+2)];
static __device__ int    g_revert[BB*(LL+2)];              // pos (or -1) per level
static __device__ int    g_numlev[BB];
static __device__ float  g_Csv[BB*LL];
static __device__ __align__(16) float2 g_eu[BB*LL*DI];     // node-ordered (ew, up)
static __device__ __align__(16) float  g_ag[BB*LL*DI];     // pos-ordered aggr
static __device__ __align__(16) float  g_yz[BB*LL*DI];     // (b,l,c)

// ------------------------- helpers -----------------------------------------
__device__ __forceinline__ float siluf(float x){ return x / (1.f + expf(-x)); }
__device__ __forceinline__ float softplusf(float x){
    return fmaxf(x, 0.f) + log1pf(expf(-fabsf(x)));
}
__device__ __forceinline__ float warpsum(float v){
    #pragma unroll
    for (int o = 16; o > 0; o >>= 1) v += __shfl_xor_sync(0xFFFFFFFFu, v, o);
    return v;
}
__device__ __forceinline__ void edge_uv(int e, int& u, int& v){
    if (e < 4032) { int r = e / 63, c = e % 63; u = r * 64 + c; v = u + 1; }
    else          { int j = e - 4032; u = j; v = j + 64; }
}
__device__ __forceinline__ void two_sum(float a, float b, float& s, float& e){
    s = a + b;
    float bv = s - a;
    e = (a - (s - bv)) + (b - bv);
}
// float-float dot + warp reduce; error ~2^-45 rel (below 2^-39 key truncation)
__device__ __forceinline__ double ff_dot_reduce(const float* __restrict__ a,
                                                const float* __restrict__ b,
                                                int lane){
    float hi = 0.f, lo = 0.f;
    #pragma unroll
    for (int j = 0; j < 6; j++) {
        float x = a[lane + 32 * j], y = b[lane + 32 * j];
        float p = x * y;
        float pe = fmaf(x, y, -p);
        float s, e;
        two_sum(hi, p, s, e);
        hi = s;
        lo += e + pe;
    }
    #pragma unroll
    for (int o = 16; o > 0; o >>= 1) {
        float oh = __shfl_xor_sync(0xFFFFFFFFu, hi, o);
        float ol = __shfl_xor_sync(0xFFFFFFFFu, lo, o);
        float s, e;
        two_sum(hi, oh, s, e);
        hi = s;
        lo += e + ol;
    }
    return (double)hi + (double)lo;
}
__device__ __forceinline__ unsigned long long key_map(double t){
    unsigned long long x = (unsigned long long)__double_as_longlong(t);
    return (x >> 63) ? ~x : (x | 0x8000000000000000ULL);
}

// ------------------------- 1. in_proj GEMM half (xc: base=0 / z: base=192) -
__global__ void __launch_bounds__(256) k_gemm_half(const float* __restrict__ A,
                                                   const float* __restrict__ W,
                                                   int nbase)
{
    __shared__ float sA[64][33];
    __shared__ float sW[64][33];
    __shared__ float st[64][68];
    int bm = blockIdx.y * 64, bn = blockIdx.x * 64 + nbase;
    int tid = threadIdx.x;
    int tx = tid & 15, ty = tid >> 4;
    float acc[4][4] = {};
    for (int k0 = 0; k0 < 96; k0 += 32) {
        for (int t = tid; t < 512; t += 256) {
            int r = t >> 3, kq = t & 7;
            float4 va = *(const float4*)(A + (size_t)(bm + r) * 96 + k0 + kq * 4);
            sA[r][kq*4+0] = va.x; sA[r][kq*4+1] = va.y;
            sA[r][kq*4+2] = va.z; sA[r][kq*4+3] = va.w;
            float4 vw = *(const float4*)(W + (size_t)(bn + r) * 96 + k0 + kq * 4);
            sW[r][kq*4+0] = vw.x; sW[r][kq*4+1] = vw.y;
            sW[r][kq*4+2] = vw.z; sW[r][kq*4+3] = vw.w;
        }
        __syncthreads();
        #pragma unroll
        for (int k = 0; k < 32; k++) {
            float a[4], b[4];
            #pragma unroll
            for (int i = 0; i < 4; i++) { a[i] = sA[ty*4+i][k]; b[i] = sW[tx*4+i][k]; }
            #pragma unroll
            for (int i = 0; i < 4; i++)
                #pragma unroll
                for (int j = 0; j < 4; j++)
                    acc[i][j] += a[i] * b[j];
        }
        __syncthreads();
    }
    int b = bm >> 12, l0 = bm & 4095;
    if (bn < DI) {
        #pragma unroll
        for (int i = 0; i < 4; i++)
            #pragma unroll
            for (int j = 0; j < 4; j++)
                st[tx*4+j][ty*4+i] = acc[i][j];
        __syncthreads();
        #pragma unroll
        for (int pass = 0; pass < 4; pass++) {
            int nn = pass * 16 + (tid >> 4);
            int mm = (tid & 15) * 4;
            float4 v = *(float4*)&st[nn][mm];
            *(float4*)&g_xcpre[((size_t)(b * DI + bn + nn)) * LL + l0 + mm] = v;
        }
    } else {
        int cb = bn - DI;
        #pragma unroll
        for (int i = 0; i < 4; i++)
            #pragma unroll
            for (int j = 0; j < 4; j++)
                st[ty*4+i][tx*4+j] = acc[i][j];
        __syncthreads();
        #pragma unroll
        for (int pass = 0; pass < 4; pass++) {
            int mm = pass * 16 + (tid >> 4);
            int nn = (tid & 15) * 4;
            float4 v = *(float4*)&st[mm][nn];
            v.x = siluf(v.x); v.y = siluf(v.y); v.z = siluf(v.z); v.w = siluf(v.w);
            *(float4*)&g_z[((size_t)(bm + mm)) * DI + cb + nn] = v;
        }
    }
}

// ------------------------- 2. depthwise conv + silu -> xst only ------------
__global__ void __launch_bounds__(256) k_conv(const float* __restrict__ cw,
                                              const float* __restrict__ cb)
{
    __shared__ float t[32][33];
    int b  = blockIdx.z;
    int c0 = blockIdx.y * 32;
    int l0 = blockIdx.x * 32;
    int tx = threadIdx.x, ty = threadIdx.y;   // 32 x 8
    int l = l0 + tx;
    int h = l >> 6, w = l & 63;
    #pragma unroll
    for (int k = 0; k < 4; k++) {
        int c = c0 + ty + 8 * k;
        const float* src = g_xcpre + (size_t)(b * DI + c) * LL;
        float acc = cb[c];
        #pragma unroll
        for (int ky = 0; ky < 3; ky++) {
            int hy = h + ky - 1;
            if ((unsigned)hy >= 64u) continue;
            #pragma unroll
            for (int kx = 0; kx < 3; kx++) {
                int wx = w + kx - 1;
                if ((unsigned)wx >= 64u) continue;
                acc += src[hy * 64 + wx] * cw[c * 9 + ky * 3 + kx];
            }
        }
        t[ty + 8 * k][tx] = siluf(acc);
    }
    __syncthreads();
    #pragma unroll
    for (int k = 0; k < 4; k++)
        g_xst[((size_t)(b * LL + l0 + ty + 8 * k)) * DI + c0 + tx] = t[tx][ty + 8 * k];
}

// ------------------------- 3. reciprocal norms (warp/node, float-float) ----
__global__ void __launch_bounds__(256) k_norm()
{
    int gid = (blockIdx.x * 256 + threadIdx.x) >> 5;   // b*L + l
    int lane = threadIdx.x & 31;
    if (gid >= BB * LL) return;
    const float* xrow = g_xst + (size_t)gid * DI;
    double s = ff_dot_reduce(xrow, xrow, lane);
    if (lane == 0) {
        double nrm = sqrt(s);
        double den = nrm > 1e-8 ? nrm : 1e-8;
        g_rinv[gid] = 1.0 / den;
    }
}

// ------------------------- 4. edge keys (warp/edge, float-float, no exp) ---
__global__ void __launch_bounds__(256) k_edge()
{
    int gid = (blockIdx.x * 256 + threadIdx.x) >> 5;
    int lane = threadIdx.x & 31;
    if (gid >= BB * NE) return;
    int b = gid / NE, e = gid % NE;
    int u, v;
    edge_uv(e, u, v);
    const float* xu = g_xst + ((size_t)(b * LL) + u) * DI;
    const float* xv = g_xst + ((size_t)(b * LL) + v) * DI;
    double s = ff_dot_reduce(xu, xv, lane);
    if (lane == 0) {
        double t = -(s * g_rinv[b * LL + u] * g_rinv[b * LL + v]);
        g_keys[gid] = (key_map(t) & ~0x1FFFULL) | (unsigned long long)e;
    }
}

// ------------------------- 5. Boruvka (active-edge compaction) + BFS -------
#define O_KEY  0
#define O_COMP 64512
#define O_PTR  80896
#define O_BEST 97280
#define O_FLAG 130048
#define O_ACT0 131072
#define O_ACT1 163328
#define BORSMEM 195584

__global__ void __launch_bounds__(1024, 1) k_boruvka()
{
    extern __shared__ unsigned char sm[];
    unsigned long long* skey = (unsigned long long*)(sm + O_KEY);
    unsigned int*       comp = (unsigned int*)(sm + O_COMP);
    unsigned int*       ptrA = (unsigned int*)(sm + O_PTR);
    unsigned long long* best = (unsigned long long*)(sm + O_BEST);
    unsigned int*       flag = (unsigned int*)(sm + O_FLAG);
    unsigned int* actbuf[2] = { (unsigned int*)(sm + O_ACT0),
                                (unsigned int*)(sm + O_ACT1) };
    __shared__ int s_done, s_chg, s_nl, s_qt, s_cnt;

    int b = blockIdx.x;
    int tid = threadIdx.x;

    for (int e = tid; e < NE; e += 1024) {
        skey[e] = g_keys[b * NE + e];
        actbuf[0][e] = (unsigned)e;
    }
    for (int i = tid; i < LL; i += 1024) comp[i] = (unsigned)i;
    if (tid < 256) flag[tid] = 0;
    __syncthreads();

    int parity = 0;
    int nact = NE;
    for (int round = 0; round < 13 && nact > 0; round++) {
        unsigned int* act = actbuf[parity];
        for (int i = tid; i < LL; i += 1024) best[i] = ~0ULL;
        if (tid == 0) s_done = 1;
        __syncthreads();

        // min-key per component over ACTIVE edges only
        for (int i = tid; i < nact; i += 1024) {
            int e = (int)act[i];
            int u, v; edge_uv(e, u, v);
            unsigned cu = comp[u], cv = comp[v];
            if (cu != cv) {
                unsigned long long k = skey[e];
                atomicMin(&best[cu], k);
                atomicMin(&best[cv], k);
            }
        }
        __syncthreads();
        // hook via chosen edge
        for (int c = tid; c < LL; c += 1024) {
            unsigned long long bk = best[c];
            if (bk != ~0ULL) {
                int e = (int)(bk & 8191ULL);
                atomicOr(&flag[e >> 5], 1u << (e & 31));
                int u, v; edge_uv(e, u, v);
                unsigned cu = comp[u], cv = comp[v];
                ptrA[c] = (cu == (unsigned)c) ? cv : cu;
                s_done = 0;
            } else {
                ptrA[c] = (unsigned)c;
            }
        }
        __syncthreads();
        if (s_done) break;
        // 2-cycle removal
        for (int c = tid; c < LL; c += 1024) {
            unsigned p = ptrA[c];
            if (p != (unsigned)c && ptrA[p] == (unsigned)c && (unsigned)c < p)
                ptrA[c] = (unsigned)c;
        }
        __syncthreads();
        // pointer jumping
        for (int it = 0; it < 13; it++) {
            if (tid == 0) s_chg = 0;
            __syncthreads();
            for (int c = tid; c < LL; c += 1024) {
                unsigned p = ptrA[c];
                unsigned g = ptrA[p];
                if (p != g) { ptrA[c] = g; s_chg = 1; }
            }
            __syncthreads();
            if (!s_chg) break;
        }
        for (int i = tid; i < LL; i += 1024) comp[i] = ptrA[comp[i]];
        if (tid == 0) s_cnt = 0;
        __syncthreads();
        // compact the active list (order-free: atomics below are commutative)
        unsigned int* nxt = actbuf[parity ^ 1];
        for (int i = tid; i < nact; i += 1024) {
            int e = (int)act[i];
            int u, v; edge_uv(e, u, v);
            if (comp[u] != comp[v]) nxt[atomicAdd(&s_cnt, 1)] = (unsigned)e;
        }
        __syncthreads();
        nact = s_cnt;
        parity ^= 1;
        __syncthreads();
    }

    // ---- warp-synchronous BFS from node 0 (warp 0 only) ----
    unsigned int* dep = (unsigned int*)(sm + O_KEY);
    unsigned int* par = (unsigned int*)(sm + O_KEY + 16384);
    unsigned int* q   = (unsigned int*)(sm + O_KEY + 32768);
    for (int i = tid; i < LL; i += 1024) dep[i] = 0xFFFFFFFFu;
    __syncthreads();
    if (tid == 0) { dep[0] = 0; par[0] = 0; q[0] = 0; s_qt = 1; }
    __syncthreads();

    if (tid < 32) {
        int qh = 0, qt = 1;
        while (qh < qt) {
            for (int i = qh + tid; i < qt; i += 32) {
                int n = (int)q[i];
                int h = n >> 6, w = n & 63;
                unsigned d = dep[n] + 1;
                if (w < 63) { int e = h * 63 + w; int m = n + 1;
                    if ((flag[e >> 5] >> (e & 31) & 1u) && dep[m] == 0xFFFFFFFFu) {
                        dep[m] = d; par[m] = (unsigned)n; q[atomicAdd(&s_qt, 1)] = (unsigned)m; } }
                if (w > 0)  { int e = h * 63 + w - 1; int m = n - 1;
                    if ((flag[e >> 5] >> (e & 31) & 1u) && dep[m] == 0xFFFFFFFFu) {
                        dep[m] = d; par[m] = (unsigned)n; q[atomicAdd(&s_qt, 1)] = (unsigned)m; } }
                if (h < 63) { int e = 4032 + n; int m = n + 64;
                    if ((flag[e >> 5] >> (e & 31) & 1u) && dep[m] == 0xFFFFFFFFu) {
                        dep[m] = d; par[m] = (unsigned)n; q[atomicAdd(&s_qt, 1)] = (unsigned)m; } }
                if (h > 0)  { int e = 4032 + n - 64; int m = n - 64;
                    if ((flag[e >> 5] >> (e & 31) & 1u) && dep[m] == 0xFFFFFFFFu) {
                        dep[m] = d; par[m] = (unsigned)n; q[atomicAdd(&s_qt, 1)] = (unsigned)m; } }
            }
            __syncwarp();
            qh = qt;
            qt = *(volatile int*)&s_qt;
            __syncwarp();
        }
    }
    __syncthreads();

    // ---- levels + positions ----
    unsigned int* lvlcnt = (unsigned int*)(sm + O_COMP);
    unsigned int* lvlmin = (unsigned int*)(sm + O_PTR);
    unsigned int* cur    = (unsigned int*)(sm + O_BEST);
    unsigned int* posA   = (unsigned int*)(sm + O_BEST + 16384);
    for (int i = tid; i < LL; i += 1024) { lvlcnt[i] = 0; lvlmin[i] = 0x7FFFFFFFu; }
    if (tid == 0) s_nl = 0;
    __syncthreads();
    for (int i = tid; i < LL; i += 1024) {
        unsigned d = dep[i];
        atomicAdd(&lvlcnt[d], 1u);
        atomicMin(&lvlmin[d], (unsigned)i);
        atomicMax(&s_nl, (int)d);
    }
    __syncthreads();
    if (tid == 0) {
        int nl = s_nl + 1;
        g_numlev[b] = nl;
        int run = 0;
        for (int d = 0; d < nl; d++) {
            g_lvl[b * (LL + 2) + d] = run;
            g_lvlcnt[b * (LL + 2) + d] = (int)lvlcnt[d];
            g_lvlmin[b * (LL + 2) + d] = (int)lvlmin[d];
            cur[d] = (unsigned)run;
            run += (int)lvlcnt[d];
        }
        g_lvl[b * (LL + 2) + nl] = LL;
    }
    __syncthreads();
    for (int i = tid; i < LL; i += 1024)
        posA[i] = atomicAdd(&cur[dep[i]], 1u);
    __syncthreads();
    for (int i = tid; i < LL; i += 1024) {
        unsigned p = posA[i];
        g_pos[b * LL + i] = (int)p;
        g_bfs[b * LL + p] = i;
        g_parp[b * LL + p] = (int)posA[par[i]];
    }
}

// ------------------------- 5b. padded-scatter revert flags (as pos) --------
__global__ void k_revert()
{
    __shared__ int nlmax;
    if (threadIdx.x == 0) {
        int m = 0;
        for (int b = 0; b < BB; b++) m = max(m, g_numlev[b]);
        nlmax = m;
    }
    __syncthreads();
    for (int d = threadIdx.x; d < nlmax; d += blockDim.x) {
        int cnt[BB];
        int md = 0;
        for (int b = 0; b < BB; b++) {
            int c = (d < g_numlev[b]) ? g_lvlcnt[b * (LL + 2) + d] : 0;
            cnt[b] = c;
            md = max(md, c);
        }
        for (int b = 0; b < BB; b++) {
            int r = -1;
            if (d > 0 && cnt[b] > 0 && cnt[b] < md)
                r = g_pos[b * LL + g_lvlmin[b * (LL + 2) + d]];
            g_revert[b * (LL + 2) + d] = r;
        }
    }
}

// ------------------------- 6. fused x_dbl + dts/deltaA/BX (node-ordered) ---
__global__ void __launch_bounds__(256) k_ssm(const float* __restrict__ XW,
                                             const float* __restrict__ dtW,
                                             const float* __restrict__ dtB,
                                             const float* __restrict__ Alog)
{
    int gw = (blockIdx.x * 256 + threadIdx.x) >> 5;   // b*LL + l
    int lane = threadIdx.x & 31;
    if (gw >= BB * LL) return;
    const float* xrow = g_xst + (size_t)gw * DI;

    float xv[6];
    #pragma unroll
    for (int j = 0; j < 6; j++) xv[j] = xrow[lane + 32 * j];

    float acc[8];
    #pragma unroll
    for (int c8 = 0; c8 < 8; c8++) {
        float s = 0.f;
        #pragma unroll
        for (int j = 0; j < 6; j++) s += xv[j] * XW[c8 * DI + lane + 32 * j];
        acc[c8] = warpsum(s);
    }
    float Bsv = acc[6];
    if (lane == 0) g_Csv[gw] = acc[7];

    float2* eurow = g_eu + (size_t)gw * DI;
    #pragma unroll
    for (int j = 0; j < 6; j++) {
        int d = lane + 32 * j;
        float s = dtB[d];
        #pragma unroll
        for (int r = 0; r < DR; r++) s += acc[r] * dtW[d * DR + r];
        float dt = softplusf(s);
        float ew = expf(-expf(Alog[d]) * dt);
        float bx = dt * Bsv * xv[j];
        eurow[d] = make_float2(ew, bx);
    }
}

// ------------------------- 7. warp-autonomous smem tree scan ----------------
#define SCAN_SMEM (CPB*LL*4*2 + LL*4 + (LL+2)*4)
__global__ void __launch_bounds__(512) k_scan()
{
    extern __shared__ unsigned char sms[];
    float* acc_all = (float*)sms;                      // [CPB][LL]
    float* ew_all  = (float*)(sms + CPB*LL*4);         // [CPB][LL]
    int*   parp_s  = (int*)(sms + CPB*LL*8);           // [LL]
    int*   lvl_s   = (int*)(sms + CPB*LL*8 + LL*4);    // [nl+1]

    int b  = blockIdx.y;
    int c0 = blockIdx.x * CPB;
    int tid = threadIdx.x;
    int warp = tid >> 5, lane = tid & 31;
    int nl = g_numlev[b];
    const int* revp = g_revert + b * (LL + 2);
    const int* bfs  = g_bfs + b * LL;
    const float2* eu = g_eu + (size_t)(b * LL) * DI;
    float* agout = g_ag + (size_t)(b * LL) * DI;

    for (int i = tid; i < LL; i += 512) parp_s[i] = g_parp[b * LL + i];
    for (int i = tid; i <= nl; i += 512) lvl_s[i] = g_lvl[b * (LL + 2) + i];
    for (int idx = tid; idx < LL * CPB; idx += 512) {
        int pos = idx / CPB, cc = idx % CPB;
        float2 v = eu[(size_t)bfs[pos] * DI + c0 + cc];
        ew_all[cc * LL + pos]  = v.x;
        acc_all[cc * LL + pos] = v.y;
    }
    __syncthreads();

    if (warp < CPB) {
        float* A = acc_all + warp * LL;
        float* E = ew_all + warp * LL;
        for (int lev = nl - 1; lev >= 1; --lev) {
            int ls = lvl_s[lev], le = lvl_s[lev + 1];
            for (int pos = ls + lane; pos < le; pos += 32)
                atomicAdd(&A[parp_s[pos]], E[pos] * A[pos]);
            __syncwarp();
        }
        for (int lev = 0; lev < nl; ++lev) {
            int ls = lvl_s[lev], le = lvl_s[lev + 1];
            int rev = revp[lev];
            for (int pos = ls + lane; pos < le; pos += 32) {
                float u = A[pos];
                float val = u;
                if (lev > 0) {
                    float w = E[pos];
                    val = u + w * (A[parp_s[pos]] - w * u);
                    if (pos == rev) val = u;
                }
                A[pos] = val;
            }
            __syncwarp();
        }
    }
    __syncthreads();

    for (int idx = tid; idx < LL * CPB; idx += 512) {
        int pos = idx / CPB, cc = idx % CPB;
        agout[(size_t)pos * DI + c0 + cc] = acc_all[cc * LL + pos];
    }
}

// ------------------------- 8. fused LN -> *Cs -> +Ds*xs -> LN -> *z --------
__global__ void __launch_bounds__(256) k_fuse(const float* __restrict__ hg,
                                              const float* __restrict__ hb,
                                              const float* __restrict__ og,
                                              const float* __restrict__ ob,
                                              const float* __restrict__ Ds)
{
    int warp = (blockIdx.x * 256 + threadIdx.x) >> 5;
    int lane = threadIdx.x & 31;
    if (warp >= BB * LL) return;
    int b = warp >> 12;
    int pos = g_pos[warp];
    const float* hrow = g_ag + ((size_t)(b * LL) + pos) * DI;
    const float* xrow = g_xst + (size_t)warp * DI;

    float v[6];
    #pragma unroll
    for (int j = 0; j < 6; j++) v[j] = hrow[lane + 32 * j];

    float s = 0.f;
    #pragma unroll
    for (int j = 0; j < 6; j++) s += v[j];
    float mu = warpsum(s) * (1.f / 192.f);
    float q = 0.f;
    #pragma unroll
    for (int j = 0; j < 6; j++) { float d = v[j] - mu; q += d * d; }
    float inv = rsqrtf(warpsum(q) * (1.f / 192.f) + 1e-5f);

    float Cv = g_Csv[warp];
    float y[6];
    #pragma unroll
    for (int j = 0; j < 6; j++) {
        int c = lane + 32 * j;
        float hn = (v[j] - mu) * inv * hg[c] + hb[c];
        y[j] = hn * Cv + Ds[c] * xrow[c];
    }

    s = 0.f;
    #pragma unroll
    for (int j = 0; j < 6; j++) s += y[j];
    float mu2 = warpsum(s) * (1.f / 192.f);
    q = 0.f;
    #pragma unroll
    for (int j = 0; j < 6; j++) { float d = y[j] - mu2; q += d * d; }
    float inv2 = rsqrtf(warpsum(q) * (1.f / 192.f) + 1e-5f);

    #pragma unroll
    for (int j = 0; j < 6; j++) {
        int c = lane + 32 * j;
        float y2 = (y[j] - mu2) * inv2 * og[c] + ob[c];
        g_yz[(size_t)warp * DI + c] = y2 * g_z[(size_t)warp * DI + c];
    }
}

// ------------------------- 9. out_proj GEMM (single N pass) -----------------
// out[m][n] = sum_k yz[m][k]*W[n][k]; M-tile 64, N=96 full, K=192.
__global__ void __launch_bounds__(256) k_gemm_out(const float* __restrict__ W,
                                                  float* __restrict__ out)
{
    __shared__ float sA[64][33];
    __shared__ float sW[96][33];
    int bm = blockIdx.x * 64;
    int tid = threadIdx.x;
    int tx = tid & 15, ty = tid >> 4;
    float acc[4][6] = {};
    for (int k0 = 0; k0 < 192; k0 += 32) {
        for (int t = tid; t < 512; t += 256) {
            int r = t >> 3, kq = t & 7;
            float4 va = *(const float4*)(g_yz + (size_t)(bm + r) * 192 + k0 + kq * 4);
            sA[r][kq*4+0] = va.x; sA[r][kq*4+1] = va.y;
            sA[r][kq*4+2] = va.z; sA[r][kq*4+3] = va.w;
        }
        for (int t = tid; t < 768; t += 256) {
            int r = t >> 3, kq = t & 7;
            float4 vw = *(const float4*)(W + (size_t)r * 192 + k0 + kq * 4);
            sW[r][kq*4+0] = vw.x; sW[r][kq*4+1] = vw.y;
            sW[r][kq*4+2] = vw.z; sW[r][kq*4+3] = vw.w;
        }
        __syncthreads();
        #pragma unroll
        for (int k = 0; k < 32; k++) {
            float a[4], bv[6];
            #pragma unroll
            for (int i = 0; i < 4; i++) a[i] = sA[ty*4+i][k];
            #pragma unroll
            for (int j = 0; j < 6; j++) bv[j] = sW[tx + 16*j][k];
            #pragma unroll
            for (int i = 0; i < 4; i++)
                #pragma unroll
                for (int j = 0; j < 6; j++)
                    acc[i][j] += a[i] * bv[j];
        }
        __syncthreads();
    }
    #pragma unroll
    for (int i = 0; i < 4; i++) {
        int m = bm + ty * 4 + i;
        #pragma unroll
        for (int j = 0; j < 6; j++)
            out[(size_t)m * 96 + tx + 16*j] = acc[i][j];
    }
}

// ------------------------- launch ------------------------------------------
extern "C" void kernel_launch(void* const* d_in, const int* in_sizes, int n_in,
                              void* d_out, int out_size)
{
    const float* x    = (const float*)d_in[0];
    const float* inw  = (const float*)d_in[1];
    const float* cw   = (const float*)d_in[2];
    const float* cb   = (const float*)d_in[3];
    const float* xpw  = (const float*)d_in[4];
    const float* dtw  = (const float*)d_in[5];
    const float* dtb  = (const float*)d_in[6];
    const float* alog = (const float*)d_in[7];
    const float* Dsp  = (const float*)d_in[8];
    const float* hg   = (const float*)d_in[9];
    const float* hbp  = (const float*)d_in[10];
    const float* og   = (const float*)d_in[11];
    const float* obp  = (const float*)d_in[12];
    const float* opw  = (const float*)d_in[13];
    float* out = (float*)d_out;

    static cudaStream_t sTree = nullptr, sZ = nullptr;
    static cudaEvent_t evStart = nullptr, evFork = nullptr, evTree = nullptr,
                       evZ = nullptr;
    if (sTree == nullptr) {
        cudaStreamCreateWithFlags(&sTree, cudaStreamNonBlocking);
        cudaStreamCreateWithFlags(&sZ, cudaStreamNonBlocking);
        cudaEventCreateWithFlags(&evStart, cudaEventDisableTiming);
        cudaEventCreateWithFlags(&evFork, cudaEventDisableTiming);
        cudaEventCreateWithFlags(&evTree, cudaEventDisableTiming);
        cudaEventCreateWithFlags(&evZ, cudaEventDisableTiming);
    }

    // z half depends only on input x: run on its own stream from t=0
    cudaEventRecord(evStart, 0);
    cudaStreamWaitEvent(sZ, evStart, 0);
    k_gemm_half<<<dim3(3, 512), 256, 0, sZ>>>(x, inw, DI);
    cudaEventRecord(evZ, sZ);

    k_gemm_half<<<dim3(3, 512), 256>>>(x, inw, 0);    // xc half
    k_conv<<<dim3(128, 6, 8), dim3(32, 8)>>>(cw, cb);

    // fork: tree chain overlaps the dense ssm pass
    cudaEventRecord(evFork, 0);
    cudaStreamWaitEvent(sTree, evFork, 0);
    k_norm<<<(BB * LL * 32 + 255) / 256, 256, 0, sTree>>>();
    k_edge<<<(BB * NE * 32 + 255) / 256, 256, 0, sTree>>>();
    cudaFuncSetAttribute(k_boruvka, cudaFuncAttributeMaxDynamicSharedMemorySize, BORSMEM);
    k_boruvka<<<BB, 1024, BORSMEM, sTree>>>();
    k_revert<<<1, 256, 0, sTree>>>();
    cudaEventRecord(evTree, sTree);

    k_ssm<<<(BB * LL * 32 + 255) / 256, 256>>>(xpw, dtw, dtb, alog);

    cudaStreamWaitEvent(0, evTree, 0);
    cudaFuncSetAttribute(k_scan, cudaFuncAttributeMaxDynamicSharedMemorySize, SCAN_SMEM);
    k_scan<<<dim3(DI / CPB, BB), 512, SCAN_SMEM>>>();

    cudaStreamWaitEvent(0, evZ, 0);
    k_fuse<<<(BB * LL * 32 + 255) / 256, 256>>>(hg, hbp, og, obp, Dsp);
    k_gemm_out<<<512, 256>>>(opw, out);
}